// round 5
// baseline (speedup 1.0000x reference)
#include <cuda_runtime.h>
#include <math.h>
#include <stdint.h>

// Problem dims
#define VV 32000
#define HH 512
#define LL 256
#define BB 16
#define TEE 512
#define TDD 256

// Output layout: [logits (B*TD*V)][dec_max_len (1)][mu (B*L)][sigma (B*L)]
#define OFF_ML  ((size_t)BB * TDD * VV)
#define OFF_MU  (OFF_ML + 1)
#define OFF_SG  (OFF_MU + (size_t)BB * LL)

// ---------------------------------------------------------------------------
// Scratch (static device globals; no allocation allowed)
// ---------------------------------------------------------------------------
__device__ float g_gx_enc[(size_t)BB * TEE * 3 * HH];   // 50.3 MB
__device__ float g_enc_out[(size_t)BB * TEE * HH];      // 16.8 MB
__device__ float g_gx_dec[(size_t)BB * TDD * 3 * LL];   // 12.6 MB
__device__ float g_dec_out[(size_t)BB * TDD * LL];      //  4.2 MB
__device__ float g_hA[BB * HH];
__device__ float g_hB[BB * HH];
__device__ float g_sfw[BB * TEE];
__device__ float g_sbw[BB * TEE];
__device__ float g_henc[BB * 2 * HH];
__device__ float g_z[BB * LL];

// Tree barrier state: 16 group counters on separate 128B lines + root counter.
// Counters ACCUMULATE across barriers (and graph replays); arrival detection is
// modulo-based, so no resets and no reset-visibility hazards.
__device__ unsigned g_cnt_grp[16 * 32];   // group g uses g_cnt_grp[g*32]
__device__ unsigned g_cnt_root;
__device__ volatile unsigned g_bar_gen;

// ---------------------------------------------------------------------------
// Grid-wide tree barrier (nb must be 128: 16 groups x 8 CTAs).
// Arrival: 8-way serialized atomics per group line (parallel across 16 lines),
// then 16-way serialized root atomics by group leaders. Release: one gen word
// (volatile, R1-proven poll pattern) observed by all CTAs.
// ---------------------------------------------------------------------------
__device__ __forceinline__ void grid_barrier(unsigned nb) {
    const unsigned GSIZE = nb >> 4;            // 8 for nb=128
    __threadfence();          // release all this CTA's stores (L2 scope)
    __syncthreads();
    if (threadIdx.x == 0) {
        unsigned gen = g_bar_gen;
        unsigned g = blockIdx.x & 15;          // interleaved group id
        unsigned a = atomicAdd(&g_cnt_grp[g * 32], 1u);
        if ((a % GSIZE) == GSIZE - 1) {        // last arriver of this group
            unsigned r = atomicAdd(&g_cnt_root, 1u);
            if ((r & 15u) == 15u) {            // last group leader
                __threadfence();
                g_bar_gen = gen + 1;
            }
        }
        while (g_bar_gen == gen) { }
        __threadfence();      // acquire
    }
    __syncthreads();
}

__device__ __forceinline__ float sigmoidf_(float x) { return 1.0f / (1.0f + expf(-x)); }

// ---------------------------------------------------------------------------
// Persistent GRU. Grid = K/CW blocks (128). Block owns CW hidden columns.
// smem h pitch = K+2 words; float2 loads are bank-conflict-free across the
// 16 batch lanes. Dot phase uses 4 accumulators to break the FFMA chain.
// ---------------------------------------------------------------------------
template<int K, int CW>
__global__ __launch_bounds__(256, 1) void gru_persist(
    const float* __restrict__ gx,    // [B, T, 3K]  (= x@Wih^T + bih, precomputed)
    const float* __restrict__ Whh,   // [3K, K]
    const float* __restrict__ bhh,   // [3K]
    const int*   __restrict__ lens,  // [B]
    const float* __restrict__ h0,    // [B, K] or nullptr (=> zeros)
    float* hA, float* hB,
    float* __restrict__ out,         // [B, T, K]
    int T)
{
    constexpr int PW = K + 2;            // smem pitch (floats)
    constexpr int NC = 16 * 3 * CW;      // dot-product threads (192 / 96)
    constexpr int NU = 16 * CW;          // update threads (64 / 32)
    __shared__ float hs[16 * PW];
    __shared__ float ex[NC];
    __shared__ int   lens_s[16];

    const int tid = threadIdx.x;
    const int bx  = blockIdx.x;
    const unsigned NB = gridDim.x;

    // dot-thread identity + persistent weight row pointer + bias
    const float4* wp = nullptr;
    float bhv = 0.0f;
    int db = tid & 15;
    if (tid < NC) {
        int didx = tid >> 4;             // 0..3CW-1
        int dg = didx / CW, dcl = didx % CW;
        int dc = bx * CW + dcl;
        wp = (const float4*)(Whh + (size_t)(dg * K + dc) * K);
        bhv = bhh[dg * K + dc];
    }
    // update-thread identity
    int ub = tid & 15, ucl = tid >> 4;
    int uc = bx * CW + ucl;

    if (tid < 16) lens_s[tid] = lens[tid];
    if (tid < NU) {                      // init h buffer A (this block's columns)
        float v = h0 ? h0[ub * K + uc] : 0.0f;
        __stcg(&hA[ub * K + uc], v);
    }
    grid_barrier(NB);

    for (int t = 0; t < T; t++) {
        float* hcur  = (t & 1) ? hB : hA;
        float* hnext = (t & 1) ? hA : hB;

        // prefetch gx[t] for update threads (independent of h -> hides latency)
        float gxr = 0.f, gxz = 0.f, gxn = 0.f;
        if (tid < NU) {
            const float* gxp = gx + (size_t)(ub * T + t) * (3 * K);
            gxr = __ldg(gxp + uc);
            gxz = __ldg(gxp + K + uc);
            gxn = __ldg(gxp + 2 * K + uc);
        }

        // stage full h[B,K] into smem (float2, pitch K+2)
        const float2* hc2 = (const float2*)hcur;
        #pragma unroll
        for (int i = tid; i < 16 * K / 2; i += 256) {
            float2 v = __ldcg(hc2 + i);
            int b = i / (K / 2), kh = i % (K / 2);
            *(float2*)&hs[b * PW + 2 * kh] = v;
        }
        __syncthreads();

        if (tid < NC) {                  // gh[b, g*K+c] = h[b,:] . Whh[g*K+c,:]
            const float2* hp = (const float2*)&hs[db * PW];
            float a0 = 0.f, a1 = 0.f, a2 = 0.f, a3 = 0.f;
            #pragma unroll 4
            for (int kk = 0; kk < K / 16; kk++) {
                float4 w0 = __ldg(wp + 4 * kk + 0);
                float4 w1 = __ldg(wp + 4 * kk + 1);
                float4 w2 = __ldg(wp + 4 * kk + 2);
                float4 w3 = __ldg(wp + 4 * kk + 3);
                float2 h0v = hp[8 * kk + 0], h1v = hp[8 * kk + 1];
                float2 h2v = hp[8 * kk + 2], h3v = hp[8 * kk + 3];
                float2 h4v = hp[8 * kk + 4], h5v = hp[8 * kk + 5];
                float2 h6v = hp[8 * kk + 6], h7v = hp[8 * kk + 7];
                a0 += w0.x * h0v.x + w0.y * h0v.y + w0.z * h1v.x + w0.w * h1v.y;
                a1 += w1.x * h2v.x + w1.y * h2v.y + w1.z * h3v.x + w1.w * h3v.y;
                a2 += w2.x * h4v.x + w2.y * h4v.y + w2.z * h5v.x + w2.w * h5v.y;
                a3 += w3.x * h6v.x + w3.y * h6v.y + w3.z * h7v.x + w3.w * h7v.y;
            }
            ex[(tid >> 4) * 16 + db] = ((a0 + a1) + (a2 + a3)) + bhv;
        }
        __syncthreads();

        if (tid < NU) {                  // combine gates, update h, write out
            float ghr = ex[(0 * CW + ucl) * 16 + ub];
            float ghz = ex[(1 * CW + ucl) * 16 + ub];
            float ghn = ex[(2 * CW + ucl) * 16 + ub];
            float r = sigmoidf_(gxr + ghr);
            float z = sigmoidf_(gxz + ghz);
            float n = tanhf   (gxn + r * ghn);
            float hold = hs[ub * PW + uc];
            float hnew = (1.0f - z) * n + z * hold;
            bool valid = (t < lens_s[ub]);
            __stcg(&hnext[ub * K + uc], valid ? hnew : hold);
            out[(size_t)(ub * T + t) * K + uc] = valid ? hnew : 0.0f;
        }
        grid_barrier(NB);
    }
}

// ---------------------------------------------------------------------------
// 128x128x8 fp32 SGEMM-NT, double-buffered smem, 1 sync per k-tile.
// C[i,j] = sum_k A[i,k]*W[j,k] + bias[j]
// Optional row gather (A row i = Atab + ids[i]*KD) and zero-row tile skip.
// ---------------------------------------------------------------------------
template<int KD>
__global__ __launch_bounds__(256, 2) void gemm_nt128(
    float* __restrict__ C,
    const float* __restrict__ Adirect,
    const int*   __restrict__ ids,
    const float* __restrict__ Atab,
    const float* __restrict__ W,
    const float* __restrict__ bias,
    int N,
    const int* __restrict__ skiplen,   // optional: row i -> b=i/tper, t=i%tper
    int tper)
{
    __shared__ float As[2][8][128];
    __shared__ float Bs[2][8][128];
    const int tid  = threadIdx.x;
    const int row0 = blockIdx.y * 128, col0 = blockIdx.x * 128;
    const int ty = tid >> 4, tx = tid & 15;

    if (skiplen) {   // whole M-tile is zero rows -> output = bias only
        int bb = row0 / tper, t0 = row0 % tper;
        if (t0 >= __ldg(&skiplen[bb])) {
            float4 blo = *(const float4*)(bias + col0 + tx * 8);
            float4 bhi = *(const float4*)(bias + col0 + tx * 8 + 4);
            #pragma unroll
            for (int i = 0; i < 8; i++) {
                float* cp = C + (size_t)(row0 + ty * 8 + i) * N + col0 + tx * 8;
                *(float4*)cp = blo; *(float4*)(cp + 4) = bhi;
            }
            return;
        }
    }

    const int lr  = tid >> 1;
    const int lk4 = (tid & 1) * 4;
    const float* arow = ids ? (Atab + (size_t)__ldg(&ids[row0 + lr]) * KD)
                            : (Adirect + (size_t)(row0 + lr) * KD);
    const float* wrow = W + (size_t)(col0 + lr) * KD;

    // prologue: fill buffer 0
    {
        float4 av = *(const float4*)(arow + lk4);
        float4 wv = *(const float4*)(wrow + lk4);
        As[0][lk4 + 0][lr] = av.x; As[0][lk4 + 1][lr] = av.y;
        As[0][lk4 + 2][lr] = av.z; As[0][lk4 + 3][lr] = av.w;
        Bs[0][lk4 + 0][lr] = wv.x; Bs[0][lk4 + 1][lr] = wv.y;
        Bs[0][lk4 + 2][lr] = wv.z; Bs[0][lk4 + 3][lr] = wv.w;
    }
    __syncthreads();

    float acc[8][8];
    #pragma unroll
    for (int i = 0; i < 8; i++)
        #pragma unroll
        for (int j = 0; j < 8; j++) acc[i][j] = 0.0f;

    constexpr int NK = KD / 8;
    #pragma unroll 1
    for (int kt = 0; kt < NK; kt++) {
        const int cur = kt & 1;
        float4 av2, wv2;
        if (kt + 1 < NK) {
            av2 = *(const float4*)(arow + (kt + 1) * 8 + lk4);
            wv2 = *(const float4*)(wrow + (kt + 1) * 8 + lk4);
        }
        #pragma unroll
        for (int k = 0; k < 8; k++) {
            float a[8], b[8];
            *(float4*)&a[0] = *(const float4*)&As[cur][k][ty * 8];
            *(float4*)&a[4] = *(const float4*)&As[cur][k][ty * 8 + 4];
            *(float4*)&b[0] = *(const float4*)&Bs[cur][k][tx * 8];
            *(float4*)&b[4] = *(const float4*)&Bs[cur][k][tx * 8 + 4];
            #pragma unroll
            for (int i = 0; i < 8; i++)
                #pragma unroll
                for (int j = 0; j < 8; j++)
                    acc[i][j] += a[i] * b[j];
        }
        if (kt + 1 < NK) {
            const int nxt = cur ^ 1;
            As[nxt][lk4 + 0][lr] = av2.x; As[nxt][lk4 + 1][lr] = av2.y;
            As[nxt][lk4 + 2][lr] = av2.z; As[nxt][lk4 + 3][lr] = av2.w;
            Bs[nxt][lk4 + 0][lr] = wv2.x; Bs[nxt][lk4 + 1][lr] = wv2.y;
            Bs[nxt][lk4 + 2][lr] = wv2.z; Bs[nxt][lk4 + 3][lr] = wv2.w;
        }
        __syncthreads();
    }

    float4 blo = *(const float4*)(bias + col0 + tx * 8);
    float4 bhi = *(const float4*)(bias + col0 + tx * 8 + 4);
    #pragma unroll
    for (int i = 0; i < 8; i++) {
        float* cp = C + (size_t)(row0 + ty * 8 + i) * N + col0 + tx * 8;
        float4 v0 = make_float4(acc[i][0] + blo.x, acc[i][1] + blo.y,
                                acc[i][2] + blo.z, acc[i][3] + blo.w);
        float4 v1 = make_float4(acc[i][4] + bhi.x, acc[i][5] + bhi.y,
                                acc[i][6] + bhi.z, acc[i][7] + bhi.w);
        *(float4*)cp = v0; *(float4*)(cp + 4) = v1;
    }
}

// ---------------------------------------------------------------------------
// Padding no-ops: profiled slot = my 4th launch => 2 noops put gru_enc there
// ---------------------------------------------------------------------------
__global__ void noop_a() {}
__global__ void noop_b() {}

// ---------------------------------------------------------------------------
// Attention scores (R1-proven): sfw[b,t] = out[b,t,:].last[b,:]; sbw with first
// ---------------------------------------------------------------------------
__global__ __launch_bounds__(256) void attn_scores() {
    const int b = blockIdx.x, tid = threadIdx.x;
    __shared__ float last_s[HH], first_s[HH];
    for (int i = tid; i < HH; i += 256) {
        last_s[i]  = g_hA[b * HH + i];
        first_s[i] = g_enc_out[((size_t)b * TEE + 0) * HH + i];
    }
    __syncthreads();
    const int w = tid >> 5, lane = tid & 31;
    for (int t = w; t < TEE; t += 8) {
        const float* orow = g_enc_out + ((size_t)(b * TEE + t)) * HH;
        float af = 0.0f, ab = 0.0f;
        #pragma unroll 4
        for (int i = lane; i < HH; i += 32) {
            float v = orow[i];
            af += v * last_s[i];
            ab += v * first_s[i];
        }
        #pragma unroll
        for (int o = 16; o > 0; o >>= 1) {
            af += __shfl_xor_sync(0xffffffffu, af, o);
            ab += __shfl_xor_sync(0xffffffffu, ab, o);
        }
        if (lane == 0) { g_sfw[b * TEE + t] = af; g_sbw[b * TEE + t] = ab; }
    }
}

__device__ __forceinline__ float blk_reduce(float v, float* red, bool ismax) {
    #pragma unroll
    for (int o = 16; o > 0; o >>= 1) {
        float u = __shfl_xor_sync(0xffffffffu, v, o);
        v = ismax ? fmaxf(v, u) : (v + u);
    }
    int w = threadIdx.x >> 5;
    if ((threadIdx.x & 31) == 0) red[w] = v;
    __syncthreads();
    if (threadIdx.x == 0) {
        float a = red[0];
        for (int i = 1; i < 8; i++) a = ismax ? fmaxf(a, red[i]) : (a + red[i]);
        red[0] = a;
    }
    __syncthreads();
    float r = red[0];
    __syncthreads();
    return r;
}

// ---------------------------------------------------------------------------
// Masked dual softmax + semantic pooling + h_enc assembly (R1-proven).
// ---------------------------------------------------------------------------
__global__ __launch_bounds__(256) void softmax_semantic(const int* __restrict__ enc_len) {
    const int b = blockIdx.x, tid = threadIdx.x;
    const int len = enc_len[b];
    __shared__ float sa[TEE];
    __shared__ float red[8];

    // forward pass
    float v0 = (tid       < len) ? g_sfw[b * TEE + tid]       : -1e30f;
    float v1 = (tid + 256 < len) ? g_sfw[b * TEE + tid + 256] : -1e30f;
    float M = blk_reduce(fmaxf(v0, v1), red, true);
    float e0 = (tid       < len) ? expf(v0 - M) : 0.0f;
    float e1 = (tid + 256 < len) ? expf(v1 - M) : 0.0f;
    float S = blk_reduce(e0 + e1, red, false);
    float inv = 0.5f / S;
    sa[tid] = e0 * inv; sa[tid + 256] = e1 * inv;
    __syncthreads();

    // backward pass
    v0 = (tid       < len) ? g_sbw[b * TEE + tid]       : -1e30f;
    v1 = (tid + 256 < len) ? g_sbw[b * TEE + tid + 256] : -1e30f;
    M = blk_reduce(fmaxf(v0, v1), red, true);
    e0 = (tid       < len) ? expf(v0 - M) : 0.0f;
    e1 = (tid + 256 < len) ? expf(v1 - M) : 0.0f;
    S = blk_reduce(e0 + e1, red, false);
    inv = 0.5f / S;
    sa[tid] += e0 * inv; sa[tid + 256] += e1 * inv;
    __syncthreads();

    // semantic[b,d] = sum_t alpha[t] * out[b,t,d];  h_enc = [last, semantic]
    for (int d = tid; d < HH; d += 256) {
        float acc = 0.0f;
        #pragma unroll 4
        for (int t = 0; t < TEE; t++)
            acc += sa[t] * g_enc_out[((size_t)(b * TEE + t)) * HH + d];
        g_henc[b * 2 * HH + HH + d] = acc;
        g_henc[b * 2 * HH + d] = g_hA[b * HH + d];
    }
}

// ---------------------------------------------------------------------------
// Latent head (R1-proven): mu/sigma/z + tail outputs. 1 block per b.
// ---------------------------------------------------------------------------
__global__ __launch_bounds__(256) void latent_head(
    const float* __restrict__ W_mu, const float* __restrict__ b_mu,
    const float* __restrict__ W_ls, const float* __restrict__ b_ls,
    const float* __restrict__ noise, const int* __restrict__ dec_len,
    float* __restrict__ outbuf)
{
    const int b = blockIdx.x, tid = threadIdx.x;
    __shared__ float he[2 * HH];
    __shared__ float muv[LL], lsv[LL];
    for (int i = tid; i < 2 * HH; i += 256) he[i] = g_henc[b * 2 * HH + i];
    __syncthreads();

    const int w = tid >> 5, lane = tid & 31;
    for (int o = w; o < 2 * LL; o += 8) {
        const float* Wr; float bia; int j;
        if (o < LL) { j = o;      Wr = W_mu + (size_t)j * (2 * HH); bia = b_mu[j]; }
        else        { j = o - LL; Wr = W_ls + (size_t)j * (2 * HH); bia = b_ls[j]; }
        float acc = 0.0f;
        #pragma unroll 4
        for (int k = lane; k < 2 * HH; k += 32) acc += Wr[k] * he[k];
        #pragma unroll
        for (int s = 16; s > 0; s >>= 1) acc += __shfl_xor_sync(0xffffffffu, acc, s);
        if (lane == 0) { if (o < LL) muv[j] = acc + bia; else lsv[j] = acc + bia; }
    }
    __syncthreads();

    if (tid < LL) {
        float mu = muv[tid];
        float sg = expf(lsv[tid]);
        float zz = mu + sg * noise[b * LL + tid];
        g_z[b * LL + tid] = zz;
        outbuf[OFF_MU + b * LL + tid] = mu;
        outbuf[OFF_SG + b * LL + tid] = sg;
    }
    if (b == 0 && tid == 0) {
        int m = 0;
        for (int i = 0; i < BB; i++) m = max(m, dec_len[i]);
        outbuf[OFF_ML] = (float)m;
    }
}

// ---------------------------------------------------------------------------
// Launch
// ---------------------------------------------------------------------------
extern "C" void kernel_launch(void* const* d_in, const int* in_sizes, int n_in,
                              void* d_out, int out_size) {
    const float* emb     = (const float*)d_in[0];
    const float* enc_Wih = (const float*)d_in[1];
    const float* enc_Whh = (const float*)d_in[2];
    const float* enc_bih = (const float*)d_in[3];
    const float* enc_bhh = (const float*)d_in[4];
    const float* dec_Wih = (const float*)d_in[5];
    const float* dec_Whh = (const float*)d_in[6];
    const float* dec_bih = (const float*)d_in[7];
    const float* dec_bhh = (const float*)d_in[8];
    const float* W_mu    = (const float*)d_in[9];
    const float* b_mu    = (const float*)d_in[10];
    const float* W_ls    = (const float*)d_in[11];
    const float* b_ls    = (const float*)d_in[12];
    const float* W_fc    = (const float*)d_in[13];
    const float* b_fc    = (const float*)d_in[14];
    const float* noise   = (const float*)d_in[15];
    const int*   enc_ids = (const int*)d_in[16];
    const int*   enc_len = (const int*)d_in[17];
    const int*   dec_ids = (const int*)d_in[18];
    const int*   dec_len = (const int*)d_in[19];
    float* outbuf = (float*)d_out;

    float *p_gx_enc, *p_enc_out, *p_gx_dec, *p_dec_out, *p_hA, *p_hB, *p_z;
    cudaGetSymbolAddress((void**)&p_gx_enc, g_gx_enc);
    cudaGetSymbolAddress((void**)&p_enc_out, g_enc_out);
    cudaGetSymbolAddress((void**)&p_gx_dec, g_gx_dec);
    cudaGetSymbolAddress((void**)&p_dec_out, g_dec_out);
    cudaGetSymbolAddress((void**)&p_hA, g_hA);
    cudaGetSymbolAddress((void**)&p_hB, g_hB);
    cudaGetSymbolAddress((void**)&p_z, g_z);

    // 1) gx_enc = emb[enc_ids] @ enc_Wih^T + bih   [8192 x 1536, K=512]
    gemm_nt128<512><<<dim3(1536 / 128, (BB * TEE) / 128), 256>>>(
        p_gx_enc, nullptr, enc_ids, emb, enc_Wih, enc_bih, 3 * HH, nullptr, 1);

    // 2-3) padding no-ops (keep gru_enc at my launch #4 = profiled slot)
    noop_a<<<1, 32>>>();
    noop_b<<<1, 32>>>();

    // 4) encoder GRU (persistent, 512 steps)  <-- profiled launch
    gru_persist<HH, 4><<<HH / 4, 256>>>(
        p_gx_enc, enc_Whh, enc_bhh, enc_len, nullptr, p_hA, p_hB, p_enc_out, TEE);

    // 5-7) attention + latent path (R1 versions)
    attn_scores<<<BB, 256>>>();
    softmax_semantic<<<BB, 256>>>(enc_len);
    latent_head<<<BB, 256>>>(W_mu, b_mu, W_ls, b_ls, noise, dec_len, outbuf);

    // 8) gx_dec = emb[dec_ids] @ dec_Wih^T + bih   [4096 x 768, K=512]
    gemm_nt128<512><<<dim3((3 * LL) / 128, (BB * TDD) / 128), 256>>>(
        p_gx_dec, nullptr, dec_ids, emb, dec_Wih, dec_bih, 3 * LL, nullptr, 1);

    // 9) decoder GRU (persistent, 256 steps), h0 = z
    gru_persist<LL, 2><<<LL / 2, 256>>>(
        p_gx_dec, dec_Whh, dec_bhh, dec_len, p_z, p_hA, p_hB, p_dec_out, TDD);

    // 10) logits = dec_out @ W_fc^T + b_fc  [4096 x 32000, K=256], zero-row skip
    gemm_nt128<256><<<dim3(VV / 128, (BB * TDD) / 128), 256>>>(
        outbuf, p_dec_out, nullptr, nullptr, W_fc, b_fc, VV, dec_len, TDD);
}

// round 6
// speedup vs baseline: 1.0826x; 1.0826x over previous
#include <cuda_runtime.h>
#include <math.h>
#include <stdint.h>

// Problem dims
#define VV 32000
#define HH 512
#define LL 256
#define BB 16
#define TEE 512
#define TDD 256

// Output layout: [logits (B*TD*V)][dec_max_len (1)][mu (B*L)][sigma (B*L)]
#define OFF_ML  ((size_t)BB * TDD * VV)
#define OFF_MU  (OFF_ML + 1)
#define OFF_SG  (OFF_MU + (size_t)BB * LL)

// ---------------------------------------------------------------------------
// Scratch (static device globals; no allocation allowed)
// ---------------------------------------------------------------------------
__device__ float g_gx_enc[(size_t)BB * TEE * 3 * HH];   // 50.3 MB
__device__ float g_enc_out[(size_t)BB * TEE * HH];      // 16.8 MB
__device__ float g_gx_dec[(size_t)BB * TDD * 3 * LL];   // 12.6 MB
__device__ float g_dec_out[(size_t)BB * TDD * LL];      //  4.2 MB
__device__ float g_hA[BB * HH];
__device__ float g_hB[BB * HH];
__device__ float g_sfw[BB * TEE];
__device__ float g_sbw[BB * TEE];
__device__ float g_henc[BB * 2 * HH];
__device__ float g_z[BB * LL];
__device__ unsigned g_bar_count;
__device__ volatile unsigned g_bar_gen;

// ---------------------------------------------------------------------------
// Grid-wide barrier (R1/R4-proven flat version; all CTAs co-resident)
// ---------------------------------------------------------------------------
__device__ __forceinline__ void grid_barrier(unsigned nb) {
    __threadfence();          // every thread makes its stores visible (release)
    __syncthreads();
    if (threadIdx.x == 0) {
        unsigned gen = g_bar_gen;
        unsigned arrived = atomicAdd(&g_bar_count, 1u);
        if (arrived == nb - 1) {
            g_bar_count = 0;
            __threadfence();
            g_bar_gen = gen + 1;
        } else {
            while (g_bar_gen == gen) { }
        }
        __threadfence();      // acquire
    }
    __syncthreads();
}

__device__ __forceinline__ float sigmoidf_(float x) { return 1.0f / (1.0f + expf(-x)); }

// ---------------------------------------------------------------------------
// Persistent GRU. Grid = K/CW blocks (128). Block owns CW hidden columns.
// smem h pitch = K+4 words (rows 16B-aligned): 16B-group(lane b) = 129b = b
// (mod 8), so every 8-lane LDS.128 phase hits 8 distinct 16B groups ->
// conflict-free float4 loads; staging writes are consecutive -> conflict-free.
// Dot phase: 4 accumulators, 4 LDG.128 + 4 LDS.128 per 16-k chunk.
// ---------------------------------------------------------------------------
template<int K, int CW>
__global__ __launch_bounds__(256, 1) void gru_persist(
    const float* __restrict__ gx,    // [B, T, 3K]  (= x@Wih^T + bih, precomputed)
    const float* __restrict__ Whh,   // [3K, K]
    const float* __restrict__ bhh,   // [3K]
    const int*   __restrict__ lens,  // [B]
    const float* __restrict__ h0,    // [B, K] or nullptr (=> zeros)
    float* hA, float* hB,
    float* __restrict__ out,         // [B, T, K]
    int T)
{
    constexpr int PW = K + 4;            // smem pitch (floats), 16B-aligned rows
    constexpr int NC = 16 * 3 * CW;      // dot-product threads (192 / 96)
    constexpr int NU = 16 * CW;          // update threads (64 / 32)
    __shared__ float hs[16 * PW];
    __shared__ float ex[NC];
    __shared__ int   lens_s[16];

    const int tid = threadIdx.x;
    const int bx  = blockIdx.x;
    const unsigned NB = gridDim.x;

    // dot-thread identity + persistent weight row pointer + bias
    const float4* wp = nullptr;
    float bhv = 0.0f;
    int db = tid & 15;
    if (tid < NC) {
        int didx = tid >> 4;             // 0..3CW-1
        int dg = didx / CW, dcl = didx % CW;
        int dc = bx * CW + dcl;
        wp = (const float4*)(Whh + (size_t)(dg * K + dc) * K);
        bhv = bhh[dg * K + dc];
    }
    // update-thread identity
    int ub = tid & 15, ucl = tid >> 4;
    int uc = bx * CW + ucl;

    if (tid < 16) lens_s[tid] = lens[tid];
    if (tid < NU) {                      // init h buffer A (this block's columns)
        float v = h0 ? h0[ub * K + uc] : 0.0f;
        __stcg(&hA[ub * K + uc], v);
    }
    grid_barrier(NB);

    for (int t = 0; t < T; t++) {
        float* hcur  = (t & 1) ? hB : hA;
        float* hnext = (t & 1) ? hA : hB;

        // prefetch gx[t] for update threads (independent of h -> hides latency)
        float gxr = 0.f, gxz = 0.f, gxn = 0.f;
        if (tid < NU) {
            const float* gxp = gx + (size_t)(ub * T + t) * (3 * K);
            gxr = __ldg(gxp + uc);
            gxz = __ldg(gxp + K + uc);
            gxn = __ldg(gxp + 2 * K + uc);
        }

        // stage full h[B,K] into smem (float4, pitch K+4)
        const float4* hc4 = (const float4*)hcur;
        #pragma unroll
        for (int i = tid; i < 16 * K / 4; i += 256) {
            float4 v = __ldcg(hc4 + i);
            int b = i / (K / 4), kq = i % (K / 4);
            *(float4*)&hs[b * PW + 4 * kq] = v;
        }
        __syncthreads();

        if (tid < NC) {                  // gh[b, g*K+c] = h[b,:] . Whh[g*K+c,:]
            const float4* hp = (const float4*)&hs[db * PW];
            float a0 = 0.f, a1 = 0.f, a2 = 0.f, a3 = 0.f;
            #pragma unroll 4
            for (int kk = 0; kk < K / 16; kk++) {
                float4 w0 = __ldg(wp + 4 * kk + 0);
                float4 w1 = __ldg(wp + 4 * kk + 1);
                float4 w2 = __ldg(wp + 4 * kk + 2);
                float4 w3 = __ldg(wp + 4 * kk + 3);
                float4 h0v = hp[4 * kk + 0];
                float4 h1v = hp[4 * kk + 1];
                float4 h2v = hp[4 * kk + 2];
                float4 h3v = hp[4 * kk + 3];
                a0 += w0.x * h0v.x + w0.y * h0v.y + w0.z * h0v.z + w0.w * h0v.w;
                a1 += w1.x * h1v.x + w1.y * h1v.y + w1.z * h1v.z + w1.w * h1v.w;
                a2 += w2.x * h2v.x + w2.y * h2v.y + w2.z * h2v.z + w2.w * h2v.w;
                a3 += w3.x * h3v.x + w3.y * h3v.y + w3.z * h3v.z + w3.w * h3v.w;
            }
            ex[(tid >> 4) * 16 + db] = ((a0 + a1) + (a2 + a3)) + bhv;
        }
        __syncthreads();

        if (tid < NU) {                  // combine gates, update h, write out
            float ghr = ex[(0 * CW + ucl) * 16 + ub];
            float ghz = ex[(1 * CW + ucl) * 16 + ub];
            float ghn = ex[(2 * CW + ucl) * 16 + ub];
            float r = sigmoidf_(gxr + ghr);
            float z = sigmoidf_(gxz + ghz);
            float n = tanhf   (gxn + r * ghn);
            float hold = hs[ub * PW + uc];
            float hnew = (1.0f - z) * n + z * hold;
            bool valid = (t < lens_s[ub]);
            __stcg(&hnext[ub * K + uc], valid ? hnew : hold);
            out[(size_t)(ub * T + t) * K + uc] = valid ? hnew : 0.0f;
        }
        grid_barrier(NB);
    }
}

// ---------------------------------------------------------------------------
// 128x128x8 fp32 SGEMM-NT, double-buffered smem, 1 sync per k-tile.
// C[i,j] = sum_k A[i,k]*W[j,k] + bias[j]
// Optional row gather (A row i = Atab + ids[i]*KD) and zero-row tile skip.
// ---------------------------------------------------------------------------
template<int KD>
__global__ __launch_bounds__(256, 2) void gemm_nt128(
    float* __restrict__ C,
    const float* __restrict__ Adirect,
    const int*   __restrict__ ids,
    const float* __restrict__ Atab,
    const float* __restrict__ W,
    const float* __restrict__ bias,
    int N,
    const int* __restrict__ skiplen,   // optional: row i -> b=i/tper, t=i%tper
    int tper)
{
    __shared__ float As[2][8][128];
    __shared__ float Bs[2][8][128];
    const int tid  = threadIdx.x;
    const int row0 = blockIdx.y * 128, col0 = blockIdx.x * 128;
    const int ty = tid >> 4, tx = tid & 15;

    if (skiplen) {   // whole M-tile is zero rows -> output = bias only
        int bb = row0 / tper, t0 = row0 % tper;
        if (t0 >= __ldg(&skiplen[bb])) {
            float4 blo = *(const float4*)(bias + col0 + tx * 8);
            float4 bhi = *(const float4*)(bias + col0 + tx * 8 + 4);
            #pragma unroll
            for (int i = 0; i < 8; i++) {
                float* cp = C + (size_t)(row0 + ty * 8 + i) * N + col0 + tx * 8;
                *(float4*)cp = blo; *(float4*)(cp + 4) = bhi;
            }
            return;
        }
    }

    const int lr  = tid >> 1;
    const int lk4 = (tid & 1) * 4;
    const float* arow = ids ? (Atab + (size_t)__ldg(&ids[row0 + lr]) * KD)
                            : (Adirect + (size_t)(row0 + lr) * KD);
    const float* wrow = W + (size_t)(col0 + lr) * KD;

    // prologue: fill buffer 0
    {
        float4 av = *(const float4*)(arow + lk4);
        float4 wv = *(const float4*)(wrow + lk4);
        As[0][lk4 + 0][lr] = av.x; As[0][lk4 + 1][lr] = av.y;
        As[0][lk4 + 2][lr] = av.z; As[0][lk4 + 3][lr] = av.w;
        Bs[0][lk4 + 0][lr] = wv.x; Bs[0][lk4 + 1][lr] = wv.y;
        Bs[0][lk4 + 2][lr] = wv.z; Bs[0][lk4 + 3][lr] = wv.w;
    }
    __syncthreads();

    float acc[8][8];
    #pragma unroll
    for (int i = 0; i < 8; i++)
        #pragma unroll
        for (int j = 0; j < 8; j++) acc[i][j] = 0.0f;

    constexpr int NK = KD / 8;
    #pragma unroll 1
    for (int kt = 0; kt < NK; kt++) {
        const int cur = kt & 1;
        float4 av2, wv2;
        if (kt + 1 < NK) {
            av2 = *(const float4*)(arow + (kt + 1) * 8 + lk4);
            wv2 = *(const float4*)(wrow + (kt + 1) * 8 + lk4);
        }
        #pragma unroll
        for (int k = 0; k < 8; k++) {
            float a[8], b[8];
            *(float4*)&a[0] = *(const float4*)&As[cur][k][ty * 8];
            *(float4*)&a[4] = *(const float4*)&As[cur][k][ty * 8 + 4];
            *(float4*)&b[0] = *(const float4*)&Bs[cur][k][tx * 8];
            *(float4*)&b[4] = *(const float4*)&Bs[cur][k][tx * 8 + 4];
            #pragma unroll
            for (int i = 0; i < 8; i++)
                #pragma unroll
                for (int j = 0; j < 8; j++)
                    acc[i][j] += a[i] * b[j];
        }
        if (kt + 1 < NK) {
            const int nxt = cur ^ 1;
            As[nxt][lk4 + 0][lr] = av2.x; As[nxt][lk4 + 1][lr] = av2.y;
            As[nxt][lk4 + 2][lr] = av2.z; As[nxt][lk4 + 3][lr] = av2.w;
            Bs[nxt][lk4 + 0][lr] = wv2.x; Bs[nxt][lk4 + 1][lr] = wv2.y;
            Bs[nxt][lk4 + 2][lr] = wv2.z; Bs[nxt][lk4 + 3][lr] = wv2.w;
        }
        __syncthreads();
    }

    float4 blo = *(const float4*)(bias + col0 + tx * 8);
    float4 bhi = *(const float4*)(bias + col0 + tx * 8 + 4);
    #pragma unroll
    for (int i = 0; i < 8; i++) {
        float* cp = C + (size_t)(row0 + ty * 8 + i) * N + col0 + tx * 8;
        float4 v0 = make_float4(acc[i][0] + blo.x, acc[i][1] + blo.y,
                                acc[i][2] + blo.z, acc[i][3] + blo.w);
        float4 v1 = make_float4(acc[i][4] + bhi.x, acc[i][5] + bhi.y,
                                acc[i][6] + bhi.z, acc[i][7] + bhi.w);
        *(float4*)cp = v0; *(float4*)(cp + 4) = v1;
    }
}

// ---------------------------------------------------------------------------
// Padding no-ops: profiled slot = my 4th launch => 2 noops put gru_enc there
// ---------------------------------------------------------------------------
__global__ void noop_a() {}
__global__ void noop_b() {}

// ---------------------------------------------------------------------------
// Attention scores (R1-proven): sfw[b,t] = out[b,t,:].last[b,:]; sbw with first
// ---------------------------------------------------------------------------
__global__ __launch_bounds__(256) void attn_scores() {
    const int b = blockIdx.x, tid = threadIdx.x;
    __shared__ float last_s[HH], first_s[HH];
    for (int i = tid; i < HH; i += 256) {
        last_s[i]  = g_hA[b * HH + i];
        first_s[i] = g_enc_out[((size_t)b * TEE + 0) * HH + i];
    }
    __syncthreads();
    const int w = tid >> 5, lane = tid & 31;
    for (int t = w; t < TEE; t += 8) {
        const float* orow = g_enc_out + ((size_t)(b * TEE + t)) * HH;
        float af = 0.0f, ab = 0.0f;
        #pragma unroll 4
        for (int i = lane; i < HH; i += 32) {
            float v = orow[i];
            af += v * last_s[i];
            ab += v * first_s[i];
        }
        #pragma unroll
        for (int o = 16; o > 0; o >>= 1) {
            af += __shfl_xor_sync(0xffffffffu, af, o);
            ab += __shfl_xor_sync(0xffffffffu, ab, o);
        }
        if (lane == 0) { g_sfw[b * TEE + t] = af; g_sbw[b * TEE + t] = ab; }
    }
}

__device__ __forceinline__ float blk_reduce(float v, float* red, bool ismax) {
    #pragma unroll
    for (int o = 16; o > 0; o >>= 1) {
        float u = __shfl_xor_sync(0xffffffffu, v, o);
        v = ismax ? fmaxf(v, u) : (v + u);
    }
    int w = threadIdx.x >> 5;
    if ((threadIdx.x & 31) == 0) red[w] = v;
    __syncthreads();
    if (threadIdx.x == 0) {
        float a = red[0];
        for (int i = 1; i < 8; i++) a = ismax ? fmaxf(a, red[i]) : (a + red[i]);
        red[0] = a;
    }
    __syncthreads();
    float r = red[0];
    __syncthreads();
    return r;
}

// ---------------------------------------------------------------------------
// Masked dual softmax + semantic pooling + h_enc assembly (R1-proven).
// ---------------------------------------------------------------------------
__global__ __launch_bounds__(256) void softmax_semantic(const int* __restrict__ enc_len) {
    const int b = blockIdx.x, tid = threadIdx.x;
    const int len = enc_len[b];
    __shared__ float sa[TEE];
    __shared__ float red[8];

    // forward pass
    float v0 = (tid       < len) ? g_sfw[b * TEE + tid]       : -1e30f;
    float v1 = (tid + 256 < len) ? g_sfw[b * TEE + tid + 256] : -1e30f;
    float M = blk_reduce(fmaxf(v0, v1), red, true);
    float e0 = (tid       < len) ? expf(v0 - M) : 0.0f;
    float e1 = (tid + 256 < len) ? expf(v1 - M) : 0.0f;
    float S = blk_reduce(e0 + e1, red, false);
    float inv = 0.5f / S;
    sa[tid] = e0 * inv; sa[tid + 256] = e1 * inv;
    __syncthreads();

    // backward pass
    v0 = (tid       < len) ? g_sbw[b * TEE + tid]       : -1e30f;
    v1 = (tid + 256 < len) ? g_sbw[b * TEE + tid + 256] : -1e30f;
    M = blk_reduce(fmaxf(v0, v1), red, true);
    e0 = (tid       < len) ? expf(v0 - M) : 0.0f;
    e1 = (tid + 256 < len) ? expf(v1 - M) : 0.0f;
    S = blk_reduce(e0 + e1, red, false);
    inv = 0.5f / S;
    sa[tid] += e0 * inv; sa[tid + 256] += e1 * inv;
    __syncthreads();

    // semantic[b,d] = sum_t alpha[t] * out[b,t,d];  h_enc = [last, semantic]
    for (int d = tid; d < HH; d += 256) {
        float acc = 0.0f;
        #pragma unroll 4
        for (int t = 0; t < TEE; t++)
            acc += sa[t] * g_enc_out[((size_t)(b * TEE + t)) * HH + d];
        g_henc[b * 2 * HH + HH + d] = acc;
        g_henc[b * 2 * HH + d] = g_hA[b * HH + d];
    }
}

// ---------------------------------------------------------------------------
// Latent head (R1-proven): mu/sigma/z + tail outputs. 1 block per b.
// ---------------------------------------------------------------------------
__global__ __launch_bounds__(256) void latent_head(
    const float* __restrict__ W_mu, const float* __restrict__ b_mu,
    const float* __restrict__ W_ls, const float* __restrict__ b_ls,
    const float* __restrict__ noise, const int* __restrict__ dec_len,
    float* __restrict__ outbuf)
{
    const int b = blockIdx.x, tid = threadIdx.x;
    __shared__ float he[2 * HH];
    __shared__ float muv[LL], lsv[LL];
    for (int i = tid; i < 2 * HH; i += 256) he[i] = g_henc[b * 2 * HH + i];
    __syncthreads();

    const int w = tid >> 5, lane = tid & 31;
    for (int o = w; o < 2 * LL; o += 8) {
        const float* Wr; float bia; int j;
        if (o < LL) { j = o;      Wr = W_mu + (size_t)j * (2 * HH); bia = b_mu[j]; }
        else        { j = o - LL; Wr = W_ls + (size_t)j * (2 * HH); bia = b_ls[j]; }
        float acc = 0.0f;
        #pragma unroll 4
        for (int k = lane; k < 2 * HH; k += 32) acc += Wr[k] * he[k];
        #pragma unroll
        for (int s = 16; s > 0; s >>= 1) acc += __shfl_xor_sync(0xffffffffu, acc, s);
        if (lane == 0) { if (o < LL) muv[j] = acc + bia; else lsv[j] = acc + bia; }
    }
    __syncthreads();

    if (tid < LL) {
        float mu = muv[tid];
        float sg = expf(lsv[tid]);
        float zz = mu + sg * noise[b * LL + tid];
        g_z[b * LL + tid] = zz;
        outbuf[OFF_MU + b * LL + tid] = mu;
        outbuf[OFF_SG + b * LL + tid] = sg;
    }
    if (b == 0 && tid == 0) {
        int m = 0;
        for (int i = 0; i < BB; i++) m = max(m, dec_len[i]);
        outbuf[OFF_ML] = (float)m;
    }
}

// ---------------------------------------------------------------------------
// Launch
// ---------------------------------------------------------------------------
extern "C" void kernel_launch(void* const* d_in, const int* in_sizes, int n_in,
                              void* d_out, int out_size) {
    const float* emb     = (const float*)d_in[0];
    const float* enc_Wih = (const float*)d_in[1];
    const float* enc_Whh = (const float*)d_in[2];
    const float* enc_bih = (const float*)d_in[3];
    const float* enc_bhh = (const float*)d_in[4];
    const float* dec_Wih = (const float*)d_in[5];
    const float* dec_Whh = (const float*)d_in[6];
    const float* dec_bih = (const float*)d_in[7];
    const float* dec_bhh = (const float*)d_in[8];
    const float* W_mu    = (const float*)d_in[9];
    const float* b_mu    = (const float*)d_in[10];
    const float* W_ls    = (const float*)d_in[11];
    const float* b_ls    = (const float*)d_in[12];
    const float* W_fc    = (const float*)d_in[13];
    const float* b_fc    = (const float*)d_in[14];
    const float* noise   = (const float*)d_in[15];
    const int*   enc_ids = (const int*)d_in[16];
    const int*   enc_len = (const int*)d_in[17];
    const int*   dec_ids = (const int*)d_in[18];
    const int*   dec_len = (const int*)d_in[19];
    float* outbuf = (float*)d_out;

    float *p_gx_enc, *p_enc_out, *p_gx_dec, *p_dec_out, *p_hA, *p_hB, *p_z;
    cudaGetSymbolAddress((void**)&p_gx_enc, g_gx_enc);
    cudaGetSymbolAddress((void**)&p_enc_out, g_enc_out);
    cudaGetSymbolAddress((void**)&p_gx_dec, g_gx_dec);
    cudaGetSymbolAddress((void**)&p_dec_out, g_dec_out);
    cudaGetSymbolAddress((void**)&p_hA, g_hA);
    cudaGetSymbolAddress((void**)&p_hB, g_hB);
    cudaGetSymbolAddress((void**)&p_z, g_z);

    // 1) gx_enc = emb[enc_ids] @ enc_Wih^T + bih   [8192 x 1536, K=512]
    gemm_nt128<512><<<dim3(1536 / 128, (BB * TEE) / 128), 256>>>(
        p_gx_enc, nullptr, enc_ids, emb, enc_Wih, enc_bih, 3 * HH, nullptr, 1);

    // 2-3) padding no-ops (keep gru_enc at my launch #4 = profiled slot)
    noop_a<<<1, 32>>>();
    noop_b<<<1, 32>>>();

    // 4) encoder GRU (persistent, 512 steps)  <-- profiled launch
    gru_persist<HH, 4><<<HH / 4, 256>>>(
        p_gx_enc, enc_Whh, enc_bhh, enc_len, nullptr, p_hA, p_hB, p_enc_out, TEE);

    // 5-7) attention + latent path (R1 versions)
    attn_scores<<<BB, 256>>>();
    softmax_semantic<<<BB, 256>>>(enc_len);
    latent_head<<<BB, 256>>>(W_mu, b_mu, W_ls, b_ls, noise, dec_len, outbuf);

    // 8) gx_dec = emb[dec_ids] @ dec_Wih^T + bih   [4096 x 768, K=512]
    gemm_nt128<512><<<dim3((3 * LL) / 128, (BB * TDD) / 128), 256>>>(
        p_gx_dec, nullptr, dec_ids, emb, dec_Wih, dec_bih, 3 * LL, nullptr, 1);

    // 9) decoder GRU (persistent, 256 steps), h0 = z
    gru_persist<LL, 2><<<LL / 2, 256>>>(
        p_gx_dec, dec_Whh, dec_bhh, dec_len, p_z, p_hA, p_hB, p_dec_out, TDD);

    // 10) logits = dec_out @ W_fc^T + b_fc  [4096 x 32000, K=256], zero-row skip
    gemm_nt128<256><<<dim3(VV / 128, (BB * TDD) / 128), 256>>>(
        outbuf, p_dec_out, nullptr, nullptr, W_fc, b_fc, VV, dec_len, TDD);
}

// round 7
// speedup vs baseline: 1.1743x; 1.0848x over previous
#include <cuda_runtime.h>
#include <math.h>
#include <stdint.h>

// Problem dims
#define VV 32000
#define HH 512
#define LL 256
#define BB 16
#define TEE 512
#define TDD 256

// Output layout: [logits (B*TD*V)][dec_max_len (1)][mu (B*L)][sigma (B*L)]
#define OFF_ML  ((size_t)BB * TDD * VV)
#define OFF_MU  (OFF_ML + 1)
#define OFF_SG  (OFF_MU + (size_t)BB * LL)

// ---------------------------------------------------------------------------
// Scratch (static device globals; no allocation allowed)
// ---------------------------------------------------------------------------
__device__ float g_gx_enc[(size_t)BB * TEE * 3 * HH];   // 50.3 MB
__device__ float g_enc_out[(size_t)BB * TEE * HH];      // 16.8 MB
__device__ float g_gx_dec[(size_t)BB * TDD * 3 * LL];   // 12.6 MB
__device__ float g_dec_out[(size_t)BB * TDD * LL];      //  4.2 MB
__device__ float g_hA[BB * HH];
__device__ float g_hB[BB * HH];
__device__ float g_sfw[BB * TEE];
__device__ float g_sbw[BB * TEE];
__device__ float g_henc[BB * 2 * HH];
__device__ float g_z[BB * LL];
__device__ unsigned g_bar_count;
__device__ volatile unsigned g_bar_gen;

// ---------------------------------------------------------------------------
// Grid-wide barrier (R1/R4-proven flat version; all CTAs co-resident)
// ---------------------------------------------------------------------------
__device__ __forceinline__ void grid_barrier(unsigned nb) {
    __threadfence();          // every thread makes its stores visible (release)
    __syncthreads();
    if (threadIdx.x == 0) {
        unsigned gen = g_bar_gen;
        unsigned arrived = atomicAdd(&g_bar_count, 1u);
        if (arrived == nb - 1) {
            g_bar_count = 0;
            __threadfence();
            g_bar_gen = gen + 1;
        } else {
            while (g_bar_gen == gen) { }
        }
        __threadfence();      // acquire
    }
    __syncthreads();
}

__device__ __forceinline__ float sigmoidf_(float x) { return 1.0f / (1.0f + expf(-x)); }

// ---------------------------------------------------------------------------
// Persistent GRU, 512 threads, 2-way K-split dot phase.
// Grid = K/CW blocks (128). Block owns CW hidden columns.
// Dot threads: tid < 16*3CW*2; lane db=tid&15, half=(tid>>4)&1, didx=tid>>5.
// Each computes a K/2-length partial of gh[b, didx]; partials summed by the
// update threads. smem h pitch = K+4 (16B-aligned rows): lane 16B-group =
// db*129 + half*(K/8) + k = db (mod 8) -> conflict-free LDS.128.
// ---------------------------------------------------------------------------
template<int K, int CW>
__global__ __launch_bounds__(512, 1) void gru_persist(
    const float* __restrict__ gx,    // [B, T, 3K]  (= x@Wih^T + bih, precomputed)
    const float* __restrict__ Whh,   // [3K, K]
    const float* __restrict__ bhh,   // [3K]
    const int*   __restrict__ lens,  // [B]
    const float* __restrict__ h0,    // [B, K] or nullptr (=> zeros)
    float* hA, float* hB,
    float* __restrict__ out,         // [B, T, K]
    int T)
{
    constexpr int PW = K + 4;            // smem pitch (floats), 16B-aligned rows
    constexpr int NC = 16 * 3 * CW * 2;  // dot threads (384 enc / 192 dec)
    constexpr int NU = 16 * CW;          // update threads (64 / 32)
    constexpr int KH = K / 2;            // half-K per dot thread
    __shared__ float hs[16 * PW];
    __shared__ float pex[16 * 3 * CW * 2];   // [didx][half*16 + b]
    __shared__ int   lens_s[16];

    const int tid = threadIdx.x;
    const int bx  = blockIdx.x;
    const unsigned NB = gridDim.x;

    // dot-thread identity + persistent weight half-row pointer + bias
    const float4* wp = nullptr;
    float bhv = 0.0f;
    int db = tid & 15;
    int half = (tid >> 4) & 1;
    int didx = tid >> 5;                 // 0..3CW-1
    if (tid < NC) {
        int dg = didx / CW, dcl = didx % CW;
        int dc = bx * CW + dcl;
        wp = (const float4*)(Whh + (size_t)(dg * K + dc) * K + half * KH);
        bhv = (half == 0) ? bhh[dg * K + dc] : 0.0f;
    }
    // update-thread identity
    int ub = tid & 15, ucl = tid >> 4;
    int uc = bx * CW + ucl;

    if (tid < 16) lens_s[tid] = lens[tid];
    if (tid < NU) {                      // init h buffer A (this block's columns)
        float v = h0 ? h0[ub * K + uc] : 0.0f;
        __stcg(&hA[ub * K + uc], v);
    }
    grid_barrier(NB);

    for (int t = 0; t < T; t++) {
        float* hcur  = (t & 1) ? hB : hA;
        float* hnext = (t & 1) ? hA : hB;

        // prefetch gx[t] for update threads (independent of h -> hides latency)
        float gxr = 0.f, gxz = 0.f, gxn = 0.f;
        if (tid < NU) {
            const float* gxp = gx + (size_t)(ub * T + t) * (3 * K);
            gxr = __ldg(gxp + uc);
            gxz = __ldg(gxp + K + uc);
            gxn = __ldg(gxp + 2 * K + uc);
        }

        // stage full h[B,K] into smem (float4, pitch K+4), 512 threads
        const float4* hc4 = (const float4*)hcur;
        #pragma unroll
        for (int i = tid; i < 16 * K / 4; i += 512) {
            float4 v = __ldcg(hc4 + i);
            int b = i / (K / 4), kq = i % (K / 4);
            *(float4*)&hs[b * PW + 4 * kq] = v;
        }
        __syncthreads();

        if (tid < NC) {     // partial gh over K/2: h[b, half*KH .. +KH) . w
            const float4* hp = (const float4*)&hs[db * PW + half * KH];
            float a0 = 0.f, a1 = 0.f, a2 = 0.f, a3 = 0.f;
            #pragma unroll 4
            for (int kk = 0; kk < KH / 16; kk++) {
                float4 w0 = __ldg(wp + 4 * kk + 0);
                float4 w1 = __ldg(wp + 4 * kk + 1);
                float4 w2 = __ldg(wp + 4 * kk + 2);
                float4 w3 = __ldg(wp + 4 * kk + 3);
                float4 h0v = hp[4 * kk + 0];
                float4 h1v = hp[4 * kk + 1];
                float4 h2v = hp[4 * kk + 2];
                float4 h3v = hp[4 * kk + 3];
                a0 += w0.x * h0v.x + w0.y * h0v.y + w0.z * h0v.z + w0.w * h0v.w;
                a1 += w1.x * h1v.x + w1.y * h1v.y + w1.z * h1v.z + w1.w * h1v.w;
                a2 += w2.x * h2v.x + w2.y * h2v.y + w2.z * h2v.z + w2.w * h2v.w;
                a3 += w3.x * h3v.x + w3.y * h3v.y + w3.z * h3v.z + w3.w * h3v.w;
            }
            pex[didx * 32 + (half << 4) + db] = ((a0 + a1) + (a2 + a3)) + bhv;
        }
        __syncthreads();

        if (tid < NU) {                  // combine halves + gates, update h
            float ghr = pex[(0 * CW + ucl) * 32 + ub] + pex[(0 * CW + ucl) * 32 + 16 + ub];
            float ghz = pex[(1 * CW + ucl) * 32 + ub] + pex[(1 * CW + ucl) * 32 + 16 + ub];
            float ghn = pex[(2 * CW + ucl) * 32 + ub] + pex[(2 * CW + ucl) * 32 + 16 + ub];
            float r = sigmoidf_(gxr + ghr);
            float z = sigmoidf_(gxz + ghz);
            float n = tanhf   (gxn + r * ghn);
            float hold = hs[ub * PW + uc];
            float hnew = (1.0f - z) * n + z * hold;
            bool valid = (t < lens_s[ub]);
            __stcg(&hnext[ub * K + uc], valid ? hnew : hold);
            out[(size_t)(ub * T + t) * K + uc] = valid ? hnew : 0.0f;
        }
        grid_barrier(NB);
    }
}

// ---------------------------------------------------------------------------
// 128x128x8 fp32 SGEMM-NT, double-buffered smem, 1 sync per k-tile.
// C[i,j] = sum_k A[i,k]*W[j,k] + bias[j]
// Optional row gather (A row i = Atab + ids[i]*KD) and zero-row tile skip.
// ---------------------------------------------------------------------------
template<int KD>
__global__ __launch_bounds__(256, 2) void gemm_nt128(
    float* __restrict__ C,
    const float* __restrict__ Adirect,
    const int*   __restrict__ ids,
    const float* __restrict__ Atab,
    const float* __restrict__ W,
    const float* __restrict__ bias,
    int N,
    const int* __restrict__ skiplen,   // optional: row i -> b=i/tper, t=i%tper
    int tper)
{
    __shared__ float As[2][8][128];
    __shared__ float Bs[2][8][128];
    const int tid  = threadIdx.x;
    const int row0 = blockIdx.y * 128, col0 = blockIdx.x * 128;
    const int ty = tid >> 4, tx = tid & 15;

    if (skiplen) {   // whole M-tile is zero rows -> output = bias only
        int bb = row0 / tper, t0 = row0 % tper;
        if (t0 >= __ldg(&skiplen[bb])) {
            float4 blo = *(const float4*)(bias + col0 + tx * 8);
            float4 bhi = *(const float4*)(bias + col0 + tx * 8 + 4);
            #pragma unroll
            for (int i = 0; i < 8; i++) {
                float* cp = C + (size_t)(row0 + ty * 8 + i) * N + col0 + tx * 8;
                *(float4*)cp = blo; *(float4*)(cp + 4) = bhi;
            }
            return;
        }
    }

    const int lr  = tid >> 1;
    const int lk4 = (tid & 1) * 4;
    const float* arow = ids ? (Atab + (size_t)__ldg(&ids[row0 + lr]) * KD)
                            : (Adirect + (size_t)(row0 + lr) * KD);
    const float* wrow = W + (size_t)(col0 + lr) * KD;

    // prologue: fill buffer 0
    {
        float4 av = *(const float4*)(arow + lk4);
        float4 wv = *(const float4*)(wrow + lk4);
        As[0][lk4 + 0][lr] = av.x; As[0][lk4 + 1][lr] = av.y;
        As[0][lk4 + 2][lr] = av.z; As[0][lk4 + 3][lr] = av.w;
        Bs[0][lk4 + 0][lr] = wv.x; Bs[0][lk4 + 1][lr] = wv.y;
        Bs[0][lk4 + 2][lr] = wv.z; Bs[0][lk4 + 3][lr] = wv.w;
    }
    __syncthreads();

    float acc[8][8];
    #pragma unroll
    for (int i = 0; i < 8; i++)
        #pragma unroll
        for (int j = 0; j < 8; j++) acc[i][j] = 0.0f;

    constexpr int NK = KD / 8;
    #pragma unroll 1
    for (int kt = 0; kt < NK; kt++) {
        const int cur = kt & 1;
        float4 av2, wv2;
        if (kt + 1 < NK) {
            av2 = *(const float4*)(arow + (kt + 1) * 8 + lk4);
            wv2 = *(const float4*)(wrow + (kt + 1) * 8 + lk4);
        }
        #pragma unroll
        for (int k = 0; k < 8; k++) {
            float a[8], b[8];
            *(float4*)&a[0] = *(const float4*)&As[cur][k][ty * 8];
            *(float4*)&a[4] = *(const float4*)&As[cur][k][ty * 8 + 4];
            *(float4*)&b[0] = *(const float4*)&Bs[cur][k][tx * 8];
            *(float4*)&b[4] = *(const float4*)&Bs[cur][k][tx * 8 + 4];
            #pragma unroll
            for (int i = 0; i < 8; i++)
                #pragma unroll
                for (int j = 0; j < 8; j++)
                    acc[i][j] += a[i] * b[j];
        }
        if (kt + 1 < NK) {
            const int nxt = cur ^ 1;
            As[nxt][lk4 + 0][lr] = av2.x; As[nxt][lk4 + 1][lr] = av2.y;
            As[nxt][lk4 + 2][lr] = av2.z; As[nxt][lk4 + 3][lr] = av2.w;
            Bs[nxt][lk4 + 0][lr] = wv2.x; Bs[nxt][lk4 + 1][lr] = wv2.y;
            Bs[nxt][lk4 + 2][lr] = wv2.z; Bs[nxt][lk4 + 3][lr] = wv2.w;
        }
        __syncthreads();
    }

    float4 blo = *(const float4*)(bias + col0 + tx * 8);
    float4 bhi = *(const float4*)(bias + col0 + tx * 8 + 4);
    #pragma unroll
    for (int i = 0; i < 8; i++) {
        float* cp = C + (size_t)(row0 + ty * 8 + i) * N + col0 + tx * 8;
        float4 v0 = make_float4(acc[i][0] + blo.x, acc[i][1] + blo.y,
                                acc[i][2] + blo.z, acc[i][3] + blo.w);
        float4 v1 = make_float4(acc[i][4] + bhi.x, acc[i][5] + bhi.y,
                                acc[i][6] + bhi.z, acc[i][7] + bhi.w);
        *(float4*)cp = v0; *(float4*)(cp + 4) = v1;
    }
}

// ---------------------------------------------------------------------------
// Padding no-ops: profiled slot = my 4th launch => 2 noops put gru_enc there
// ---------------------------------------------------------------------------
__global__ void noop_a() {}
__global__ void noop_b() {}

// ---------------------------------------------------------------------------
// Attention scores (R1-proven): sfw[b,t] = out[b,t,:].last[b,:]; sbw with first
// ---------------------------------------------------------------------------
__global__ __launch_bounds__(256) void attn_scores() {
    const int b = blockIdx.x, tid = threadIdx.x;
    __shared__ float last_s[HH], first_s[HH];
    for (int i = tid; i < HH; i += 256) {
        last_s[i]  = g_hA[b * HH + i];
        first_s[i] = g_enc_out[((size_t)b * TEE + 0) * HH + i];
    }
    __syncthreads();
    const int w = tid >> 5, lane = tid & 31;
    for (int t = w; t < TEE; t += 8) {
        const float* orow = g_enc_out + ((size_t)(b * TEE + t)) * HH;
        float af = 0.0f, ab = 0.0f;
        #pragma unroll 4
        for (int i = lane; i < HH; i += 32) {
            float v = orow[i];
            af += v * last_s[i];
            ab += v * first_s[i];
        }
        #pragma unroll
        for (int o = 16; o > 0; o >>= 1) {
            af += __shfl_xor_sync(0xffffffffu, af, o);
            ab += __shfl_xor_sync(0xffffffffu, ab, o);
        }
        if (lane == 0) { g_sfw[b * TEE + t] = af; g_sbw[b * TEE + t] = ab; }
    }
}

__device__ __forceinline__ float blk_reduce(float v, float* red, bool ismax) {
    #pragma unroll
    for (int o = 16; o > 0; o >>= 1) {
        float u = __shfl_xor_sync(0xffffffffu, v, o);
        v = ismax ? fmaxf(v, u) : (v + u);
    }
    int w = threadIdx.x >> 5;
    if ((threadIdx.x & 31) == 0) red[w] = v;
    __syncthreads();
    if (threadIdx.x == 0) {
        float a = red[0];
        for (int i = 1; i < 8; i++) a = ismax ? fmaxf(a, red[i]) : (a + red[i]);
        red[0] = a;
    }
    __syncthreads();
    float r = red[0];
    __syncthreads();
    return r;
}

// ---------------------------------------------------------------------------
// Masked dual softmax + semantic pooling + h_enc assembly (R1-proven).
// ---------------------------------------------------------------------------
__global__ __launch_bounds__(256) void softmax_semantic(const int* __restrict__ enc_len) {
    const int b = blockIdx.x, tid = threadIdx.x;
    const int len = enc_len[b];
    __shared__ float sa[TEE];
    __shared__ float red[8];

    // forward pass
    float v0 = (tid       < len) ? g_sfw[b * TEE + tid]       : -1e30f;
    float v1 = (tid + 256 < len) ? g_sfw[b * TEE + tid + 256] : -1e30f;
    float M = blk_reduce(fmaxf(v0, v1), red, true);
    float e0 = (tid       < len) ? expf(v0 - M) : 0.0f;
    float e1 = (tid + 256 < len) ? expf(v1 - M) : 0.0f;
    float S = blk_reduce(e0 + e1, red, false);
    float inv = 0.5f / S;
    sa[tid] = e0 * inv; sa[tid + 256] = e1 * inv;
    __syncthreads();

    // backward pass
    v0 = (tid       < len) ? g_sbw[b * TEE + tid]       : -1e30f;
    v1 = (tid + 256 < len) ? g_sbw[b * TEE + tid + 256] : -1e30f;
    M = blk_reduce(fmaxf(v0, v1), red, true);
    e0 = (tid       < len) ? expf(v0 - M) : 0.0f;
    e1 = (tid + 256 < len) ? expf(v1 - M) : 0.0f;
    S = blk_reduce(e0 + e1, red, false);
    inv = 0.5f / S;
    sa[tid] += e0 * inv; sa[tid + 256] += e1 * inv;
    __syncthreads();

    // semantic[b,d] = sum_t alpha[t] * out[b,t,d];  h_enc = [last, semantic]
    for (int d = tid; d < HH; d += 256) {
        float acc = 0.0f;
        #pragma unroll 4
        for (int t = 0; t < TEE; t++)
            acc += sa[t] * g_enc_out[((size_t)(b * TEE + t)) * HH + d];
        g_henc[b * 2 * HH + HH + d] = acc;
        g_henc[b * 2 * HH + d] = g_hA[b * HH + d];
    }
}

// ---------------------------------------------------------------------------
// Latent head (R1-proven): mu/sigma/z + tail outputs. 1 block per b.
// ---------------------------------------------------------------------------
__global__ __launch_bounds__(256) void latent_head(
    const float* __restrict__ W_mu, const float* __restrict__ b_mu,
    const float* __restrict__ W_ls, const float* __restrict__ b_ls,
    const float* __restrict__ noise, const int* __restrict__ dec_len,
    float* __restrict__ outbuf)
{
    const int b = blockIdx.x, tid = threadIdx.x;
    __shared__ float he[2 * HH];
    __shared__ float muv[LL], lsv[LL];
    for (int i = tid; i < 2 * HH; i += 256) he[i] = g_henc[b * 2 * HH + i];
    __syncthreads();

    const int w = tid >> 5, lane = tid & 31;
    for (int o = w; o < 2 * LL; o += 8) {
        const float* Wr; float bia; int j;
        if (o < LL) { j = o;      Wr = W_mu + (size_t)j * (2 * HH); bia = b_mu[j]; }
        else        { j = o - LL; Wr = W_ls + (size_t)j * (2 * HH); bia = b_ls[j]; }
        float acc = 0.0f;
        #pragma unroll 4
        for (int k = lane; k < 2 * HH; k += 32) acc += Wr[k] * he[k];
        #pragma unroll
        for (int s = 16; s > 0; s >>= 1) acc += __shfl_xor_sync(0xffffffffu, acc, s);
        if (lane == 0) { if (o < LL) muv[j] = acc + bia; else lsv[j] = acc + bia; }
    }
    __syncthreads();

    if (tid < LL) {
        float mu = muv[tid];
        float sg = expf(lsv[tid]);
        float zz = mu + sg * noise[b * LL + tid];
        g_z[b * LL + tid] = zz;
        outbuf[OFF_MU + b * LL + tid] = mu;
        outbuf[OFF_SG + b * LL + tid] = sg;
    }
    if (b == 0 && tid == 0) {
        int m = 0;
        for (int i = 0; i < BB; i++) m = max(m, dec_len[i]);
        outbuf[OFF_ML] = (float)m;
    }
}

// ---------------------------------------------------------------------------
// Launch
// ---------------------------------------------------------------------------
extern "C" void kernel_launch(void* const* d_in, const int* in_sizes, int n_in,
                              void* d_out, int out_size) {
    const float* emb     = (const float*)d_in[0];
    const float* enc_Wih = (const float*)d_in[1];
    const float* enc_Whh = (const float*)d_in[2];
    const float* enc_bih = (const float*)d_in[3];
    const float* enc_bhh = (const float*)d_in[4];
    const float* dec_Wih = (const float*)d_in[5];
    const float* dec_Whh = (const float*)d_in[6];
    const float* dec_bih = (const float*)d_in[7];
    const float* dec_bhh = (const float*)d_in[8];
    const float* W_mu    = (const float*)d_in[9];
    const float* b_mu    = (const float*)d_in[10];
    const float* W_ls    = (const float*)d_in[11];
    const float* b_ls    = (const float*)d_in[12];
    const float* W_fc    = (const float*)d_in[13];
    const float* b_fc    = (const float*)d_in[14];
    const float* noise   = (const float*)d_in[15];
    const int*   enc_ids = (const int*)d_in[16];
    const int*   enc_len = (const int*)d_in[17];
    const int*   dec_ids = (const int*)d_in[18];
    const int*   dec_len = (const int*)d_in[19];
    float* outbuf = (float*)d_out;

    float *p_gx_enc, *p_enc_out, *p_gx_dec, *p_dec_out, *p_hA, *p_hB, *p_z;
    cudaGetSymbolAddress((void**)&p_gx_enc, g_gx_enc);
    cudaGetSymbolAddress((void**)&p_enc_out, g_enc_out);
    cudaGetSymbolAddress((void**)&p_gx_dec, g_gx_dec);
    cudaGetSymbolAddress((void**)&p_dec_out, g_dec_out);
    cudaGetSymbolAddress((void**)&p_hA, g_hA);
    cudaGetSymbolAddress((void**)&p_hB, g_hB);
    cudaGetSymbolAddress((void**)&p_z, g_z);

    // 1) gx_enc = emb[enc_ids] @ enc_Wih^T + bih   [8192 x 1536, K=512]
    gemm_nt128<512><<<dim3(1536 / 128, (BB * TEE) / 128), 256>>>(
        p_gx_enc, nullptr, enc_ids, emb, enc_Wih, enc_bih, 3 * HH, nullptr, 1);

    // 2-3) padding no-ops (keep gru_enc at my launch #4 = profiled slot)
    noop_a<<<1, 32>>>();
    noop_b<<<1, 32>>>();

    // 4) encoder GRU (persistent, 512 steps, 512 threads)  <-- profiled launch
    gru_persist<HH, 4><<<HH / 4, 512>>>(
        p_gx_enc, enc_Whh, enc_bhh, enc_len, nullptr, p_hA, p_hB, p_enc_out, TEE);

    // 5-7) attention + latent path (R1 versions)
    attn_scores<<<BB, 256>>>();
    softmax_semantic<<<BB, 256>>>(enc_len);
    latent_head<<<BB, 256>>>(W_mu, b_mu, W_ls, b_ls, noise, dec_len, outbuf);

    // 8) gx_dec = emb[dec_ids] @ dec_Wih^T + bih   [4096 x 768, K=512]
    gemm_nt128<512><<<dim3((3 * LL) / 128, (BB * TDD) / 128), 256>>>(
        p_gx_dec, nullptr, dec_ids, emb, dec_Wih, dec_bih, 3 * LL, nullptr, 1);

    // 9) decoder GRU (persistent, 256 steps, 512 threads), h0 = z
    gru_persist<LL, 2><<<LL / 2, 512>>>(
        p_gx_dec, dec_Whh, dec_bhh, dec_len, p_z, p_hA, p_hB, p_dec_out, TDD);

    // 10) logits = dec_out @ W_fc^T + b_fc  [4096 x 32000, K=256], zero-row skip
    gemm_nt128<256><<<dim3(VV / 128, (BB * TDD) / 128), 256>>>(
        outbuf, p_dec_out, nullptr, nullptr, W_fc, b_fc, VV, dec_len, TDD);
}

// round 8
// speedup vs baseline: 1.2578x; 1.0711x over previous
#include <cuda_runtime.h>
#include <math.h>
#include <stdint.h>

// Problem dims
#define VV 32000
#define HH 512
#define LL 256
#define BB 16
#define TEE 512
#define TDD 256

// Output layout: [logits (B*TD*V)][dec_max_len (1)][mu (B*L)][sigma (B*L)]
#define OFF_ML  ((size_t)BB * TDD * VV)
#define OFF_MU  (OFF_ML + 1)
#define OFF_SG  (OFF_MU + (size_t)BB * LL)

// ---------------------------------------------------------------------------
// Scratch (static device globals; no allocation allowed)
// ---------------------------------------------------------------------------
__device__ float g_gx_enc[(size_t)BB * TEE * 3 * HH];   // 50.3 MB
__device__ float g_enc_out[(size_t)BB * TEE * HH];      // 16.8 MB
__device__ float g_gx_dec[(size_t)BB * TDD * 3 * LL];   // 12.6 MB
__device__ float g_dec_out[(size_t)BB * TDD * LL];      //  4.2 MB
__device__ float g_hA[BB * HH];
__device__ float g_hB[BB * HH];
__device__ float g_sfw[BB * TEE];
__device__ float g_sbw[BB * TEE];
__device__ float g_henc[BB * 2 * HH];
__device__ float g_z[BB * LL];
__device__ unsigned g_bar_count;
__device__ volatile unsigned g_bar_gen;

// ---------------------------------------------------------------------------
// Grid-wide barrier (R1/R4-proven flat version; all CTAs co-resident)
// ---------------------------------------------------------------------------
__device__ __forceinline__ void grid_barrier(unsigned nb) {
    __threadfence();          // every thread makes its stores visible (release)
    __syncthreads();
    if (threadIdx.x == 0) {
        unsigned gen = g_bar_gen;
        unsigned arrived = atomicAdd(&g_bar_count, 1u);
        if (arrived == nb - 1) {
            g_bar_count = 0;
            __threadfence();
            g_bar_gen = gen + 1;
        } else {
            while (g_bar_gen == gen) { }
        }
        __threadfence();      // acquire
    }
    __syncthreads();
}

__device__ __forceinline__ float sigmoidf_(float x) { return 1.0f / (1.0f + expf(-x)); }
__device__ __forceinline__ float dot4_(float4 w, float4 h) {
    return w.x * h.x + w.y * h.y + w.z * h.z + w.w * h.w;
}

// ---------------------------------------------------------------------------
// Persistent GRU, 512 threads, 3-gate-fused dot with NS-way K-split.
// Grid = K/CW blocks (128). Block owns CW hidden columns.
// Dot thread (tid < 16*CW*NS): db=tid&15, q=(tid>>4)%NS, cl=tid/(16*NS).
// Computes partials of ALL THREE gates for column cl over k-slice q
// (h float4 loaded once, used 3x -> smem h traffic cut 3x vs unfused).
// smem h pitch = K+4: lane 16B-group = db*129 + q*KQ/4 = db (mod 8) ->
// conflict-free LDS.128. pex[g][cl][q][b] partials summed by update threads.
// ---------------------------------------------------------------------------
template<int K, int CW, int NS>
__global__ __launch_bounds__(512, 1) void gru_persist(
    const float* __restrict__ gx,    // [B, T, 3K]  (= x@Wih^T + bih, precomputed)
    const float* __restrict__ Whh,   // [3K, K]
    const float* __restrict__ bhh,   // [3K]
    const int*   __restrict__ lens,  // [B]
    const float* __restrict__ h0,    // [B, K] or nullptr (=> zeros)
    float* hA, float* hB,
    float* __restrict__ out,         // [B, T, K]
    int T)
{
    constexpr int PW = K + 4;            // smem pitch (floats), 16B-aligned rows
    constexpr int NC = 16 * CW * NS;     // dot threads (512 enc / 256 dec)
    constexpr int NU = 16 * CW;          // update threads (64 / 32)
    constexpr int KQ = K / NS;           // k-slice per dot thread (64 / 32)
    __shared__ float hs[16 * PW];
    __shared__ float pex[3 * CW * NS * 16];  // [g][cl][q][b]
    __shared__ int   lens_s[16];

    const int tid = threadIdx.x;
    const int bx  = blockIdx.x;
    const unsigned NB = gridDim.x;

    // dot-thread identity + persistent weight slice pointers (3 gates)
    const float4 *w0p = nullptr, *w1p = nullptr, *w2p = nullptr;
    int db = tid & 15;
    int q  = (tid >> 4) % NS;
    int cl = tid / (16 * NS);
    if (tid < NC) {
        int dc = bx * CW + cl;
        w0p = (const float4*)(Whh + (size_t)(0 * K + dc) * K + q * KQ);
        w1p = (const float4*)(Whh + (size_t)(1 * K + dc) * K + q * KQ);
        w2p = (const float4*)(Whh + (size_t)(2 * K + dc) * K + q * KQ);
    }
    // update-thread identity + bias registers (loaded once)
    int ub = tid & 15, ucl = tid >> 4;
    int uc = bx * CW + ucl;
    float bhr = 0.f, bhz = 0.f, bhn = 0.f;
    if (tid < NU) {
        bhr = bhh[uc]; bhz = bhh[K + uc]; bhn = bhh[2 * K + uc];
    }

    if (tid < 16) lens_s[tid] = lens[tid];
    if (tid < NU) {                      // init h buffer A (this block's columns)
        float v = h0 ? h0[ub * K + uc] : 0.0f;
        __stcg(&hA[ub * K + uc], v);
    }
    grid_barrier(NB);

    for (int t = 0; t < T; t++) {
        float* hcur  = (t & 1) ? hB : hA;
        float* hnext = (t & 1) ? hA : hB;

        // prefetch gx[t] for update threads (independent of h -> hides latency)
        float gxr = 0.f, gxz = 0.f, gxn = 0.f;
        if (tid < NU) {
            const float* gxp = gx + (size_t)(ub * T + t) * (3 * K);
            gxr = __ldg(gxp + uc);
            gxz = __ldg(gxp + K + uc);
            gxn = __ldg(gxp + 2 * K + uc);
        }

        // stage full h[B,K] into smem (float4, pitch K+4), 512 threads
        const float4* hc4 = (const float4*)hcur;
        #pragma unroll
        for (int i = tid; i < 16 * K / 4; i += 512) {
            float4 v = __ldcg(hc4 + i);
            int b = i / (K / 4), kq = i % (K / 4);
            *(float4*)&hs[b * PW + 4 * kq] = v;
        }
        __syncthreads();

        if (tid < NC) {   // 3-gate partials over k-slice q for (b=db, col=cl)
            const float4* hp = (const float4*)&hs[db * PW + q * KQ];
            float a00 = 0.f, a01 = 0.f;   // gate r
            float a10 = 0.f, a11 = 0.f;   // gate z
            float a20 = 0.f, a21 = 0.f;   // gate n
            #pragma unroll
            for (int kk = 0; kk < KQ / 8; kk++) {
                float4 hv0 = hp[2 * kk + 0];
                float4 hv1 = hp[2 * kk + 1];
                float4 wa0 = __ldg(w0p + 2 * kk + 0);
                float4 wa1 = __ldg(w0p + 2 * kk + 1);
                float4 wb0 = __ldg(w1p + 2 * kk + 0);
                float4 wb1 = __ldg(w1p + 2 * kk + 1);
                float4 wc0 = __ldg(w2p + 2 * kk + 0);
                float4 wc1 = __ldg(w2p + 2 * kk + 1);
                a00 += dot4_(wa0, hv0); a01 += dot4_(wa1, hv1);
                a10 += dot4_(wb0, hv0); a11 += dot4_(wb1, hv1);
                a20 += dot4_(wc0, hv0); a21 += dot4_(wc1, hv1);
            }
            pex[((0 * CW + cl) * NS + q) * 16 + db] = a00 + a01;
            pex[((1 * CW + cl) * NS + q) * 16 + db] = a10 + a11;
            pex[((2 * CW + cl) * NS + q) * 16 + db] = a20 + a21;
        }
        __syncthreads();

        if (tid < NU) {                  // sum partials + gates, update h
            float ghr = 0.f, ghz = 0.f, ghn = 0.f;
            #pragma unroll
            for (int qq = 0; qq < NS; qq++) {
                ghr += pex[((0 * CW + ucl) * NS + qq) * 16 + ub];
                ghz += pex[((1 * CW + ucl) * NS + qq) * 16 + ub];
                ghn += pex[((2 * CW + ucl) * NS + qq) * 16 + ub];
            }
            float r = sigmoidf_(gxr + ghr + bhr);
            float z = sigmoidf_(gxz + ghz + bhz);
            float n = tanhf   (gxn + r * (ghn + bhn));
            float hold = hs[ub * PW + uc];
            float hnew = (1.0f - z) * n + z * hold;
            bool valid = (t < lens_s[ub]);
            __stcg(&hnext[ub * K + uc], valid ? hnew : hold);
            out[(size_t)(ub * T + t) * K + uc] = valid ? hnew : 0.0f;
        }
        grid_barrier(NB);
    }
}

// ---------------------------------------------------------------------------
// 128x128x8 fp32 SGEMM-NT, double-buffered smem, 1 sync per k-tile.
// C[i,j] = sum_k A[i,k]*W[j,k] + bias[j]
// Optional row gather (A row i = Atab + ids[i]*KD) and zero-row tile skip.
// ---------------------------------------------------------------------------
template<int KD>
__global__ __launch_bounds__(256, 2) void gemm_nt128(
    float* __restrict__ C,
    const float* __restrict__ Adirect,
    const int*   __restrict__ ids,
    const float* __restrict__ Atab,
    const float* __restrict__ W,
    const float* __restrict__ bias,
    int N,
    const int* __restrict__ skiplen,   // optional: row i -> b=i/tper, t=i%tper
    int tper)
{
    __shared__ float As[2][8][128];
    __shared__ float Bs[2][8][128];
    const int tid  = threadIdx.x;
    const int row0 = blockIdx.y * 128, col0 = blockIdx.x * 128;
    const int ty = tid >> 4, tx = tid & 15;

    if (skiplen) {   // whole M-tile is zero rows -> output = bias only
        int bb = row0 / tper, t0 = row0 % tper;
        if (t0 >= __ldg(&skiplen[bb])) {
            float4 blo = *(const float4*)(bias + col0 + tx * 8);
            float4 bhi = *(const float4*)(bias + col0 + tx * 8 + 4);
            #pragma unroll
            for (int i = 0; i < 8; i++) {
                float* cp = C + (size_t)(row0 + ty * 8 + i) * N + col0 + tx * 8;
                *(float4*)cp = blo; *(float4*)(cp + 4) = bhi;
            }
            return;
        }
    }

    const int lr  = tid >> 1;
    const int lk4 = (tid & 1) * 4;
    const float* arow = ids ? (Atab + (size_t)__ldg(&ids[row0 + lr]) * KD)
                            : (Adirect + (size_t)(row0 + lr) * KD);
    const float* wrow = W + (size_t)(col0 + lr) * KD;

    // prologue: fill buffer 0
    {
        float4 av = *(const float4*)(arow + lk4);
        float4 wv = *(const float4*)(wrow + lk4);
        As[0][lk4 + 0][lr] = av.x; As[0][lk4 + 1][lr] = av.y;
        As[0][lk4 + 2][lr] = av.z; As[0][lk4 + 3][lr] = av.w;
        Bs[0][lk4 + 0][lr] = wv.x; Bs[0][lk4 + 1][lr] = wv.y;
        Bs[0][lk4 + 2][lr] = wv.z; Bs[0][lk4 + 3][lr] = wv.w;
    }
    __syncthreads();

    float acc[8][8];
    #pragma unroll
    for (int i = 0; i < 8; i++)
        #pragma unroll
        for (int j = 0; j < 8; j++) acc[i][j] = 0.0f;

    constexpr int NK = KD / 8;
    #pragma unroll 1
    for (int kt = 0; kt < NK; kt++) {
        const int cur = kt & 1;
        float4 av2, wv2;
        if (kt + 1 < NK) {
            av2 = *(const float4*)(arow + (kt + 1) * 8 + lk4);
            wv2 = *(const float4*)(wrow + (kt + 1) * 8 + lk4);
        }
        #pragma unroll
        for (int k = 0; k < 8; k++) {
            float a[8], b[8];
            *(float4*)&a[0] = *(const float4*)&As[cur][k][ty * 8];
            *(float4*)&a[4] = *(const float4*)&As[cur][k][ty * 8 + 4];
            *(float4*)&b[0] = *(const float4*)&Bs[cur][k][tx * 8];
            *(float4*)&b[4] = *(const float4*)&Bs[cur][k][tx * 8 + 4];
            #pragma unroll
            for (int i = 0; i < 8; i++)
                #pragma unroll
                for (int j = 0; j < 8; j++)
                    acc[i][j] += a[i] * b[j];
        }
        if (kt + 1 < NK) {
            const int nxt = cur ^ 1;
            As[nxt][lk4 + 0][lr] = av2.x; As[nxt][lk4 + 1][lr] = av2.y;
            As[nxt][lk4 + 2][lr] = av2.z; As[nxt][lk4 + 3][lr] = av2.w;
            Bs[nxt][lk4 + 0][lr] = wv2.x; Bs[nxt][lk4 + 1][lr] = wv2.y;
            Bs[nxt][lk4 + 2][lr] = wv2.z; Bs[nxt][lk4 + 3][lr] = wv2.w;
        }
        __syncthreads();
    }

    float4 blo = *(const float4*)(bias + col0 + tx * 8);
    float4 bhi = *(const float4*)(bias + col0 + tx * 8 + 4);
    #pragma unroll
    for (int i = 0; i < 8; i++) {
        float* cp = C + (size_t)(row0 + ty * 8 + i) * N + col0 + tx * 8;
        float4 v0 = make_float4(acc[i][0] + blo.x, acc[i][1] + blo.y,
                                acc[i][2] + blo.z, acc[i][3] + blo.w);
        float4 v1 = make_float4(acc[i][4] + bhi.x, acc[i][5] + bhi.y,
                                acc[i][6] + bhi.z, acc[i][7] + bhi.w);
        *(float4*)cp = v0; *(float4*)(cp + 4) = v1;
    }
}

// ---------------------------------------------------------------------------
// Padding no-ops: profiled slot = my 4th launch => 2 noops put gru_enc there
// ---------------------------------------------------------------------------
__global__ void noop_a() {}
__global__ void noop_b() {}

// ---------------------------------------------------------------------------
// Attention scores (R1-proven): sfw[b,t] = out[b,t,:].last[b,:]; sbw with first
// ---------------------------------------------------------------------------
__global__ __launch_bounds__(256) void attn_scores() {
    const int b = blockIdx.x, tid = threadIdx.x;
    __shared__ float last_s[HH], first_s[HH];
    for (int i = tid; i < HH; i += 256) {
        last_s[i]  = g_hA[b * HH + i];
        first_s[i] = g_enc_out[((size_t)b * TEE + 0) * HH + i];
    }
    __syncthreads();
    const int w = tid >> 5, lane = tid & 31;
    for (int t = w; t < TEE; t += 8) {
        const float* orow = g_enc_out + ((size_t)(b * TEE + t)) * HH;
        float af = 0.0f, ab = 0.0f;
        #pragma unroll 4
        for (int i = lane; i < HH; i += 32) {
            float v = orow[i];
            af += v * last_s[i];
            ab += v * first_s[i];
        }
        #pragma unroll
        for (int o = 16; o > 0; o >>= 1) {
            af += __shfl_xor_sync(0xffffffffu, af, o);
            ab += __shfl_xor_sync(0xffffffffu, ab, o);
        }
        if (lane == 0) { g_sfw[b * TEE + t] = af; g_sbw[b * TEE + t] = ab; }
    }
}

__device__ __forceinline__ float blk_reduce(float v, float* red, bool ismax) {
    #pragma unroll
    for (int o = 16; o > 0; o >>= 1) {
        float u = __shfl_xor_sync(0xffffffffu, v, o);
        v = ismax ? fmaxf(v, u) : (v + u);
    }
    int w = threadIdx.x >> 5;
    if ((threadIdx.x & 31) == 0) red[w] = v;
    __syncthreads();
    if (threadIdx.x == 0) {
        float a = red[0];
        for (int i = 1; i < 8; i++) a = ismax ? fmaxf(a, red[i]) : (a + red[i]);
        red[0] = a;
    }
    __syncthreads();
    float r = red[0];
    __syncthreads();
    return r;
}

// ---------------------------------------------------------------------------
// Masked dual softmax + semantic pooling + h_enc assembly (R1-proven).
// ---------------------------------------------------------------------------
__global__ __launch_bounds__(256) void softmax_semantic(const int* __restrict__ enc_len) {
    const int b = blockIdx.x, tid = threadIdx.x;
    const int len = enc_len[b];
    __shared__ float sa[TEE];
    __shared__ float red[8];

    // forward pass
    float v0 = (tid       < len) ? g_sfw[b * TEE + tid]       : -1e30f;
    float v1 = (tid + 256 < len) ? g_sfw[b * TEE + tid + 256] : -1e30f;
    float M = blk_reduce(fmaxf(v0, v1), red, true);
    float e0 = (tid       < len) ? expf(v0 - M) : 0.0f;
    float e1 = (tid + 256 < len) ? expf(v1 - M) : 0.0f;
    float S = blk_reduce(e0 + e1, red, false);
    float inv = 0.5f / S;
    sa[tid] = e0 * inv; sa[tid + 256] = e1 * inv;
    __syncthreads();

    // backward pass
    v0 = (tid       < len) ? g_sbw[b * TEE + tid]       : -1e30f;
    v1 = (tid + 256 < len) ? g_sbw[b * TEE + tid + 256] : -1e30f;
    M = blk_reduce(fmaxf(v0, v1), red, true);
    e0 = (tid       < len) ? expf(v0 - M) : 0.0f;
    e1 = (tid + 256 < len) ? expf(v1 - M) : 0.0f;
    S = blk_reduce(e0 + e1, red, false);
    inv = 0.5f / S;
    sa[tid] += e0 * inv; sa[tid + 256] += e1 * inv;
    __syncthreads();

    // semantic[b,d] = sum_t alpha[t] * out[b,t,d];  h_enc = [last, semantic]
    for (int d = tid; d < HH; d += 256) {
        float acc = 0.0f;
        #pragma unroll 4
        for (int t = 0; t < TEE; t++)
            acc += sa[t] * g_enc_out[((size_t)(b * TEE + t)) * HH + d];
        g_henc[b * 2 * HH + HH + d] = acc;
        g_henc[b * 2 * HH + d] = g_hA[b * HH + d];
    }
}

// ---------------------------------------------------------------------------
// Latent head (R1-proven): mu/sigma/z + tail outputs. 1 block per b.
// ---------------------------------------------------------------------------
__global__ __launch_bounds__(256) void latent_head(
    const float* __restrict__ W_mu, const float* __restrict__ b_mu,
    const float* __restrict__ W_ls, const float* __restrict__ b_ls,
    const float* __restrict__ noise, const int* __restrict__ dec_len,
    float* __restrict__ outbuf)
{
    const int b = blockIdx.x, tid = threadIdx.x;
    __shared__ float he[2 * HH];
    __shared__ float muv[LL], lsv[LL];
    for (int i = tid; i < 2 * HH; i += 256) he[i] = g_henc[b * 2 * HH + i];
    __syncthreads();

    const int w = tid >> 5, lane = tid & 31;
    for (int o = w; o < 2 * LL; o += 8) {
        const float* Wr; float bia; int j;
        if (o < LL) { j = o;      Wr = W_mu + (size_t)j * (2 * HH); bia = b_mu[j]; }
        else        { j = o - LL; Wr = W_ls + (size_t)j * (2 * HH); bia = b_ls[j]; }
        float acc = 0.0f;
        #pragma unroll 4
        for (int k = lane; k < 2 * HH; k += 32) acc += Wr[k] * he[k];
        #pragma unroll
        for (int s = 16; s > 0; s >>= 1) acc += __shfl_xor_sync(0xffffffffu, acc, s);
        if (lane == 0) { if (o < LL) muv[j] = acc + bia; else lsv[j] = acc + bia; }
    }
    __syncthreads();

    if (tid < LL) {
        float mu = muv[tid];
        float sg = expf(lsv[tid]);
        float zz = mu + sg * noise[b * LL + tid];
        g_z[b * LL + tid] = zz;
        outbuf[OFF_MU + b * LL + tid] = mu;
        outbuf[OFF_SG + b * LL + tid] = sg;
    }
    if (b == 0 && tid == 0) {
        int m = 0;
        for (int i = 0; i < BB; i++) m = max(m, dec_len[i]);
        outbuf[OFF_ML] = (float)m;
    }
}

// ---------------------------------------------------------------------------
// Launch
// ---------------------------------------------------------------------------
extern "C" void kernel_launch(void* const* d_in, const int* in_sizes, int n_in,
                              void* d_out, int out_size) {
    const float* emb     = (const float*)d_in[0];
    const float* enc_Wih = (const float*)d_in[1];
    const float* enc_Whh = (const float*)d_in[2];
    const float* enc_bih = (const float*)d_in[3];
    const float* enc_bhh = (const float*)d_in[4];
    const float* dec_Wih = (const float*)d_in[5];
    const float* dec_Whh = (const float*)d_in[6];
    const float* dec_bih = (const float*)d_in[7];
    const float* dec_bhh = (const float*)d_in[8];
    const float* W_mu    = (const float*)d_in[9];
    const float* b_mu    = (const float*)d_in[10];
    const float* W_ls    = (const float*)d_in[11];
    const float* b_ls    = (const float*)d_in[12];
    const float* W_fc    = (const float*)d_in[13];
    const float* b_fc    = (const float*)d_in[14];
    const float* noise   = (const float*)d_in[15];
    const int*   enc_ids = (const int*)d_in[16];
    const int*   enc_len = (const int*)d_in[17];
    const int*   dec_ids = (const int*)d_in[18];
    const int*   dec_len = (const int*)d_in[19];
    float* outbuf = (float*)d_out;

    float *p_gx_enc, *p_enc_out, *p_gx_dec, *p_dec_out, *p_hA, *p_hB, *p_z;
    cudaGetSymbolAddress((void**)&p_gx_enc, g_gx_enc);
    cudaGetSymbolAddress((void**)&p_enc_out, g_enc_out);
    cudaGetSymbolAddress((void**)&p_gx_dec, g_gx_dec);
    cudaGetSymbolAddress((void**)&p_dec_out, g_dec_out);
    cudaGetSymbolAddress((void**)&p_hA, g_hA);
    cudaGetSymbolAddress((void**)&p_hB, g_hB);
    cudaGetSymbolAddress((void**)&p_z, g_z);

    // 1) gx_enc = emb[enc_ids] @ enc_Wih^T + bih   [8192 x 1536, K=512]
    gemm_nt128<512><<<dim3(1536 / 128, (BB * TEE) / 128), 256>>>(
        p_gx_enc, nullptr, enc_ids, emb, enc_Wih, enc_bih, 3 * HH, nullptr, 1);

    // 2-3) padding no-ops (keep gru_enc at my launch #4 = profiled slot)
    noop_a<<<1, 32>>>();
    noop_b<<<1, 32>>>();

    // 4) encoder GRU (persistent, 512 steps, 512 threads)  <-- profiled launch
    gru_persist<HH, 4, 8><<<HH / 4, 512>>>(
        p_gx_enc, enc_Whh, enc_bhh, enc_len, nullptr, p_hA, p_hB, p_enc_out, TEE);

    // 5-7) attention + latent path (R1 versions)
    attn_scores<<<BB, 256>>>();
    softmax_semantic<<<BB, 256>>>(enc_len);
    latent_head<<<BB, 256>>>(W_mu, b_mu, W_ls, b_ls, noise, dec_len, outbuf);

    // 8) gx_dec = emb[dec_ids] @ dec_Wih^T + bih   [4096 x 768, K=512]
    gemm_nt128<512><<<dim3((3 * LL) / 128, (BB * TDD) / 128), 256>>>(
        p_gx_dec, nullptr, dec_ids, emb, dec_Wih, dec_bih, 3 * LL, nullptr, 1);

    // 9) decoder GRU (persistent, 256 steps, 512 threads), h0 = z
    gru_persist<LL, 2, 8><<<LL / 2, 512>>>(
        p_gx_dec, dec_Whh, dec_bhh, dec_len, p_z, p_hA, p_hB, p_dec_out, TDD);

    // 10) logits = dec_out @ W_fc^T + b_fc  [4096 x 32000, K=256], zero-row skip
    gemm_nt128<256><<<dim3(VV / 128, (BB * TDD) / 128), 256>>>(
        outbuf, p_dec_out, nullptr, nullptr, W_fc, b_fc, VV, dec_len, TDD);
}

// round 10
// speedup vs baseline: 1.2670x; 1.0073x over previous
#include <cuda_runtime.h>
#include <cuda_bf16.h>
#include <mma.h>
#include <math.h>
#include <stdint.h>

using namespace nvcuda;

// Problem dims
#define VV 32000
#define HH 512
#define LL 256
#define BB 16
#define TEE 512
#define TDD 256

// Output layout: [logits (B*TD*V)][dec_max_len (1)][mu (B*L)][sigma (B*L)]
#define OFF_ML  ((size_t)BB * TDD * VV)
#define OFF_MU  (OFF_ML + 1)
#define OFF_SG  (OFF_MU + (size_t)BB * LL)

// ---------------------------------------------------------------------------
// Scratch (static device globals; no allocation allowed)
// ---------------------------------------------------------------------------
__device__ float g_gx_enc[(size_t)BB * TEE * 3 * HH];   // 50.3 MB
__device__ float g_enc_out[(size_t)BB * TEE * HH];      // 16.8 MB
__device__ float g_gx_dec[(size_t)BB * TDD * 3 * LL];   // 12.6 MB
__device__ float g_dec_out[(size_t)BB * TDD * LL];      //  4.2 MB
__device__ float g_hA[BB * HH];
__device__ float g_hB[BB * HH];
__device__ float g_sfw[BB * TEE];
__device__ float g_sbw[BB * TEE];
__device__ float g_henc[BB * 2 * HH];
__device__ float g_z[BB * LL];
__device__ unsigned g_bar_count;
__device__ volatile unsigned g_bar_gen;

// Split-bf16 operands for the logits GEMM (K-concat: [hi|lo|hi] x [hi|hi|lo])
__device__ __nv_bfloat16 g_wfc_bf[(size_t)VV * 768];        // 49.2 MB
__device__ __nv_bfloat16 g_abf[(size_t)BB * TDD * 768];     //  6.3 MB

// ---------------------------------------------------------------------------
// Grid-wide barrier (R1/R4-proven flat version; all CTAs co-resident)
// ---------------------------------------------------------------------------
__device__ __forceinline__ void grid_barrier(unsigned nb) {
    __threadfence();
    __syncthreads();
    if (threadIdx.x == 0) {
        unsigned gen = g_bar_gen;
        unsigned arrived = atomicAdd(&g_bar_count, 1u);
        if (arrived == nb - 1) {
            g_bar_count = 0;
            __threadfence();
            g_bar_gen = gen + 1;
        } else {
            while (g_bar_gen == gen) { }
        }
        __threadfence();
    }
    __syncthreads();
}

__device__ __forceinline__ float sigmoidf_(float x) { return 1.0f / (1.0f + expf(-x)); }
__device__ __forceinline__ float dot4_(float4 w, float4 h) {
    return w.x * h.x + w.y * h.y + w.z * h.z + w.w * h.w;
}

// ---------------------------------------------------------------------------
// Persistent GRU (R8-proven), 512 threads, 3-gate-fused dot, NS-way K-split.
// ---------------------------------------------------------------------------
template<int K, int CW, int NS>
__global__ __launch_bounds__(512, 1) void gru_persist(
    const float* __restrict__ gx,
    const float* __restrict__ Whh,
    const float* __restrict__ bhh,
    const int*   __restrict__ lens,
    const float* __restrict__ h0,
    float* hA, float* hB,
    float* __restrict__ out,
    int T)
{
    constexpr int PW = K + 4;
    constexpr int NC = 16 * CW * NS;
    constexpr int NU = 16 * CW;
    constexpr int KQ = K / NS;
    __shared__ float hs[16 * PW];
    __shared__ float pex[3 * CW * NS * 16];
    __shared__ int   lens_s[16];

    const int tid = threadIdx.x;
    const int bx  = blockIdx.x;
    const unsigned NB = gridDim.x;

    const float4 *w0p = nullptr, *w1p = nullptr, *w2p = nullptr;
    int db = tid & 15;
    int q  = (tid >> 4) % NS;
    int cl = tid / (16 * NS);
    if (tid < NC) {
        int dc = bx * CW + cl;
        w0p = (const float4*)(Whh + (size_t)(0 * K + dc) * K + q * KQ);
        w1p = (const float4*)(Whh + (size_t)(1 * K + dc) * K + q * KQ);
        w2p = (const float4*)(Whh + (size_t)(2 * K + dc) * K + q * KQ);
    }
    int ub = tid & 15, ucl = tid >> 4;
    int uc = bx * CW + ucl;
    float bhr = 0.f, bhz = 0.f, bhn = 0.f;
    if (tid < NU) {
        bhr = bhh[uc]; bhz = bhh[K + uc]; bhn = bhh[2 * K + uc];
    }

    if (tid < 16) lens_s[tid] = lens[tid];
    if (tid < NU) {
        float v = h0 ? h0[ub * K + uc] : 0.0f;
        __stcg(&hA[ub * K + uc], v);
    }
    grid_barrier(NB);

    for (int t = 0; t < T; t++) {
        float* hcur  = (t & 1) ? hB : hA;
        float* hnext = (t & 1) ? hA : hB;

        float gxr = 0.f, gxz = 0.f, gxn = 0.f;
        if (tid < NU) {
            const float* gxp = gx + (size_t)(ub * T + t) * (3 * K);
            gxr = __ldg(gxp + uc);
            gxz = __ldg(gxp + K + uc);
            gxn = __ldg(gxp + 2 * K + uc);
        }

        const float4* hc4 = (const float4*)hcur;
        #pragma unroll
        for (int i = tid; i < 16 * K / 4; i += 512) {
            float4 v = __ldcg(hc4 + i);
            int b = i / (K / 4), kq = i % (K / 4);
            *(float4*)&hs[b * PW + 4 * kq] = v;
        }
        __syncthreads();

        if (tid < NC) {
            const float4* hp = (const float4*)&hs[db * PW + q * KQ];
            float a00 = 0.f, a01 = 0.f, a10 = 0.f, a11 = 0.f, a20 = 0.f, a21 = 0.f;
            #pragma unroll
            for (int kk = 0; kk < KQ / 8; kk++) {
                float4 hv0 = hp[2 * kk + 0];
                float4 hv1 = hp[2 * kk + 1];
                float4 wa0 = __ldg(w0p + 2 * kk + 0);
                float4 wa1 = __ldg(w0p + 2 * kk + 1);
                float4 wb0 = __ldg(w1p + 2 * kk + 0);
                float4 wb1 = __ldg(w1p + 2 * kk + 1);
                float4 wc0 = __ldg(w2p + 2 * kk + 0);
                float4 wc1 = __ldg(w2p + 2 * kk + 1);
                a00 += dot4_(wa0, hv0); a01 += dot4_(wa1, hv1);
                a10 += dot4_(wb0, hv0); a11 += dot4_(wb1, hv1);
                a20 += dot4_(wc0, hv0); a21 += dot4_(wc1, hv1);
            }
            pex[((0 * CW + cl) * NS + q) * 16 + db] = a00 + a01;
            pex[((1 * CW + cl) * NS + q) * 16 + db] = a10 + a11;
            pex[((2 * CW + cl) * NS + q) * 16 + db] = a20 + a21;
        }
        __syncthreads();

        if (tid < NU) {
            float ghr = 0.f, ghz = 0.f, ghn = 0.f;
            #pragma unroll
            for (int qq = 0; qq < NS; qq++) {
                ghr += pex[((0 * CW + ucl) * NS + qq) * 16 + ub];
                ghz += pex[((1 * CW + ucl) * NS + qq) * 16 + ub];
                ghn += pex[((2 * CW + ucl) * NS + qq) * 16 + ub];
            }
            float r = sigmoidf_(gxr + ghr + bhr);
            float z = sigmoidf_(gxz + ghz + bhz);
            float n = tanhf   (gxn + r * (ghn + bhn));
            float hold = hs[ub * PW + uc];
            float hnew = (1.0f - z) * n + z * hold;
            bool valid = (t < lens_s[ub]);
            __stcg(&hnext[ub * K + uc], valid ? hnew : hold);
            out[(size_t)(ub * T + t) * K + uc] = valid ? hnew : 0.0f;
        }
        grid_barrier(NB);
    }
}

// ---------------------------------------------------------------------------
// 128x128x8 fp32 SGEMM-NT (R8-proven), used for gx_enc / gx_dec.
// ---------------------------------------------------------------------------
template<int KD>
__global__ __launch_bounds__(256, 2) void gemm_nt128(
    float* __restrict__ C,
    const float* __restrict__ Adirect,
    const int*   __restrict__ ids,
    const float* __restrict__ Atab,
    const float* __restrict__ W,
    const float* __restrict__ bias,
    int N,
    const int* __restrict__ skiplen,
    int tper)
{
    __shared__ float As[2][8][128];
    __shared__ float Bs[2][8][128];
    const int tid  = threadIdx.x;
    const int row0 = blockIdx.y * 128, col0 = blockIdx.x * 128;
    const int ty = tid >> 4, tx = tid & 15;

    if (skiplen) {
        int bb = row0 / tper, t0 = row0 % tper;
        if (t0 >= __ldg(&skiplen[bb])) {
            float4 blo = *(const float4*)(bias + col0 + tx * 8);
            float4 bhi = *(const float4*)(bias + col0 + tx * 8 + 4);
            #pragma unroll
            for (int i = 0; i < 8; i++) {
                float* cp = C + (size_t)(row0 + ty * 8 + i) * N + col0 + tx * 8;
                *(float4*)cp = blo; *(float4*)(cp + 4) = bhi;
            }
            return;
        }
    }

    const int lr  = tid >> 1;
    const int lk4 = (tid & 1) * 4;
    const float* arow = ids ? (Atab + (size_t)__ldg(&ids[row0 + lr]) * KD)
                            : (Adirect + (size_t)(row0 + lr) * KD);
    const float* wrow = W + (size_t)(col0 + lr) * KD;

    {
        float4 av = *(const float4*)(arow + lk4);
        float4 wv = *(const float4*)(wrow + lk4);
        As[0][lk4 + 0][lr] = av.x; As[0][lk4 + 1][lr] = av.y;
        As[0][lk4 + 2][lr] = av.z; As[0][lk4 + 3][lr] = av.w;
        Bs[0][lk4 + 0][lr] = wv.x; Bs[0][lk4 + 1][lr] = wv.y;
        Bs[0][lk4 + 2][lr] = wv.z; Bs[0][lk4 + 3][lr] = wv.w;
    }
    __syncthreads();

    float acc[8][8];
    #pragma unroll
    for (int i = 0; i < 8; i++)
        #pragma unroll
        for (int j = 0; j < 8; j++) acc[i][j] = 0.0f;

    constexpr int NK = KD / 8;
    #pragma unroll 1
    for (int kt = 0; kt < NK; kt++) {
        const int cur = kt & 1;
        float4 av2, wv2;
        if (kt + 1 < NK) {
            av2 = *(const float4*)(arow + (kt + 1) * 8 + lk4);
            wv2 = *(const float4*)(wrow + (kt + 1) * 8 + lk4);
        }
        #pragma unroll
        for (int k = 0; k < 8; k++) {
            float a[8], b[8];
            *(float4*)&a[0] = *(const float4*)&As[cur][k][ty * 8];
            *(float4*)&a[4] = *(const float4*)&As[cur][k][ty * 8 + 4];
            *(float4*)&b[0] = *(const float4*)&Bs[cur][k][tx * 8];
            *(float4*)&b[4] = *(const float4*)&Bs[cur][k][tx * 8 + 4];
            #pragma unroll
            for (int i = 0; i < 8; i++)
                #pragma unroll
                for (int j = 0; j < 8; j++)
                    acc[i][j] += a[i] * b[j];
        }
        if (kt + 1 < NK) {
            const int nxt = cur ^ 1;
            As[nxt][lk4 + 0][lr] = av2.x; As[nxt][lk4 + 1][lr] = av2.y;
            As[nxt][lk4 + 2][lr] = av2.z; As[nxt][lk4 + 3][lr] = av2.w;
            Bs[nxt][lk4 + 0][lr] = wv2.x; Bs[nxt][lk4 + 1][lr] = wv2.y;
            Bs[nxt][lk4 + 2][lr] = wv2.z; Bs[nxt][lk4 + 3][lr] = wv2.w;
        }
        __syncthreads();
    }

    float4 blo = *(const float4*)(bias + col0 + tx * 8);
    float4 bhi = *(const float4*)(bias + col0 + tx * 8 + 4);
    #pragma unroll
    for (int i = 0; i < 8; i++) {
        float* cp = C + (size_t)(row0 + ty * 8 + i) * N + col0 + tx * 8;
        float4 v0 = make_float4(acc[i][0] + blo.x, acc[i][1] + blo.y,
                                acc[i][2] + blo.z, acc[i][3] + blo.w);
        float4 v1 = make_float4(acc[i][4] + bhi.x, acc[i][5] + bhi.y,
                                acc[i][6] + bhi.z, acc[i][7] + bhi.w);
        *(float4*)cp = v0; *(float4*)(cp + 4) = v1;
    }
}

// ---------------------------------------------------------------------------
// Split-bf16 prep: W'[n] = [hi | hi | lo], A'[m] = [hi | lo | hi]
// ---------------------------------------------------------------------------
__global__ __launch_bounds__(256) void prep_w(const float* __restrict__ W) {
    int n = blockIdx.x, k = threadIdx.x;
    float x = __ldg(&W[(size_t)n * LL + k]);
    __nv_bfloat16 hi = __float2bfloat16(x);
    __nv_bfloat16 lo = __float2bfloat16(x - __bfloat162float(hi));
    __nv_bfloat16* dst = g_wfc_bf + (size_t)n * 768;
    dst[k] = hi; dst[LL + k] = hi; dst[2 * LL + k] = lo;
}
__global__ __launch_bounds__(256) void prep_a() {
    int m = blockIdx.x, k = threadIdx.x;
    float x = g_dec_out[(size_t)m * LL + k];
    __nv_bfloat16 hi = __float2bfloat16(x);
    __nv_bfloat16 lo = __float2bfloat16(x - __bfloat162float(hi));
    __nv_bfloat16* dst = g_abf + (size_t)m * 768;
    dst[k] = hi; dst[LL + k] = lo; dst[2 * LL + k] = hi;
}

// ---------------------------------------------------------------------------
// wmma bf16 GEMM for logits: C[4096,32000] = A'[4096,768] @ W'[32000,768]^T
// CTA: 128x128 tile, 8 warps (4m x 2n), warp = 32x64 = 2x4 wmma 16x16x16
// fragments, fp32 accum. K=768 in 24 chunks of 32, double-buffered smem.
// ---------------------------------------------------------------------------
#define WKC   32                              // bf16 per K chunk
#define NCHNK (768 / WKC)                     // 24
#define APIT  40                              // smem pitch (bf16), mult of 8
#define CPIT  132                             // staging pitch (f32), mult of 4
#define SM_A  0
#define SM_B  (2 * 128 * APIT * 2)            // 20480 B
#define SM_C  (2 * SM_B)                      // 40960 B
#define SM_TOT (SM_C + 128 * CPIT * 4)        // 108544 B

__global__ __launch_bounds__(256) void logits_wmma(
    const float* __restrict__ bias,
    const int* __restrict__ dec_len,
    float* __restrict__ C)
{
    extern __shared__ char smc[];
    __nv_bfloat16* As = (__nv_bfloat16*)(smc + SM_A);   // [2][128][APIT]
    __nv_bfloat16* Bs = (__nv_bfloat16*)(smc + SM_B);   // [2][128][APIT]
    float*        Cst = (float*)(smc + SM_C);           // [128][CPIT]

    const int tid = threadIdx.x;
    const int col0 = blockIdx.x * 128, row0 = blockIdx.y * 128;

    // whole-tile zero-row skip -> bias only
    {
        int bb = row0 / TDD, t0 = row0 % TDD;
        if (t0 >= __ldg(&dec_len[bb])) {
            int r = tid >> 1, half = tid & 1;
            float* cp = C + (size_t)(row0 + r) * VV + col0 + half * 64;
            #pragma unroll
            for (int i = 0; i < 16; i++) {
                const float* bp = bias + col0 + half * 64 + i * 4;
                *(float4*)(cp + i * 4) = make_float4(__ldg(bp), __ldg(bp + 1),
                                                     __ldg(bp + 2), __ldg(bp + 3));
            }
            return;
        }
    }

    const int wid = tid >> 5;
    const int wm = wid >> 1;        // 0..3 -> m offset wm*32
    const int wn = wid & 1;         // 0..1 -> n offset wn*64

    // loader identity: row r (0..127), 16-bf16 segment (0/1)
    const int lr  = tid >> 1;
    const int seg = (tid & 1) * 16;
    const __nv_bfloat16* Ag = g_abf    + (size_t)(row0 + lr) * 768 + seg;
    const __nv_bfloat16* Bg = g_wfc_bf + (size_t)(col0 + lr) * 768 + seg;

    // prologue: chunk 0 -> buffer 0
    {
        uint4 a0 = *(const uint4*)(Ag + 0);
        uint4 a1 = *(const uint4*)(Ag + 8);
        uint4 b0 = *(const uint4*)(Bg + 0);
        uint4 b1 = *(const uint4*)(Bg + 8);
        __nv_bfloat16* ap = As + lr * APIT + seg;
        __nv_bfloat16* bp = Bs + lr * APIT + seg;
        *(uint4*)(ap + 0) = a0; *(uint4*)(ap + 8) = a1;
        *(uint4*)(bp + 0) = b0; *(uint4*)(bp + 8) = b1;
    }
    __syncthreads();

    wmma::fragment<wmma::accumulator, 16, 16, 16, float> cf[2][4];
    #pragma unroll
    for (int i = 0; i < 2; i++)
        #pragma unroll
        for (int j = 0; j < 4; j++)
            wmma::fill_fragment(cf[i][j], 0.0f);

    #pragma unroll 1
    for (int ch = 0; ch < NCHNK; ch++) {
        const int cur = ch & 1;
        uint4 a0, a1, b0, b1;
        if (ch + 1 < NCHNK) {
            const __nv_bfloat16* Agn = Ag + (ch + 1) * WKC;
            const __nv_bfloat16* Bgn = Bg + (ch + 1) * WKC;
            a0 = *(const uint4*)(Agn + 0);
            a1 = *(const uint4*)(Agn + 8);
            b0 = *(const uint4*)(Bgn + 0);
            b1 = *(const uint4*)(Bgn + 8);
        }

        const __nv_bfloat16* Ab = As + cur * 128 * APIT;
        const __nv_bfloat16* Bb = Bs + cur * 128 * APIT;
        #pragma unroll
        for (int kk = 0; kk < WKC; kk += 16) {
            wmma::fragment<wmma::matrix_a, 16, 16, 16, __nv_bfloat16, wmma::row_major> af[2];
            wmma::fragment<wmma::matrix_b, 16, 16, 16, __nv_bfloat16, wmma::col_major> bf[4];
            #pragma unroll
            for (int i = 0; i < 2; i++)
                wmma::load_matrix_sync(af[i], Ab + (wm * 32 + i * 16) * APIT + kk, APIT);
            #pragma unroll
            for (int j = 0; j < 4; j++)
                wmma::load_matrix_sync(bf[j], Bb + (wn * 64 + j * 16) * APIT + kk, APIT);
            #pragma unroll
            for (int i = 0; i < 2; i++)
                #pragma unroll
                for (int j = 0; j < 4; j++)
                    wmma::mma_sync(cf[i][j], af[i], bf[j], cf[i][j]);
        }

        if (ch + 1 < NCHNK) {
            const int nxt = cur ^ 1;
            __nv_bfloat16* ap = As + nxt * 128 * APIT + lr * APIT + seg;
            __nv_bfloat16* bp = Bs + nxt * 128 * APIT + lr * APIT + seg;
            *(uint4*)(ap + 0) = a0; *(uint4*)(ap + 8) = a1;
            *(uint4*)(bp + 0) = b0; *(uint4*)(bp + 8) = b1;
        }
        __syncthreads();
    }

    // stage accumulators to smem
    #pragma unroll
    for (int i = 0; i < 2; i++)
        #pragma unroll
        for (int j = 0; j < 4; j++)
            wmma::store_matrix_sync(Cst + (wm * 32 + i * 16) * CPIT + wn * 64 + j * 16,
                                    cf[i][j], CPIT, wmma::mem_row_major);
    __syncthreads();

    // bias add + coalesced store
    {
        int r = tid >> 1, half = tid & 1;
        const float* sp = Cst + r * CPIT + half * 64;
        float* cp = C + (size_t)(row0 + r) * VV + col0 + half * 64;
        #pragma unroll
        for (int i = 0; i < 16; i++) {
            const float* bp = bias + col0 + half * 64 + i * 4;
            float4 v = *(const float4*)(sp + i * 4);
            *(float4*)(cp + i * 4) = make_float4(v.x + __ldg(bp), v.y + __ldg(bp + 1),
                                                 v.z + __ldg(bp + 2), v.w + __ldg(bp + 3));
        }
    }
}

// ---------------------------------------------------------------------------
// Padding no-op (keeps gru_enc at my 4th launch = ncu profiled slot)
// ---------------------------------------------------------------------------
__global__ void noop_a() {}

// ---------------------------------------------------------------------------
// Attention scores (R1-proven)
// ---------------------------------------------------------------------------
__global__ __launch_bounds__(256) void attn_scores() {
    const int b = blockIdx.x, tid = threadIdx.x;
    __shared__ float last_s[HH], first_s[HH];
    for (int i = tid; i < HH; i += 256) {
        last_s[i]  = g_hA[b * HH + i];
        first_s[i] = g_enc_out[((size_t)b * TEE + 0) * HH + i];
    }
    __syncthreads();
    const int w = tid >> 5, lane = tid & 31;
    for (int t = w; t < TEE; t += 8) {
        const float* orow = g_enc_out + ((size_t)(b * TEE + t)) * HH;
        float af = 0.0f, ab = 0.0f;
        #pragma unroll 4
        for (int i = lane; i < HH; i += 32) {
            float v = orow[i];
            af += v * last_s[i];
            ab += v * first_s[i];
        }
        #pragma unroll
        for (int o = 16; o > 0; o >>= 1) {
            af += __shfl_xor_sync(0xffffffffu, af, o);
            ab += __shfl_xor_sync(0xffffffffu, ab, o);
        }
        if (lane == 0) { g_sfw[b * TEE + t] = af; g_sbw[b * TEE + t] = ab; }
    }
}

__device__ __forceinline__ float blk_reduce(float v, float* red, bool ismax) {
    #pragma unroll
    for (int o = 16; o > 0; o >>= 1) {
        float u = __shfl_xor_sync(0xffffffffu, v, o);
        v = ismax ? fmaxf(v, u) : (v + u);
    }
    int w = threadIdx.x >> 5;
    if ((threadIdx.x & 31) == 0) red[w] = v;
    __syncthreads();
    if (threadIdx.x == 0) {
        float a = red[0];
        for (int i = 1; i < 8; i++) a = ismax ? fmaxf(a, red[i]) : (a + red[i]);
        red[0] = a;
    }
    __syncthreads();
    float r = red[0];
    __syncthreads();
    return r;
}

// ---------------------------------------------------------------------------
// Masked dual softmax + semantic pooling + h_enc assembly (R1-proven).
// ---------------------------------------------------------------------------
__global__ __launch_bounds__(256) void softmax_semantic(const int* __restrict__ enc_len) {
    const int b = blockIdx.x, tid = threadIdx.x;
    const int len = enc_len[b];
    __shared__ float sa[TEE];
    __shared__ float red[8];

    float v0 = (tid       < len) ? g_sfw[b * TEE + tid]       : -1e30f;
    float v1 = (tid + 256 < len) ? g_sfw[b * TEE + tid + 256] : -1e30f;
    float M = blk_reduce(fmaxf(v0, v1), red, true);
    float e0 = (tid       < len) ? expf(v0 - M) : 0.0f;
    float e1 = (tid + 256 < len) ? expf(v1 - M) : 0.0f;
    float S = blk_reduce(e0 + e1, red, false);
    float inv = 0.5f / S;
    sa[tid] = e0 * inv; sa[tid + 256] = e1 * inv;
    __syncthreads();

    v0 = (tid       < len) ? g_sbw[b * TEE + tid]       : -1e30f;
    v1 = (tid + 256 < len) ? g_sbw[b * TEE + tid + 256] : -1e30f;
    M = blk_reduce(fmaxf(v0, v1), red, true);
    e0 = (tid       < len) ? expf(v0 - M) : 0.0f;
    e1 = (tid + 256 < len) ? expf(v1 - M) : 0.0f;
    S = blk_reduce(e0 + e1, red, false);
    inv = 0.5f / S;
    sa[tid] += e0 * inv; sa[tid + 256] += e1 * inv;
    __syncthreads();

    for (int d = tid; d < HH; d += 256) {
        float acc = 0.0f;
        #pragma unroll 4
        for (int t = 0; t < TEE; t++)
            acc += sa[t] * g_enc_out[((size_t)(b * TEE + t)) * HH + d];
        g_henc[b * 2 * HH + HH + d] = acc;
        g_henc[b * 2 * HH + d] = g_hA[b * HH + d];
    }
}

// ---------------------------------------------------------------------------
// Latent head (R1-proven)
// ---------------------------------------------------------------------------
__global__ __launch_bounds__(256) void latent_head(
    const float* __restrict__ W_mu, const float* __restrict__ b_mu,
    const float* __restrict__ W_ls, const float* __restrict__ b_ls,
    const float* __restrict__ noise, const int* __restrict__ dec_len,
    float* __restrict__ outbuf)
{
    const int b = blockIdx.x, tid = threadIdx.x;
    __shared__ float he[2 * HH];
    __shared__ float muv[LL], lsv[LL];
    for (int i = tid; i < 2 * HH; i += 256) he[i] = g_henc[b * 2 * HH + i];
    __syncthreads();

    const int w = tid >> 5, lane = tid & 31;
    for (int o = w; o < 2 * LL; o += 8) {
        const float* Wr; float bia; int j;
        if (o < LL) { j = o;      Wr = W_mu + (size_t)j * (2 * HH); bia = b_mu[j]; }
        else        { j = o - LL; Wr = W_ls + (size_t)j * (2 * HH); bia = b_ls[j]; }
        float acc = 0.0f;
        #pragma unroll 4
        for (int k = lane; k < 2 * HH; k += 32) acc += Wr[k] * he[k];
        #pragma unroll
        for (int s = 16; s > 0; s >>= 1) acc += __shfl_xor_sync(0xffffffffu, acc, s);
        if (lane == 0) { if (o < LL) muv[j] = acc + bia; else lsv[j] = acc + bia; }
    }
    __syncthreads();

    if (tid < LL) {
        float mu = muv[tid];
        float sg = expf(lsv[tid]);
        float zz = mu + sg * noise[b * LL + tid];
        g_z[b * LL + tid] = zz;
        outbuf[OFF_MU + b * LL + tid] = mu;
        outbuf[OFF_SG + b * LL + tid] = sg;
    }
    if (b == 0 && tid == 0) {
        int m = 0;
        for (int i = 0; i < BB; i++) m = max(m, dec_len[i]);
        outbuf[OFF_ML] = (float)m;
    }
}

// ---------------------------------------------------------------------------
// Launch
// ---------------------------------------------------------------------------
extern "C" void kernel_launch(void* const* d_in, const int* in_sizes, int n_in,
                              void* d_out, int out_size) {
    const float* emb     = (const float*)d_in[0];
    const float* enc_Wih = (const float*)d_in[1];
    const float* enc_Whh = (const float*)d_in[2];
    const float* enc_bih = (const float*)d_in[3];
    const float* enc_bhh = (const float*)d_in[4];
    const float* dec_Wih = (const float*)d_in[5];
    const float* dec_Whh = (const float*)d_in[6];
    const float* dec_bih = (const float*)d_in[7];
    const float* dec_bhh = (const float*)d_in[8];
    const float* W_mu    = (const float*)d_in[9];
    const float* b_mu    = (const float*)d_in[10];
    const float* W_ls    = (const float*)d_in[11];
    const float* b_ls    = (const float*)d_in[12];
    const float* W_fc    = (const float*)d_in[13];
    const float* b_fc    = (const float*)d_in[14];
    const float* noise   = (const float*)d_in[15];
    const int*   enc_ids = (const int*)d_in[16];
    const int*   enc_len = (const int*)d_in[17];
    const int*   dec_ids = (const int*)d_in[18];
    const int*   dec_len = (const int*)d_in[19];
    float* outbuf = (float*)d_out;

    float *p_gx_enc, *p_enc_out, *p_gx_dec, *p_dec_out, *p_hA, *p_hB, *p_z;
    cudaGetSymbolAddress((void**)&p_gx_enc, g_gx_enc);
    cudaGetSymbolAddress((void**)&p_enc_out, g_enc_out);
    cudaGetSymbolAddress((void**)&p_gx_dec, g_gx_dec);
    cudaGetSymbolAddress((void**)&p_dec_out, g_dec_out);
    cudaGetSymbolAddress((void**)&p_hA, g_hA);
    cudaGetSymbolAddress((void**)&p_hB, g_hB);
    cudaGetSymbolAddress((void**)&p_z, g_z);

    cudaFuncSetAttribute(logits_wmma, cudaFuncAttributeMaxDynamicSharedMemorySize, SM_TOT);

    // 1) gx_enc = emb[enc_ids] @ enc_Wih^T + bih   [8192 x 1536, K=512]
    gemm_nt128<512><<<dim3(1536 / 128, (BB * TEE) / 128), 256>>>(
        p_gx_enc, nullptr, enc_ids, emb, enc_Wih, enc_bih, 3 * HH, nullptr, 1);

    // 2) W_fc -> split-bf16 W' (independent; runs early)
    prep_w<<<VV, 256>>>(W_fc);

    // 3) padding no-op (keep gru_enc at launch #4 = profiled slot)
    noop_a<<<1, 32>>>();

    // 4) encoder GRU (persistent, 512 steps, 512 threads)  <-- profiled launch
    gru_persist<HH, 4, 8><<<HH / 4, 512>>>(
        p_gx_enc, enc_Whh, enc_bhh, enc_len, nullptr, p_hA, p_hB, p_enc_out, TEE);

    // 5-7) attention + latent path
    attn_scores<<<BB, 256>>>();
    softmax_semantic<<<BB, 256>>>(enc_len);
    latent_head<<<BB, 256>>>(W_mu, b_mu, W_ls, b_ls, noise, dec_len, outbuf);

    // 8) gx_dec = emb[dec_ids] @ dec_Wih^T + bih   [4096 x 768, K=512]
    gemm_nt128<512><<<dim3((3 * LL) / 128, (BB * TDD) / 128), 256>>>(
        p_gx_dec, nullptr, dec_ids, emb, dec_Wih, dec_bih, 3 * LL, nullptr, 1);

    // 9) decoder GRU (persistent, 256 steps, 512 threads), h0 = z
    gru_persist<LL, 2, 8><<<LL / 2, 512>>>(
        p_gx_dec, dec_Whh, dec_bhh, dec_len, p_z, p_hA, p_hB, p_dec_out, TDD);

    // 10) dec_out -> split-bf16 A'
    prep_a<<<BB * TDD, 256>>>();

    // 11) logits = A' @ W'^T + b_fc  (wmma bf16, K=768, zero-tile skip)
    logits_wmma<<<dim3(VV / 128, (BB * TDD) / 128), 256, SM_TOT>>>(
        b_fc, dec_len, outbuf);
}

// round 13
// speedup vs baseline: 1.3003x; 1.0263x over previous
#include <cuda_runtime.h>
#include <cuda_bf16.h>
#include <mma.h>
#include <math.h>
#include <stdint.h>

using namespace nvcuda;

// Problem dims
#define VV 32000
#define HH 512
#define LL 256
#define BB 16
#define TEE 512
#define TDD 256

// Output layout: [logits (B*TD*V)][dec_max_len (1)][mu (B*L)][sigma (B*L)]
#define OFF_ML  ((size_t)BB * TDD * VV)
#define OFF_MU  (OFF_ML + 1)
#define OFF_SG  (OFF_MU + (size_t)BB * LL)

// ---------------------------------------------------------------------------
// Scratch (static device globals; no allocation allowed)
// ---------------------------------------------------------------------------
__device__ float g_gx_enc[(size_t)BB * TEE * 3 * HH];   // 50.3 MB
__device__ float g_enc_out[(size_t)BB * TEE * HH];      // 16.8 MB
__device__ float g_gx_dec[(size_t)BB * TDD * 3 * LL];   // 12.6 MB
__device__ float g_dec_out[(size_t)BB * TDD * LL];      //  4.2 MB
__device__ float g_hA[BB * HH];
__device__ float g_hB[BB * HH];
__device__ float g_sfw[BB * TEE];
__device__ float g_sbw[BB * TEE];
__device__ float g_henc[BB * 2 * HH];
__device__ float g_z[BB * LL];
__device__ unsigned g_bar_count;
__device__ volatile unsigned g_bar_gen;

// Split-bf16 operands for the logits GEMM (K-concat: [hi|lo|hi] x [hi|hi|lo])
__device__ __nv_bfloat16 g_wfc_bf[(size_t)VV * 768];        // 49.2 MB
__device__ __nv_bfloat16 g_abf[(size_t)BB * TDD * 768];     //  6.3 MB

// ---------------------------------------------------------------------------
// Grid-wide barrier (R1/R4-proven flat version; all CTAs co-resident)
// ---------------------------------------------------------------------------
__device__ __forceinline__ void grid_barrier(unsigned nb) {
    __threadfence();
    __syncthreads();
    if (threadIdx.x == 0) {
        unsigned gen = g_bar_gen;
        unsigned arrived = atomicAdd(&g_bar_count, 1u);
        if (arrived == nb - 1) {
            g_bar_count = 0;
            __threadfence();
            g_bar_gen = gen + 1;
        } else {
            while (g_bar_gen == gen) { }
        }
        __threadfence();
    }
    __syncthreads();
}

__device__ __forceinline__ float sigmoidf_(float x) { return 1.0f / (1.0f + expf(-x)); }
__device__ __forceinline__ float dot4_(float4 w, float4 h) {
    return w.x * h.x + w.y * h.y + w.z * h.z + w.w * h.w;
}

// ---------------------------------------------------------------------------
// Persistent GRU (R8-proven), 512 threads, 3-gate-fused dot, NS-way K-split.
// ---------------------------------------------------------------------------
template<int K, int CW, int NS>
__global__ __launch_bounds__(512, 1) void gru_persist(
    const float* __restrict__ gx,
    const float* __restrict__ Whh,
    const float* __restrict__ bhh,
    const int*   __restrict__ lens,
    const float* __restrict__ h0,
    float* hA, float* hB,
    float* __restrict__ out,
    int T)
{
    constexpr int PW = K + 4;
    constexpr int NC = 16 * CW * NS;
    constexpr int NU = 16 * CW;
    constexpr int KQ = K / NS;
    __shared__ float hs[16 * PW];
    __shared__ float pex[3 * CW * NS * 16];
    __shared__ int   lens_s[16];

    const int tid = threadIdx.x;
    const int bx  = blockIdx.x;
    const unsigned NB = gridDim.x;

    const float4 *w0p = nullptr, *w1p = nullptr, *w2p = nullptr;
    int db = tid & 15;
    int q  = (tid >> 4) % NS;
    int cl = tid / (16 * NS);
    if (tid < NC) {
        int dc = bx * CW + cl;
        w0p = (const float4*)(Whh + (size_t)(0 * K + dc) * K + q * KQ);
        w1p = (const float4*)(Whh + (size_t)(1 * K + dc) * K + q * KQ);
        w2p = (const float4*)(Whh + (size_t)(2 * K + dc) * K + q * KQ);
    }
    int ub = tid & 15, ucl = tid >> 4;
    int uc = bx * CW + ucl;
    float bhr = 0.f, bhz = 0.f, bhn = 0.f;
    if (tid < NU) {
        bhr = bhh[uc]; bhz = bhh[K + uc]; bhn = bhh[2 * K + uc];
    }

    if (tid < 16) lens_s[tid] = lens[tid];
    if (tid < NU) {
        float v = h0 ? h0[ub * K + uc] : 0.0f;
        __stcg(&hA[ub * K + uc], v);
    }
    grid_barrier(NB);

    for (int t = 0; t < T; t++) {
        float* hcur  = (t & 1) ? hB : hA;
        float* hnext = (t & 1) ? hA : hB;

        float gxr = 0.f, gxz = 0.f, gxn = 0.f;
        if (tid < NU) {
            const float* gxp = gx + (size_t)(ub * T + t) * (3 * K);
            gxr = __ldg(gxp + uc);
            gxz = __ldg(gxp + K + uc);
            gxn = __ldg(gxp + 2 * K + uc);
        }

        const float4* hc4 = (const float4*)hcur;
        #pragma unroll
        for (int i = tid; i < 16 * K / 4; i += 512) {
            float4 v = __ldcg(hc4 + i);
            int b = i / (K / 4), kq = i % (K / 4);
            *(float4*)&hs[b * PW + 4 * kq] = v;
        }
        __syncthreads();

        if (tid < NC) {
            const float4* hp = (const float4*)&hs[db * PW + q * KQ];
            float a00 = 0.f, a01 = 0.f, a10 = 0.f, a11 = 0.f, a20 = 0.f, a21 = 0.f;
            #pragma unroll
            for (int kk = 0; kk < KQ / 8; kk++) {
                float4 hv0 = hp[2 * kk + 0];
                float4 hv1 = hp[2 * kk + 1];
                float4 wa0 = __ldg(w0p + 2 * kk + 0);
                float4 wa1 = __ldg(w0p + 2 * kk + 1);
                float4 wb0 = __ldg(w1p + 2 * kk + 0);
                float4 wb1 = __ldg(w1p + 2 * kk + 1);
                float4 wc0 = __ldg(w2p + 2 * kk + 0);
                float4 wc1 = __ldg(w2p + 2 * kk + 1);
                a00 += dot4_(wa0, hv0); a01 += dot4_(wa1, hv1);
                a10 += dot4_(wb0, hv0); a11 += dot4_(wb1, hv1);
                a20 += dot4_(wc0, hv0); a21 += dot4_(wc1, hv1);
            }
            pex[((0 * CW + cl) * NS + q) * 16 + db] = a00 + a01;
            pex[((1 * CW + cl) * NS + q) * 16 + db] = a10 + a11;
            pex[((2 * CW + cl) * NS + q) * 16 + db] = a20 + a21;
        }
        __syncthreads();

        if (tid < NU) {
            float ghr = 0.f, ghz = 0.f, ghn = 0.f;
            #pragma unroll
            for (int qq = 0; qq < NS; qq++) {
                ghr += pex[((0 * CW + ucl) * NS + qq) * 16 + ub];
                ghz += pex[((1 * CW + ucl) * NS + qq) * 16 + ub];
                ghn += pex[((2 * CW + ucl) * NS + qq) * 16 + ub];
            }
            float r = sigmoidf_(gxr + ghr + bhr);
            float z = sigmoidf_(gxz + ghz + bhz);
            float n = tanhf   (gxn + r * (ghn + bhn));
            float hold = hs[ub * PW + uc];
            float hnew = (1.0f - z) * n + z * hold;
            bool valid = (t < lens_s[ub]);
            __stcg(&hnext[ub * K + uc], valid ? hnew : hold);
            out[(size_t)(ub * T + t) * K + uc] = valid ? hnew : 0.0f;
        }
        grid_barrier(NB);
    }
}

// ---------------------------------------------------------------------------
// 128x128x8 fp32 SGEMM-NT (R8-proven), used for gx_enc / gx_dec.
// ---------------------------------------------------------------------------
template<int KD>
__global__ __launch_bounds__(256, 2) void gemm_nt128(
    float* __restrict__ C,
    const float* __restrict__ Adirect,
    const int*   __restrict__ ids,
    const float* __restrict__ Atab,
    const float* __restrict__ W,
    const float* __restrict__ bias,
    int N,
    const int* __restrict__ skiplen,
    int tper)
{
    __shared__ float As[2][8][128];
    __shared__ float Bs[2][8][128];
    const int tid  = threadIdx.x;
    const int row0 = blockIdx.y * 128, col0 = blockIdx.x * 128;
    const int ty = tid >> 4, tx = tid & 15;

    if (skiplen) {
        int bb = row0 / tper, t0 = row0 % tper;
        if (t0 >= __ldg(&skiplen[bb])) {
            float4 blo = *(const float4*)(bias + col0 + tx * 8);
            float4 bhi = *(const float4*)(bias + col0 + tx * 8 + 4);
            #pragma unroll
            for (int i = 0; i < 8; i++) {
                float* cp = C + (size_t)(row0 + ty * 8 + i) * N + col0 + tx * 8;
                *(float4*)cp = blo; *(float4*)(cp + 4) = bhi;
            }
            return;
        }
    }

    const int lr  = tid >> 1;
    const int lk4 = (tid & 1) * 4;
    const float* arow = ids ? (Atab + (size_t)__ldg(&ids[row0 + lr]) * KD)
                            : (Adirect + (size_t)(row0 + lr) * KD);
    const float* wrow = W + (size_t)(col0 + lr) * KD;

    {
        float4 av = *(const float4*)(arow + lk4);
        float4 wv = *(const float4*)(wrow + lk4);
        As[0][lk4 + 0][lr] = av.x; As[0][lk4 + 1][lr] = av.y;
        As[0][lk4 + 2][lr] = av.z; As[0][lk4 + 3][lr] = av.w;
        Bs[0][lk4 + 0][lr] = wv.x; Bs[0][lk4 + 1][lr] = wv.y;
        Bs[0][lk4 + 2][lr] = wv.z; Bs[0][lk4 + 3][lr] = wv.w;
    }
    __syncthreads();

    float acc[8][8];
    #pragma unroll
    for (int i = 0; i < 8; i++)
        #pragma unroll
        for (int j = 0; j < 8; j++) acc[i][j] = 0.0f;

    constexpr int NK = KD / 8;
    #pragma unroll 1
    for (int kt = 0; kt < NK; kt++) {
        const int cur = kt & 1;
        float4 av2, wv2;
        if (kt + 1 < NK) {
            av2 = *(const float4*)(arow + (kt + 1) * 8 + lk4);
            wv2 = *(const float4*)(wrow + (kt + 1) * 8 + lk4);
        }
        #pragma unroll
        for (int k = 0; k < 8; k++) {
            float a[8], b[8];
            *(float4*)&a[0] = *(const float4*)&As[cur][k][ty * 8];
            *(float4*)&a[4] = *(const float4*)&As[cur][k][ty * 8 + 4];
            *(float4*)&b[0] = *(const float4*)&Bs[cur][k][tx * 8];
            *(float4*)&b[4] = *(const float4*)&Bs[cur][k][tx * 8 + 4];
            #pragma unroll
            for (int i = 0; i < 8; i++)
                #pragma unroll
                for (int j = 0; j < 8; j++)
                    acc[i][j] += a[i] * b[j];
        }
        if (kt + 1 < NK) {
            const int nxt = cur ^ 1;
            As[nxt][lk4 + 0][lr] = av2.x; As[nxt][lk4 + 1][lr] = av2.y;
            As[nxt][lk4 + 2][lr] = av2.z; As[nxt][lk4 + 3][lr] = av2.w;
            Bs[nxt][lk4 + 0][lr] = wv2.x; Bs[nxt][lk4 + 1][lr] = wv2.y;
            Bs[nxt][lk4 + 2][lr] = wv2.z; Bs[nxt][lk4 + 3][lr] = wv2.w;
        }
        __syncthreads();
    }

    float4 blo = *(const float4*)(bias + col0 + tx * 8);
    float4 bhi = *(const float4*)(bias + col0 + tx * 8 + 4);
    #pragma unroll
    for (int i = 0; i < 8; i++) {
        float* cp = C + (size_t)(row0 + ty * 8 + i) * N + col0 + tx * 8;
        float4 v0 = make_float4(acc[i][0] + blo.x, acc[i][1] + blo.y,
                                acc[i][2] + blo.z, acc[i][3] + blo.w);
        float4 v1 = make_float4(acc[i][4] + bhi.x, acc[i][5] + bhi.y,
                                acc[i][6] + bhi.z, acc[i][7] + bhi.w);
        *(float4*)cp = v0; *(float4*)(cp + 4) = v1;
    }
}

// ---------------------------------------------------------------------------
// Split-bf16 prep: W'[n] = [hi | hi | lo], A'[m] = [hi | lo | hi]
// ---------------------------------------------------------------------------
__global__ __launch_bounds__(256) void prep_w(const float* __restrict__ W) {
    int n = blockIdx.x, k = threadIdx.x;
    float x = __ldg(&W[(size_t)n * LL + k]);
    __nv_bfloat16 hi = __float2bfloat16(x);
    __nv_bfloat16 lo = __float2bfloat16(x - __bfloat162float(hi));
    __nv_bfloat16* dst = g_wfc_bf + (size_t)n * 768;
    dst[k] = hi; dst[LL + k] = hi; dst[2 * LL + k] = lo;
}
__global__ __launch_bounds__(256) void prep_a() {
    int m = blockIdx.x, k = threadIdx.x;
    float x = g_dec_out[(size_t)m * LL + k];
    __nv_bfloat16 hi = __float2bfloat16(x);
    __nv_bfloat16 lo = __float2bfloat16(x - __bfloat162float(hi));
    __nv_bfloat16* dst = g_abf + (size_t)m * 768;
    dst[k] = hi; dst[LL + k] = lo; dst[2 * LL + k] = hi;
}

// ---------------------------------------------------------------------------
// wmma bf16 GEMM for logits: C[4096,32000] = A'[4096,768] @ W'[32000,768]^T
// CTA: 128x128 tile, 8 warps (4m x 2n), warp = 32x64 = 2x4 wmma 16x16x16
// fragments, fp32 accum. K=768 in 12 chunks of 64, double-buffered smem;
// C staging reuses the A/B smem after the final chunk sync (73.7 KB total
// -> 2 CTAs/SM).
// ---------------------------------------------------------------------------
#define WKC   64                              // bf16 per K chunk
#define NCHNK (768 / WKC)                     // 12
#define APIT  72                              // smem pitch (bf16), mult of 8
#define CPIT  132                             // staging pitch (f32), mult of 4
#define SM_A  0
#define SM_B  (2 * 128 * APIT * 2)            // 36864 B
#define SM_TOT (2 * SM_B)                     // 73728 B (C staging overlaps A)

__global__ __launch_bounds__(256) void logits_wmma(
    const float* __restrict__ bias,
    const int* __restrict__ dec_len,
    float* __restrict__ C)
{
    extern __shared__ char smc[];
    __nv_bfloat16* As = (__nv_bfloat16*)(smc + SM_A);   // [2][128][APIT]
    __nv_bfloat16* Bs = (__nv_bfloat16*)(smc + SM_B);   // [2][128][APIT]
    float*        Cst = (float*)(smc + SM_A);           // overlaps As/Bs

    const int tid = threadIdx.x;
    const int col0 = blockIdx.x * 128, row0 = blockIdx.y * 128;

    // whole-tile zero-row skip -> bias only
    {
        int bb = row0 / TDD, t0 = row0 % TDD;
        if (t0 >= __ldg(&dec_len[bb])) {
            int r = tid >> 1, half = tid & 1;
            float* cp = C + (size_t)(row0 + r) * VV + col0 + half * 64;
            #pragma unroll
            for (int i = 0; i < 16; i++) {
                const float* bp = bias + col0 + half * 64 + i * 4;
                *(float4*)(cp + i * 4) = make_float4(__ldg(bp), __ldg(bp + 1),
                                                     __ldg(bp + 2), __ldg(bp + 3));
            }
            return;
        }
    }

    const int wid = tid >> 5;
    const int wm = wid >> 1;        // 0..3 -> m offset wm*32
    const int wn = wid & 1;         // 0..1 -> n offset wn*64

    // loader identity: row r (0..127), 32-bf16 segment (0/1)
    const int lr  = tid >> 1;
    const int seg = (tid & 1) * 32;
    const __nv_bfloat16* Ag = g_abf    + (size_t)(row0 + lr) * 768 + seg;
    const __nv_bfloat16* Bg = g_wfc_bf + (size_t)(col0 + lr) * 768 + seg;

    // prologue: chunk 0 -> buffer 0
    {
        __nv_bfloat16* ap = As + lr * APIT + seg;
        __nv_bfloat16* bp = Bs + lr * APIT + seg;
        #pragma unroll
        for (int i = 0; i < 4; i++) {
            *(uint4*)(ap + i * 8) = *(const uint4*)(Ag + i * 8);
            *(uint4*)(bp + i * 8) = *(const uint4*)(Bg + i * 8);
        }
    }
    __syncthreads();

    wmma::fragment<wmma::accumulator, 16, 16, 16, float> cf[2][4];
    #pragma unroll
    for (int i = 0; i < 2; i++)
        #pragma unroll
        for (int j = 0; j < 4; j++)
            wmma::fill_fragment(cf[i][j], 0.0f);

    #pragma unroll 1
    for (int ch = 0; ch < NCHNK; ch++) {
        const int cur = ch & 1;
        uint4 apre[4], bpre[4];
        if (ch + 1 < NCHNK) {
            const __nv_bfloat16* Agn = Ag + (ch + 1) * WKC;
            const __nv_bfloat16* Bgn = Bg + (ch + 1) * WKC;
            #pragma unroll
            for (int i = 0; i < 4; i++) {
                apre[i] = *(const uint4*)(Agn + i * 8);
                bpre[i] = *(const uint4*)(Bgn + i * 8);
            }
        }

        const __nv_bfloat16* Ab = As + cur * 128 * APIT;
        const __nv_bfloat16* Bb = Bs + cur * 128 * APIT;
        #pragma unroll
        for (int kk = 0; kk < WKC; kk += 16) {
            wmma::fragment<wmma::matrix_a, 16, 16, 16, __nv_bfloat16, wmma::row_major> af[2];
            wmma::fragment<wmma::matrix_b, 16, 16, 16, __nv_bfloat16, wmma::col_major> bf[4];
            #pragma unroll
            for (int i = 0; i < 2; i++)
                wmma::load_matrix_sync(af[i], Ab + (wm * 32 + i * 16) * APIT + kk, APIT);
            #pragma unroll
            for (int j = 0; j < 4; j++)
                wmma::load_matrix_sync(bf[j], Bb + (wn * 64 + j * 16) * APIT + kk, APIT);
            #pragma unroll
            for (int i = 0; i < 2; i++)
                #pragma unroll
                for (int j = 0; j < 4; j++)
                    wmma::mma_sync(cf[i][j], af[i], bf[j], cf[i][j]);
        }

        if (ch + 1 < NCHNK) {
            const int nxt = cur ^ 1;
            __nv_bfloat16* ap = As + nxt * 128 * APIT + lr * APIT + seg;
            __nv_bfloat16* bp = Bs + nxt * 128 * APIT + lr * APIT + seg;
            #pragma unroll
            for (int i = 0; i < 4; i++) {
                *(uint4*)(ap + i * 8) = apre[i];
                *(uint4*)(bp + i * 8) = bpre[i];
            }
        }
        __syncthreads();
    }

    // stage accumulators to smem (A/B buffers are dead now; last sync above)
    #pragma unroll
    for (int i = 0; i < 2; i++)
        #pragma unroll
        for (int j = 0; j < 4; j++)
            wmma::store_matrix_sync(Cst + (wm * 32 + i * 16) * CPIT + wn * 64 + j * 16,
                                    cf[i][j], CPIT, wmma::mem_row_major);
    __syncthreads();

    // bias add + coalesced store
    {
        int r = tid >> 1, half = tid & 1;
        const float* sp = Cst + r * CPIT + half * 64;
        float* cp = C + (size_t)(row0 + r) * VV + col0 + half * 64;
        #pragma unroll
        for (int i = 0; i < 16; i++) {
            const float* bp = bias + col0 + half * 64 + i * 4;
            float4 v = *(const float4*)(sp + i * 4);
            *(float4*)(cp + i * 4) = make_float4(v.x + __ldg(bp), v.y + __ldg(bp + 1),
                                                 v.z + __ldg(bp + 2), v.w + __ldg(bp + 3));
        }
    }
}

// ---------------------------------------------------------------------------
// Padding no-op (keeps gru_enc at my 4th launch = ncu profiled slot)
// ---------------------------------------------------------------------------
__global__ void noop_a() {}

// ---------------------------------------------------------------------------
// Attention scores (R1-proven)
// ---------------------------------------------------------------------------
__global__ __launch_bounds__(256) void attn_scores() {
    const int b = blockIdx.x, tid = threadIdx.x;
    __shared__ float last_s[HH], first_s[HH];
    for (int i = tid; i < HH; i += 256) {
        last_s[i]  = g_hA[b * HH + i];
        first_s[i] = g_enc_out[((size_t)b * TEE + 0) * HH + i];
    }
    __syncthreads();
    const int w = tid >> 5, lane = tid & 31;
    for (int t = w; t < TEE; t += 8) {
        const float* orow = g_enc_out + ((size_t)(b * TEE + t)) * HH;
        float af = 0.0f, ab = 0.0f;
        #pragma unroll 4
        for (int i = lane; i < HH; i += 32) {
            float v = orow[i];
            af += v * last_s[i];
            ab += v * first_s[i];
        }
        #pragma unroll
        for (int o = 16; o > 0; o >>= 1) {
            af += __shfl_xor_sync(0xffffffffu, af, o);
            ab += __shfl_xor_sync(0xffffffffu, ab, o);
        }
        if (lane == 0) { g_sfw[b * TEE + t] = af; g_sbw[b * TEE + t] = ab; }
    }
}

__device__ __forceinline__ float blk_reduce(float v, float* red, bool ismax) {
    #pragma unroll
    for (int o = 16; o > 0; o >>= 1) {
        float u = __shfl_xor_sync(0xffffffffu, v, o);
        v = ismax ? fmaxf(v, u) : (v + u);
    }
    int w = threadIdx.x >> 5;
    if ((threadIdx.x & 31) == 0) red[w] = v;
    __syncthreads();
    if (threadIdx.x == 0) {
        float a = red[0];
        for (int i = 1; i < 8; i++) a = ismax ? fmaxf(a, red[i]) : (a + red[i]);
        red[0] = a;
    }
    __syncthreads();
    float r = red[0];
    __syncthreads();
    return r;
}

// ---------------------------------------------------------------------------
// Masked dual softmax + semantic pooling + h_enc assembly (R1-proven).
// ---------------------------------------------------------------------------
__global__ __launch_bounds__(256) void softmax_semantic(const int* __restrict__ enc_len) {
    const int b = blockIdx.x, tid = threadIdx.x;
    const int len = enc_len[b];
    __shared__ float sa[TEE];
    __shared__ float red[8];

    float v0 = (tid       < len) ? g_sfw[b * TEE + tid]       : -1e30f;
    float v1 = (tid + 256 < len) ? g_sfw[b * TEE + tid + 256] : -1e30f;
    float M = blk_reduce(fmaxf(v0, v1), red, true);
    float e0 = (tid       < len) ? expf(v0 - M) : 0.0f;
    float e1 = (tid + 256 < len) ? expf(v1 - M) : 0.0f;
    float S = blk_reduce(e0 + e1, red, false);
    float inv = 0.5f / S;
    sa[tid] = e0 * inv; sa[tid + 256] = e1 * inv;
    __syncthreads();

    v0 = (tid       < len) ? g_sbw[b * TEE + tid]       : -1e30f;
    v1 = (tid + 256 < len) ? g_sbw[b * TEE + tid + 256] : -1e30f;
    M = blk_reduce(fmaxf(v0, v1), red, true);
    e0 = (tid       < len) ? expf(v0 - M) : 0.0f;
    e1 = (tid + 256 < len) ? expf(v1 - M) : 0.0f;
    S = blk_reduce(e0 + e1, red, false);
    inv = 0.5f / S;
    sa[tid] += e0 * inv; sa[tid + 256] += e1 * inv;
    __syncthreads();

    for (int d = tid; d < HH; d += 256) {
        float acc = 0.0f;
        #pragma unroll 4
        for (int t = 0; t < TEE; t++)
            acc += sa[t] * g_enc_out[((size_t)(b * TEE + t)) * HH + d];
        g_henc[b * 2 * HH + HH + d] = acc;
        g_henc[b * 2 * HH + d] = g_hA[b * HH + d];
    }
}

// ---------------------------------------------------------------------------
// Latent head (R1-proven)
// ---------------------------------------------------------------------------
__global__ __launch_bounds__(256) void latent_head(
    const float* __restrict__ W_mu, const float* __restrict__ b_mu,
    const float* __restrict__ W_ls, const float* __restrict__ b_ls,
    const float* __restrict__ noise, const int* __restrict__ dec_len,
    float* __restrict__ outbuf)
{
    const int b = blockIdx.x, tid = threadIdx.x;
    __shared__ float he[2 * HH];
    __shared__ float muv[LL], lsv[LL];
    for (int i = tid; i < 2 * HH; i += 256) he[i] = g_henc[b * 2 * HH + i];
    __syncthreads();

    const int w = tid >> 5, lane = tid & 31;
    for (int o = w; o < 2 * LL; o += 8) {
        const float* Wr; float bia; int j;
        if (o < LL) { j = o;      Wr = W_mu + (size_t)j * (2 * HH); bia = b_mu[j]; }
        else        { j = o - LL; Wr = W_ls + (size_t)j * (2 * HH); bia = b_ls[j]; }
        float acc = 0.0f;
        #pragma unroll 4
        for (int k = lane; k < 2 * HH; k += 32) acc += Wr[k] * he[k];
        #pragma unroll
        for (int s = 16; s > 0; s >>= 1) acc += __shfl_xor_sync(0xffffffffu, acc, s);
        if (lane == 0) { if (o < LL) muv[j] = acc + bia; else lsv[j] = acc + bia; }
    }
    __syncthreads();

    if (tid < LL) {
        float mu = muv[tid];
        float sg = expf(lsv[tid]);
        float zz = mu + sg * noise[b * LL + tid];
        g_z[b * LL + tid] = zz;
        outbuf[OFF_MU + b * LL + tid] = mu;
        outbuf[OFF_SG + b * LL + tid] = sg;
    }
    if (b == 0 && tid == 0) {
        int m = 0;
        for (int i = 0; i < BB; i++) m = max(m, dec_len[i]);
        outbuf[OFF_ML] = (float)m;
    }
}

// ---------------------------------------------------------------------------
// Launch (identical order to R10, which ran successfully)
// ---------------------------------------------------------------------------
extern "C" void kernel_launch(void* const* d_in, const int* in_sizes, int n_in,
                              void* d_out, int out_size) {
    const float* emb     = (const float*)d_in[0];
    const float* enc_Wih = (const float*)d_in[1];
    const float* enc_Whh = (const float*)d_in[2];
    const float* enc_bih = (const float*)d_in[3];
    const float* enc_bhh = (const float*)d_in[4];
    const float* dec_Wih = (const float*)d_in[5];
    const float* dec_Whh = (const float*)d_in[6];
    const float* dec_bih = (const float*)d_in[7];
    const float* dec_bhh = (const float*)d_in[8];
    const float* W_mu    = (const float*)d_in[9];
    const float* b_mu    = (const float*)d_in[10];
    const float* W_ls    = (const float*)d_in[11];
    const float* b_ls    = (const float*)d_in[12];
    const float* W_fc    = (const float*)d_in[13];
    const float* b_fc    = (const float*)d_in[14];
    const float* noise   = (const float*)d_in[15];
    const int*   enc_ids = (const int*)d_in[16];
    const int*   enc_len = (const int*)d_in[17];
    const int*   dec_ids = (const int*)d_in[18];
    const int*   dec_len = (const int*)d_in[19];
    float* outbuf = (float*)d_out;

    float *p_gx_enc, *p_enc_out, *p_gx_dec, *p_dec_out, *p_hA, *p_hB, *p_z;
    cudaGetSymbolAddress((void**)&p_gx_enc, g_gx_enc);
    cudaGetSymbolAddress((void**)&p_enc_out, g_enc_out);
    cudaGetSymbolAddress((void**)&p_gx_dec, g_gx_dec);
    cudaGetSymbolAddress((void**)&p_dec_out, g_dec_out);
    cudaGetSymbolAddress((void**)&p_hA, g_hA);
    cudaGetSymbolAddress((void**)&p_hB, g_hB);
    cudaGetSymbolAddress((void**)&p_z, g_z);

    cudaFuncSetAttribute(logits_wmma, cudaFuncAttributeMaxDynamicSharedMemorySize, SM_TOT);

    // 1) gx_enc = emb[enc_ids] @ enc_Wih^T + bih   [8192 x 1536, K=512]
    gemm_nt128<512><<<dim3(1536 / 128, (BB * TEE) / 128), 256>>>(
        p_gx_enc, nullptr, enc_ids, emb, enc_Wih, enc_bih, 3 * HH, nullptr, 1);

    // 2) W_fc -> split-bf16 W' (independent; runs early)
    prep_w<<<VV, 256>>>(W_fc);

    // 3) padding no-op
    noop_a<<<1, 32>>>();

    // 4) encoder GRU (persistent, 512 steps, 512 threads)  <-- profiled slot
    gru_persist<HH, 4, 8><<<HH / 4, 512>>>(
        p_gx_enc, enc_Whh, enc_bhh, enc_len, nullptr, p_hA, p_hB, p_enc_out, TEE);

    // 5-7) attention + latent path
    attn_scores<<<BB, 256>>>();
    softmax_semantic<<<BB, 256>>>(enc_len);
    latent_head<<<BB, 256>>>(W_mu, b_mu, W_ls, b_ls, noise, dec_len, outbuf);

    // 8) gx_dec = emb[dec_ids] @ dec_Wih^T + bih   [4096 x 768, K=512]
    gemm_nt128<512><<<dim3((3 * LL) / 128, (BB * TDD) / 128), 256>>>(
        p_gx_dec, nullptr, dec_ids, emb, dec_Wih, dec_bih, 3 * LL, nullptr, 1);

    // 9) decoder GRU (persistent, 256 steps, 512 threads), h0 = z
    gru_persist<LL, 2, 8><<<LL / 2, 512>>>(
        p_gx_dec, dec_Whh, dec_bhh, dec_len, p_z, p_hA, p_hB, p_dec_out, TDD);

    // 10) dec_out -> split-bf16 A'
    prep_a<<<BB * TDD, 256>>>();

    // 11) logits = A' @ W'^T + b_fc  (wmma bf16, K=768, zero-tile skip)
    logits_wmma<<<dim3(VV / 128, (BB * TDD) / 128), 256, SM_TOT>>>(
        b_fc, dec_len, outbuf);
}

// round 14
// speedup vs baseline: 1.3714x; 1.0547x over previous
#include <cuda_runtime.h>
#include <cuda_bf16.h>
#include <mma.h>
#include <math.h>
#include <stdint.h>

using namespace nvcuda;

// Problem dims
#define VV 32000
#define HH 512
#define LL 256
#define BB 16
#define TEE 512
#define TDD 256

// Output layout: [logits (B*TD*V)][dec_max_len (1)][mu (B*L)][sigma (B*L)]
#define OFF_ML  ((size_t)BB * TDD * VV)
#define OFF_MU  (OFF_ML + 1)
#define OFF_SG  (OFF_MU + (size_t)BB * LL)

// ---------------------------------------------------------------------------
// Scratch (static device globals; no allocation allowed)
// ---------------------------------------------------------------------------
__device__ float g_gx_enc[(size_t)BB * TEE * 3 * HH];   // 50.3 MB
__device__ float g_enc_out[(size_t)BB * TEE * HH];      // 16.8 MB
__device__ float g_gx_dec[(size_t)BB * TDD * 3 * LL];   // 12.6 MB
__device__ float g_dec_out[(size_t)BB * TDD * LL];      //  4.2 MB
__device__ float g_hA[BB * HH];
__device__ float g_hB[BB * HH];
__device__ float g_sfw[BB * TEE];
__device__ float g_sbw[BB * TEE];
__device__ float g_henc[BB * 2 * HH];
__device__ float g_z[BB * LL];
__device__ unsigned g_bar_count;
__device__ volatile unsigned g_bar_gen;

// Split-bf16 operands for the logits GEMM (K-concat: [hi|lo|hi] x [hi|hi|lo])
__device__ __nv_bfloat16 g_wfc_bf[(size_t)VV * 768];        // 49.2 MB
__device__ __nv_bfloat16 g_abf[(size_t)BB * TDD * 768];     //  6.3 MB

// ---------------------------------------------------------------------------
// Grid-wide barrier (R1/R4-proven flat version; all CTAs co-resident)
// ---------------------------------------------------------------------------
__device__ __forceinline__ void grid_barrier(unsigned nb) {
    __threadfence();
    __syncthreads();
    if (threadIdx.x == 0) {
        unsigned gen = g_bar_gen;
        unsigned arrived = atomicAdd(&g_bar_count, 1u);
        if (arrived == nb - 1) {
            g_bar_count = 0;
            __threadfence();
            g_bar_gen = gen + 1;
        } else {
            while (g_bar_gen == gen) { }
        }
        __threadfence();
    }
    __syncthreads();
}

__device__ __forceinline__ float sigmoidf_(float x) { return 1.0f / (1.0f + expf(-x)); }
__device__ __forceinline__ float dot4_(float4 w, float4 h) {
    return w.x * h.x + w.y * h.y + w.z * h.z + w.w * h.w;
}

// ---------------------------------------------------------------------------
// Persistent GRU (R8-proven body), 512 threads, 3-gate-fused dot, NS-way
// K-split. NEW: loop truncated at maxT = max(lens) (identical in all CTAs);
// post-loop parity copy keeps the final state in hA.
// ---------------------------------------------------------------------------
template<int K, int CW, int NS>
__global__ __launch_bounds__(512, 1) void gru_persist(
    const float* __restrict__ gx,
    const float* __restrict__ Whh,
    const float* __restrict__ bhh,
    const int*   __restrict__ lens,
    const float* __restrict__ h0,
    float* hA, float* hB,
    float* __restrict__ out,
    int T)
{
    constexpr int PW = K + 4;
    constexpr int NC = 16 * CW * NS;
    constexpr int NU = 16 * CW;
    constexpr int KQ = K / NS;
    __shared__ float hs[16 * PW];
    __shared__ float pex[3 * CW * NS * 16];
    __shared__ int   lens_s[16];
    __shared__ int   maxT_s;

    const int tid = threadIdx.x;
    const int bx  = blockIdx.x;
    const unsigned NB = gridDim.x;

    const float4 *w0p = nullptr, *w1p = nullptr, *w2p = nullptr;
    int db = tid & 15;
    int q  = (tid >> 4) % NS;
    int cl = tid / (16 * NS);
    if (tid < NC) {
        int dc = bx * CW + cl;
        w0p = (const float4*)(Whh + (size_t)(0 * K + dc) * K + q * KQ);
        w1p = (const float4*)(Whh + (size_t)(1 * K + dc) * K + q * KQ);
        w2p = (const float4*)(Whh + (size_t)(2 * K + dc) * K + q * KQ);
    }
    int ub = tid & 15, ucl = tid >> 4;
    int uc = bx * CW + ucl;
    float bhr = 0.f, bhz = 0.f, bhn = 0.f;
    if (tid < NU) {
        bhr = bhh[uc]; bhz = bhh[K + uc]; bhn = bhh[2 * K + uc];
    }

    if (tid < 16) lens_s[tid] = lens[tid];
    if (tid < NU) {
        float v = h0 ? h0[ub * K + uc] : 0.0f;
        __stcg(&hA[ub * K + uc], v);
    }
    __syncthreads();
    if (tid == 0) {
        int m = 0;
        #pragma unroll
        for (int i = 0; i < 16; i++) m = max(m, lens_s[i]);
        maxT_s = m;
    }
    grid_barrier(NB);          // syncthreads inside publishes maxT_s
    const int maxT = maxT_s;   // same value in every CTA (same lens input)

    for (int t = 0; t < maxT; t++) {
        float* hcur  = (t & 1) ? hB : hA;
        float* hnext = (t & 1) ? hA : hB;

        float gxr = 0.f, gxz = 0.f, gxn = 0.f;
        if (tid < NU) {
            const float* gxp = gx + (size_t)(ub * T + t) * (3 * K);
            gxr = __ldg(gxp + uc);
            gxz = __ldg(gxp + K + uc);
            gxn = __ldg(gxp + 2 * K + uc);
        }

        const float4* hc4 = (const float4*)hcur;
        #pragma unroll
        for (int i = tid; i < 16 * K / 4; i += 512) {
            float4 v = __ldcg(hc4 + i);
            int b = i / (K / 4), kq = i % (K / 4);
            *(float4*)&hs[b * PW + 4 * kq] = v;
        }
        __syncthreads();

        if (tid < NC) {
            const float4* hp = (const float4*)&hs[db * PW + q * KQ];
            float a00 = 0.f, a01 = 0.f, a10 = 0.f, a11 = 0.f, a20 = 0.f, a21 = 0.f;
            #pragma unroll
            for (int kk = 0; kk < KQ / 8; kk++) {
                float4 hv0 = hp[2 * kk + 0];
                float4 hv1 = hp[2 * kk + 1];
                float4 wa0 = __ldg(w0p + 2 * kk + 0);
                float4 wa1 = __ldg(w0p + 2 * kk + 1);
                float4 wb0 = __ldg(w1p + 2 * kk + 0);
                float4 wb1 = __ldg(w1p + 2 * kk + 1);
                float4 wc0 = __ldg(w2p + 2 * kk + 0);
                float4 wc1 = __ldg(w2p + 2 * kk + 1);
                a00 += dot4_(wa0, hv0); a01 += dot4_(wa1, hv1);
                a10 += dot4_(wb0, hv0); a11 += dot4_(wb1, hv1);
                a20 += dot4_(wc0, hv0); a21 += dot4_(wc1, hv1);
            }
            pex[((0 * CW + cl) * NS + q) * 16 + db] = a00 + a01;
            pex[((1 * CW + cl) * NS + q) * 16 + db] = a10 + a11;
            pex[((2 * CW + cl) * NS + q) * 16 + db] = a20 + a21;
        }
        __syncthreads();

        if (tid < NU) {
            float ghr = 0.f, ghz = 0.f, ghn = 0.f;
            #pragma unroll
            for (int qq = 0; qq < NS; qq++) {
                ghr += pex[((0 * CW + ucl) * NS + qq) * 16 + ub];
                ghz += pex[((1 * CW + ucl) * NS + qq) * 16 + ub];
                ghn += pex[((2 * CW + ucl) * NS + qq) * 16 + ub];
            }
            float r = sigmoidf_(gxr + ghr + bhr);
            float z = sigmoidf_(gxz + ghz + bhz);
            float n = tanhf   (gxn + r * (ghn + bhn));
            float hold = hs[ub * PW + uc];
            float hnew = (1.0f - z) * n + z * hold;
            bool valid = (t < lens_s[ub]);
            __stcg(&hnext[ub * K + uc], valid ? hnew : hold);
            out[(size_t)(ub * T + t) * K + uc] = valid ? hnew : 0.0f;
        }
        grid_barrier(NB);
    }

    // final state must end in hA (consumers read g_hA). If maxT odd, the last
    // write went to hB for this CTA's own columns -> copy them back.
    if ((maxT & 1) && tid < NU) {
        __stcg(&hA[ub * K + uc], __ldcg(&hB[ub * K + uc]));
    }
}

// ---------------------------------------------------------------------------
// 128x128x8 fp32 SGEMM-NT (R8-proven), used for gx_enc / gx_dec.
// ---------------------------------------------------------------------------
template<int KD>
__global__ __launch_bounds__(256, 2) void gemm_nt128(
    float* __restrict__ C,
    const float* __restrict__ Adirect,
    const int*   __restrict__ ids,
    const float* __restrict__ Atab,
    const float* __restrict__ W,
    const float* __restrict__ bias,
    int N,
    const int* __restrict__ skiplen,
    int tper)
{
    __shared__ float As[2][8][128];
    __shared__ float Bs[2][8][128];
    const int tid  = threadIdx.x;
    const int row0 = blockIdx.y * 128, col0 = blockIdx.x * 128;
    const int ty = tid >> 4, tx = tid & 15;

    if (skiplen) {
        int bb = row0 / tper, t0 = row0 % tper;
        if (t0 >= __ldg(&skiplen[bb])) {
            float4 blo = *(const float4*)(bias + col0 + tx * 8);
            float4 bhi = *(const float4*)(bias + col0 + tx * 8 + 4);
            #pragma unroll
            for (int i = 0; i < 8; i++) {
                float* cp = C + (size_t)(row0 + ty * 8 + i) * N + col0 + tx * 8;
                *(float4*)cp = blo; *(float4*)(cp + 4) = bhi;
            }
            return;
        }
    }

    const int lr  = tid >> 1;
    const int lk4 = (tid & 1) * 4;
    const float* arow = ids ? (Atab + (size_t)__ldg(&ids[row0 + lr]) * KD)
                            : (Adirect + (size_t)(row0 + lr) * KD);
    const float* wrow = W + (size_t)(col0 + lr) * KD;

    {
        float4 av = *(const float4*)(arow + lk4);
        float4 wv = *(const float4*)(wrow + lk4);
        As[0][lk4 + 0][lr] = av.x; As[0][lk4 + 1][lr] = av.y;
        As[0][lk4 + 2][lr] = av.z; As[0][lk4 + 3][lr] = av.w;
        Bs[0][lk4 + 0][lr] = wv.x; Bs[0][lk4 + 1][lr] = wv.y;
        Bs[0][lk4 + 2][lr] = wv.z; Bs[0][lk4 + 3][lr] = wv.w;
    }
    __syncthreads();

    float acc[8][8];
    #pragma unroll
    for (int i = 0; i < 8; i++)
        #pragma unroll
        for (int j = 0; j < 8; j++) acc[i][j] = 0.0f;

    constexpr int NK = KD / 8;
    #pragma unroll 1
    for (int kt = 0; kt < NK; kt++) {
        const int cur = kt & 1;
        float4 av2, wv2;
        if (kt + 1 < NK) {
            av2 = *(const float4*)(arow + (kt + 1) * 8 + lk4);
            wv2 = *(const float4*)(wrow + (kt + 1) * 8 + lk4);
        }
        #pragma unroll
        for (int k = 0; k < 8; k++) {
            float a[8], b[8];
            *(float4*)&a[0] = *(const float4*)&As[cur][k][ty * 8];
            *(float4*)&a[4] = *(const float4*)&As[cur][k][ty * 8 + 4];
            *(float4*)&b[0] = *(const float4*)&Bs[cur][k][tx * 8];
            *(float4*)&b[4] = *(const float4*)&Bs[cur][k][tx * 8 + 4];
            #pragma unroll
            for (int i = 0; i < 8; i++)
                #pragma unroll
                for (int j = 0; j < 8; j++)
                    acc[i][j] += a[i] * b[j];
        }
        if (kt + 1 < NK) {
            const int nxt = cur ^ 1;
            As[nxt][lk4 + 0][lr] = av2.x; As[nxt][lk4 + 1][lr] = av2.y;
            As[nxt][lk4 + 2][lr] = av2.z; As[nxt][lk4 + 3][lr] = av2.w;
            Bs[nxt][lk4 + 0][lr] = wv2.x; Bs[nxt][lk4 + 1][lr] = wv2.y;
            Bs[nxt][lk4 + 2][lr] = wv2.z; Bs[nxt][lk4 + 3][lr] = wv2.w;
        }
        __syncthreads();
    }

    float4 blo = *(const float4*)(bias + col0 + tx * 8);
    float4 bhi = *(const float4*)(bias + col0 + tx * 8 + 4);
    #pragma unroll
    for (int i = 0; i < 8; i++) {
        float* cp = C + (size_t)(row0 + ty * 8 + i) * N + col0 + tx * 8;
        float4 v0 = make_float4(acc[i][0] + blo.x, acc[i][1] + blo.y,
                                acc[i][2] + blo.z, acc[i][3] + blo.w);
        float4 v1 = make_float4(acc[i][4] + bhi.x, acc[i][5] + bhi.y,
                                acc[i][6] + bhi.z, acc[i][7] + bhi.w);
        *(float4*)cp = v0; *(float4*)(cp + 4) = v1;
    }
}

// ---------------------------------------------------------------------------
// Split-bf16 prep: W'[n] = [hi | hi | lo], A'[m] = [hi | lo | hi]
// prep_a zeroes rows t >= dec_len[b] (dec_out may be stale there after the
// truncated decoder loop; reference semantics = 0).
// ---------------------------------------------------------------------------
__global__ __launch_bounds__(256) void prep_w(const float* __restrict__ W) {
    int n = blockIdx.x, k = threadIdx.x;
    float x = __ldg(&W[(size_t)n * LL + k]);
    __nv_bfloat16 hi = __float2bfloat16(x);
    __nv_bfloat16 lo = __float2bfloat16(x - __bfloat162float(hi));
    __nv_bfloat16* dst = g_wfc_bf + (size_t)n * 768;
    dst[k] = hi; dst[LL + k] = hi; dst[2 * LL + k] = lo;
}
__global__ __launch_bounds__(256) void prep_a(const int* __restrict__ dec_len) {
    int m = blockIdx.x, k = threadIdx.x;
    int b = m / TDD, t = m % TDD;
    float x = (t < __ldg(&dec_len[b])) ? g_dec_out[(size_t)m * LL + k] : 0.0f;
    __nv_bfloat16 hi = __float2bfloat16(x);
    __nv_bfloat16 lo = __float2bfloat16(x - __bfloat162float(hi));
    __nv_bfloat16* dst = g_abf + (size_t)m * 768;
    dst[k] = hi; dst[LL + k] = lo; dst[2 * LL + k] = hi;
}

// ---------------------------------------------------------------------------
// wmma bf16 GEMM for logits (R13-proven): 128x128 tile, 8 warps, K=768 in 12
// chunks of 64, double-buffered smem, C staging overlaps A/B -> 2 CTAs/SM.
// ---------------------------------------------------------------------------
#define WKC   64
#define NCHNK (768 / WKC)
#define APIT  72
#define CPIT  132
#define SM_A  0
#define SM_B  (2 * 128 * APIT * 2)
#define SM_TOT (2 * SM_B)

__global__ __launch_bounds__(256) void logits_wmma(
    const float* __restrict__ bias,
    const int* __restrict__ dec_len,
    float* __restrict__ C)
{
    extern __shared__ char smc[];
    __nv_bfloat16* As = (__nv_bfloat16*)(smc + SM_A);
    __nv_bfloat16* Bs = (__nv_bfloat16*)(smc + SM_B);
    float*        Cst = (float*)(smc + SM_A);

    const int tid = threadIdx.x;
    const int col0 = blockIdx.x * 128, row0 = blockIdx.y * 128;

    {
        int bb = row0 / TDD, t0 = row0 % TDD;
        if (t0 >= __ldg(&dec_len[bb])) {
            int r = tid >> 1, half = tid & 1;
            float* cp = C + (size_t)(row0 + r) * VV + col0 + half * 64;
            #pragma unroll
            for (int i = 0; i < 16; i++) {
                const float* bp = bias + col0 + half * 64 + i * 4;
                *(float4*)(cp + i * 4) = make_float4(__ldg(bp), __ldg(bp + 1),
                                                     __ldg(bp + 2), __ldg(bp + 3));
            }
            return;
        }
    }

    const int wid = tid >> 5;
    const int wm = wid >> 1;
    const int wn = wid & 1;

    const int lr  = tid >> 1;
    const int seg = (tid & 1) * 32;
    const __nv_bfloat16* Ag = g_abf    + (size_t)(row0 + lr) * 768 + seg;
    const __nv_bfloat16* Bg = g_wfc_bf + (size_t)(col0 + lr) * 768 + seg;

    {
        __nv_bfloat16* ap = As + lr * APIT + seg;
        __nv_bfloat16* bp = Bs + lr * APIT + seg;
        #pragma unroll
        for (int i = 0; i < 4; i++) {
            *(uint4*)(ap + i * 8) = *(const uint4*)(Ag + i * 8);
            *(uint4*)(bp + i * 8) = *(const uint4*)(Bg + i * 8);
        }
    }
    __syncthreads();

    wmma::fragment<wmma::accumulator, 16, 16, 16, float> cf[2][4];
    #pragma unroll
    for (int i = 0; i < 2; i++)
        #pragma unroll
        for (int j = 0; j < 4; j++)
            wmma::fill_fragment(cf[i][j], 0.0f);

    #pragma unroll 1
    for (int ch = 0; ch < NCHNK; ch++) {
        const int cur = ch & 1;
        uint4 apre[4], bpre[4];
        if (ch + 1 < NCHNK) {
            const __nv_bfloat16* Agn = Ag + (ch + 1) * WKC;
            const __nv_bfloat16* Bgn = Bg + (ch + 1) * WKC;
            #pragma unroll
            for (int i = 0; i < 4; i++) {
                apre[i] = *(const uint4*)(Agn + i * 8);
                bpre[i] = *(const uint4*)(Bgn + i * 8);
            }
        }

        const __nv_bfloat16* Ab = As + cur * 128 * APIT;
        const __nv_bfloat16* Bb = Bs + cur * 128 * APIT;
        #pragma unroll
        for (int kk = 0; kk < WKC; kk += 16) {
            wmma::fragment<wmma::matrix_a, 16, 16, 16, __nv_bfloat16, wmma::row_major> af[2];
            wmma::fragment<wmma::matrix_b, 16, 16, 16, __nv_bfloat16, wmma::col_major> bf[4];
            #pragma unroll
            for (int i = 0; i < 2; i++)
                wmma::load_matrix_sync(af[i], Ab + (wm * 32 + i * 16) * APIT + kk, APIT);
            #pragma unroll
            for (int j = 0; j < 4; j++)
                wmma::load_matrix_sync(bf[j], Bb + (wn * 64 + j * 16) * APIT + kk, APIT);
            #pragma unroll
            for (int i = 0; i < 2; i++)
                #pragma unroll
                for (int j = 0; j < 4; j++)
                    wmma::mma_sync(cf[i][j], af[i], bf[j], cf[i][j]);
        }

        if (ch + 1 < NCHNK) {
            const int nxt = cur ^ 1;
            __nv_bfloat16* ap = As + nxt * 128 * APIT + lr * APIT + seg;
            __nv_bfloat16* bp = Bs + nxt * 128 * APIT + lr * APIT + seg;
            #pragma unroll
            for (int i = 0; i < 4; i++) {
                *(uint4*)(ap + i * 8) = apre[i];
                *(uint4*)(bp + i * 8) = bpre[i];
            }
        }
        __syncthreads();
    }

    #pragma unroll
    for (int i = 0; i < 2; i++)
        #pragma unroll
        for (int j = 0; j < 4; j++)
            wmma::store_matrix_sync(Cst + (wm * 32 + i * 16) * CPIT + wn * 64 + j * 16,
                                    cf[i][j], CPIT, wmma::mem_row_major);
    __syncthreads();

    {
        int r = tid >> 1, half = tid & 1;
        const float* sp = Cst + r * CPIT + half * 64;
        float* cp = C + (size_t)(row0 + r) * VV + col0 + half * 64;
        #pragma unroll
        for (int i = 0; i < 16; i++) {
            const float* bp = bias + col0 + half * 64 + i * 4;
            float4 v = *(const float4*)(sp + i * 4);
            *(float4*)(cp + i * 4) = make_float4(v.x + __ldg(bp), v.y + __ldg(bp + 1),
                                                 v.z + __ldg(bp + 2), v.w + __ldg(bp + 3));
        }
    }
}

// ---------------------------------------------------------------------------
// Padding no-op (keeps gru_enc at my 4th launch = ncu profiled slot)
// ---------------------------------------------------------------------------
__global__ void noop_a() {}

// ---------------------------------------------------------------------------
// Attention scores (R1-proven)
// ---------------------------------------------------------------------------
__global__ __launch_bounds__(256) void attn_scores() {
    const int b = blockIdx.x, tid = threadIdx.x;
    __shared__ float last_s[HH], first_s[HH];
    for (int i = tid; i < HH; i += 256) {
        last_s[i]  = g_hA[b * HH + i];
        first_s[i] = g_enc_out[((size_t)b * TEE + 0) * HH + i];
    }
    __syncthreads();
    const int w = tid >> 5, lane = tid & 31;
    for (int t = w; t < TEE; t += 8) {
        const float* orow = g_enc_out + ((size_t)(b * TEE + t)) * HH;
        float af = 0.0f, ab = 0.0f;
        #pragma unroll 4
        for (int i = lane; i < HH; i += 32) {
            float v = orow[i];
            af += v * last_s[i];
            ab += v * first_s[i];
        }
        #pragma unroll
        for (int o = 16; o > 0; o >>= 1) {
            af += __shfl_xor_sync(0xffffffffu, af, o);
            ab += __shfl_xor_sync(0xffffffffu, ab, o);
        }
        if (lane == 0) { g_sfw[b * TEE + t] = af; g_sbw[b * TEE + t] = ab; }
    }
}

__device__ __forceinline__ float blk_reduce(float v, float* red, bool ismax) {
    #pragma unroll
    for (int o = 16; o > 0; o >>= 1) {
        float u = __shfl_xor_sync(0xffffffffu, v, o);
        v = ismax ? fmaxf(v, u) : (v + u);
    }
    int w = threadIdx.x >> 5;
    if ((threadIdx.x & 31) == 0) red[w] = v;
    __syncthreads();
    if (threadIdx.x == 0) {
        float a = red[0];
        for (int i = 1; i < 8; i++) a = ismax ? fmaxf(a, red[i]) : (a + red[i]);
        red[0] = a;
    }
    __syncthreads();
    float r = red[0];
    __syncthreads();
    return r;
}

// ---------------------------------------------------------------------------
// Masked dual softmax + semantic pooling + h_enc assembly.
// Pooling loop bounded by len: alpha beyond len is exactly 0, and enc_out
// rows beyond max(enc_len) may be stale/uninitialized after loop truncation.
// ---------------------------------------------------------------------------
__global__ __launch_bounds__(256) void softmax_semantic(const int* __restrict__ enc_len) {
    const int b = blockIdx.x, tid = threadIdx.x;
    const int len = enc_len[b];
    __shared__ float sa[TEE];
    __shared__ float red[8];

    float v0 = (tid       < len) ? g_sfw[b * TEE + tid]       : -1e30f;
    float v1 = (tid + 256 < len) ? g_sfw[b * TEE + tid + 256] : -1e30f;
    float M = blk_reduce(fmaxf(v0, v1), red, true);
    float e0 = (tid       < len) ? expf(v0 - M) : 0.0f;
    float e1 = (tid + 256 < len) ? expf(v1 - M) : 0.0f;
    float S = blk_reduce(e0 + e1, red, false);
    float inv = 0.5f / S;
    sa[tid] = e0 * inv; sa[tid + 256] = e1 * inv;
    __syncthreads();

    v0 = (tid       < len) ? g_sbw[b * TEE + tid]       : -1e30f;
    v1 = (tid + 256 < len) ? g_sbw[b * TEE + tid + 256] : -1e30f;
    M = blk_reduce(fmaxf(v0, v1), red, true);
    e0 = (tid       < len) ? expf(v0 - M) : 0.0f;
    e1 = (tid + 256 < len) ? expf(v1 - M) : 0.0f;
    S = blk_reduce(e0 + e1, red, false);
    inv = 0.5f / S;
    sa[tid] += e0 * inv; sa[tid + 256] += e1 * inv;
    __syncthreads();

    for (int d = tid; d < HH; d += 256) {
        float acc = 0.0f;
        #pragma unroll 4
        for (int t = 0; t < len; t++)
            acc += sa[t] * g_enc_out[((size_t)(b * TEE + t)) * HH + d];
        g_henc[b * 2 * HH + HH + d] = acc;
        g_henc[b * 2 * HH + d] = g_hA[b * HH + d];
    }
}

// ---------------------------------------------------------------------------
// Latent head (R1-proven)
// ---------------------------------------------------------------------------
__global__ __launch_bounds__(256) void latent_head(
    const float* __restrict__ W_mu, const float* __restrict__ b_mu,
    const float* __restrict__ W_ls, const float* __restrict__ b_ls,
    const float* __restrict__ noise, const int* __restrict__ dec_len,
    float* __restrict__ outbuf)
{
    const int b = blockIdx.x, tid = threadIdx.x;
    __shared__ float he[2 * HH];
    __shared__ float muv[LL], lsv[LL];
    for (int i = tid; i < 2 * HH; i += 256) he[i] = g_henc[b * 2 * HH + i];
    __syncthreads();

    const int w = tid >> 5, lane = tid & 31;
    for (int o = w; o < 2 * LL; o += 8) {
        const float* Wr; float bia; int j;
        if (o < LL) { j = o;      Wr = W_mu + (size_t)j * (2 * HH); bia = b_mu[j]; }
        else        { j = o - LL; Wr = W_ls + (size_t)j * (2 * HH); bia = b_ls[j]; }
        float acc = 0.0f;
        #pragma unroll 4
        for (int k = lane; k < 2 * HH; k += 32) acc += Wr[k] * he[k];
        #pragma unroll
        for (int s = 16; s > 0; s >>= 1) acc += __shfl_xor_sync(0xffffffffu, acc, s);
        if (lane == 0) { if (o < LL) muv[j] = acc + bia; else lsv[j] = acc + bia; }
    }
    __syncthreads();

    if (tid < LL) {
        float mu = muv[tid];
        float sg = expf(lsv[tid]);
        float zz = mu + sg * noise[b * LL + tid];
        g_z[b * LL + tid] = zz;
        outbuf[OFF_MU + b * LL + tid] = mu;
        outbuf[OFF_SG + b * LL + tid] = sg;
    }
    if (b == 0 && tid == 0) {
        int m = 0;
        for (int i = 0; i < BB; i++) m = max(m, dec_len[i]);
        outbuf[OFF_ML] = (float)m;
    }
}

// ---------------------------------------------------------------------------
// Launch (identical order to R13)
// ---------------------------------------------------------------------------
extern "C" void kernel_launch(void* const* d_in, const int* in_sizes, int n_in,
                              void* d_out, int out_size) {
    const float* emb     = (const float*)d_in[0];
    const float* enc_Wih = (const float*)d_in[1];
    const float* enc_Whh = (const float*)d_in[2];
    const float* enc_bih = (const float*)d_in[3];
    const float* enc_bhh = (const float*)d_in[4];
    const float* dec_Wih = (const float*)d_in[5];
    const float* dec_Whh = (const float*)d_in[6];
    const float* dec_bih = (const float*)d_in[7];
    const float* dec_bhh = (const float*)d_in[8];
    const float* W_mu    = (const float*)d_in[9];
    const float* b_mu    = (const float*)d_in[10];
    const float* W_ls    = (const float*)d_in[11];
    const float* b_ls    = (const float*)d_in[12];
    const float* W_fc    = (const float*)d_in[13];
    const float* b_fc    = (const float*)d_in[14];
    const float* noise   = (const float*)d_in[15];
    const int*   enc_ids = (const int*)d_in[16];
    const int*   enc_len = (const int*)d_in[17];
    const int*   dec_ids = (const int*)d_in[18];
    const int*   dec_len = (const int*)d_in[19];
    float* outbuf = (float*)d_out;

    float *p_gx_enc, *p_enc_out, *p_gx_dec, *p_dec_out, *p_hA, *p_hB, *p_z;
    cudaGetSymbolAddress((void**)&p_gx_enc, g_gx_enc);
    cudaGetSymbolAddress((void**)&p_enc_out, g_enc_out);
    cudaGetSymbolAddress((void**)&p_gx_dec, g_gx_dec);
    cudaGetSymbolAddress((void**)&p_dec_out, g_dec_out);
    cudaGetSymbolAddress((void**)&p_hA, g_hA);
    cudaGetSymbolAddress((void**)&p_hB, g_hB);
    cudaGetSymbolAddress((void**)&p_z, g_z);

    cudaFuncSetAttribute(logits_wmma, cudaFuncAttributeMaxDynamicSharedMemorySize, SM_TOT);

    // 1) gx_enc = emb[enc_ids] @ enc_Wih^T + bih   [8192 x 1536, K=512]
    gemm_nt128<512><<<dim3(1536 / 128, (BB * TEE) / 128), 256>>>(
        p_gx_enc, nullptr, enc_ids, emb, enc_Wih, enc_bih, 3 * HH, nullptr, 1);

    // 2) W_fc -> split-bf16 W' (independent; runs early)
    prep_w<<<VV, 256>>>(W_fc);

    // 3) padding no-op
    noop_a<<<1, 32>>>();

    // 4) encoder GRU (persistent, truncated at max(enc_len))  <-- profiled slot
    gru_persist<HH, 4, 8><<<HH / 4, 512>>>(
        p_gx_enc, enc_Whh, enc_bhh, enc_len, nullptr, p_hA, p_hB, p_enc_out, TEE);

    // 5-7) attention + latent path
    attn_scores<<<BB, 256>>>();
    softmax_semantic<<<BB, 256>>>(enc_len);
    latent_head<<<BB, 256>>>(W_mu, b_mu, W_ls, b_ls, noise, dec_len, outbuf);

    // 8) gx_dec = emb[dec_ids] @ dec_Wih^T + bih   [4096 x 768, K=512]
    gemm_nt128<512><<<dim3((3 * LL) / 128, (BB * TDD) / 128), 256>>>(
        p_gx_dec, nullptr, dec_ids, emb, dec_Wih, dec_bih, 3 * LL, nullptr, 1);

    // 9) decoder GRU (persistent, truncated at max(dec_len)), h0 = z
    gru_persist<LL, 2, 8><<<LL / 2, 512>>>(
        p_gx_dec, dec_Whh, dec_bhh, dec_len, p_z, p_hA, p_hB, p_dec_out, TDD);

    // 10) dec_out -> split-bf16 A' (zeros rows t >= dec_len[b])
    prep_a<<<BB * TDD, 256>>>(dec_len);

    // 11) logits = A' @ W'^T + b_fc  (wmma bf16, K=768, zero-tile skip)
    logits_wmma<<<dim3(VV / 128, (BB * TDD) / 128), 256, SM_TOT>>>(
        b_fc, dec_len, outbuf);
}

// round 15
// speedup vs baseline: 1.4193x; 1.0349x over previous
#include <cuda_runtime.h>
#include <cuda_bf16.h>
#include <mma.h>
#include <math.h>
#include <stdint.h>

using namespace nvcuda;

// Problem dims
#define VV 32000
#define HH 512
#define LL 256
#define BB 16
#define TEE 512
#define TDD 256

// Output layout: [logits (B*TD*V)][dec_max_len (1)][mu (B*L)][sigma (B*L)]
#define OFF_ML  ((size_t)BB * TDD * VV)
#define OFF_MU  (OFF_ML + 1)
#define OFF_SG  (OFF_MU + (size_t)BB * LL)

// ---------------------------------------------------------------------------
// Scratch (static device globals; no allocation allowed)
// ---------------------------------------------------------------------------
__device__ float g_gx_enc[(size_t)BB * TEE * 3 * HH];   // 50.3 MB
__device__ float g_enc_out[(size_t)BB * TEE * HH];      // 16.8 MB
__device__ float g_gx_dec[(size_t)BB * TDD * 3 * LL];   // 12.6 MB
__device__ float g_dec_out[(size_t)BB * TDD * LL];      //  4.2 MB
__device__ float g_hA[BB * HH];
__device__ float g_hB[BB * HH];
__device__ float g_sfw[BB * TEE];
__device__ float g_sbw[BB * TEE];
__device__ float g_henc[BB * 2 * HH];
__device__ float g_z[BB * LL];
__device__ unsigned g_bar_count;
__device__ volatile unsigned g_bar_gen;

// Split-bf16 operands for the logits GEMM (K-concat: [hi|lo|hi] x [hi|hi|lo])
__device__ __nv_bfloat16 g_wfc_bf[(size_t)VV * 768];        // 49.2 MB
__device__ __nv_bfloat16 g_abf[(size_t)BB * TDD * 768];     //  6.3 MB

// ---------------------------------------------------------------------------
// Grid-wide barrier (R1/R4-proven flat version; all CTAs co-resident)
// ---------------------------------------------------------------------------
__device__ __forceinline__ void grid_barrier(unsigned nb) {
    __threadfence();
    __syncthreads();
    if (threadIdx.x == 0) {
        unsigned gen = g_bar_gen;
        unsigned arrived = atomicAdd(&g_bar_count, 1u);
        if (arrived == nb - 1) {
            g_bar_count = 0;
            __threadfence();
            g_bar_gen = gen + 1;
        } else {
            while (g_bar_gen == gen) { }
        }
        __threadfence();
    }
    __syncthreads();
}

__device__ __forceinline__ float sigmoidf_(float x) { return 1.0f / (1.0f + expf(-x)); }
__device__ __forceinline__ float dot4_(float4 w, float4 h) {
    return w.x * h.x + w.y * h.y + w.z * h.z + w.w * h.w;
}

// ---------------------------------------------------------------------------
// Persistent GRU (R14-proven): 512 threads, 3-gate-fused dot, NS-way K-split,
// loop truncated at maxT = max(lens), parity copy keeps final state in hA.
// ---------------------------------------------------------------------------
template<int K, int CW, int NS>
__global__ __launch_bounds__(512, 1) void gru_persist(
    const float* __restrict__ gx,
    const float* __restrict__ Whh,
    const float* __restrict__ bhh,
    const int*   __restrict__ lens,
    const float* __restrict__ h0,
    float* hA, float* hB,
    float* __restrict__ out,
    int T)
{
    constexpr int PW = K + 4;
    constexpr int NC = 16 * CW * NS;
    constexpr int NU = 16 * CW;
    constexpr int KQ = K / NS;
    __shared__ float hs[16 * PW];
    __shared__ float pex[3 * CW * NS * 16];
    __shared__ int   lens_s[16];
    __shared__ int   maxT_s;

    const int tid = threadIdx.x;
    const int bx  = blockIdx.x;
    const unsigned NB = gridDim.x;

    const float4 *w0p = nullptr, *w1p = nullptr, *w2p = nullptr;
    int db = tid & 15;
    int q  = (tid >> 4) % NS;
    int cl = tid / (16 * NS);
    if (tid < NC) {
        int dc = bx * CW + cl;
        w0p = (const float4*)(Whh + (size_t)(0 * K + dc) * K + q * KQ);
        w1p = (const float4*)(Whh + (size_t)(1 * K + dc) * K + q * KQ);
        w2p = (const float4*)(Whh + (size_t)(2 * K + dc) * K + q * KQ);
    }
    int ub = tid & 15, ucl = tid >> 4;
    int uc = bx * CW + ucl;
    float bhr = 0.f, bhz = 0.f, bhn = 0.f;
    if (tid < NU) {
        bhr = bhh[uc]; bhz = bhh[K + uc]; bhn = bhh[2 * K + uc];
    }

    if (tid < 16) lens_s[tid] = lens[tid];
    if (tid < NU) {
        float v = h0 ? h0[ub * K + uc] : 0.0f;
        __stcg(&hA[ub * K + uc], v);
    }
    __syncthreads();
    if (tid == 0) {
        int m = 0;
        #pragma unroll
        for (int i = 0; i < 16; i++) m = max(m, lens_s[i]);
        maxT_s = m;
    }
    grid_barrier(NB);
    const int maxT = maxT_s;

    for (int t = 0; t < maxT; t++) {
        float* hcur  = (t & 1) ? hB : hA;
        float* hnext = (t & 1) ? hA : hB;

        float gxr = 0.f, gxz = 0.f, gxn = 0.f;
        if (tid < NU) {
            const float* gxp = gx + (size_t)(ub * T + t) * (3 * K);
            gxr = __ldg(gxp + uc);
            gxz = __ldg(gxp + K + uc);
            gxn = __ldg(gxp + 2 * K + uc);
        }

        const float4* hc4 = (const float4*)hcur;
        #pragma unroll
        for (int i = tid; i < 16 * K / 4; i += 512) {
            float4 v = __ldcg(hc4 + i);
            int b = i / (K / 4), kq = i % (K / 4);
            *(float4*)&hs[b * PW + 4 * kq] = v;
        }
        __syncthreads();

        if (tid < NC) {
            const float4* hp = (const float4*)&hs[db * PW + q * KQ];
            float a00 = 0.f, a01 = 0.f, a10 = 0.f, a11 = 0.f, a20 = 0.f, a21 = 0.f;
            #pragma unroll
            for (int kk = 0; kk < KQ / 8; kk++) {
                float4 hv0 = hp[2 * kk + 0];
                float4 hv1 = hp[2 * kk + 1];
                float4 wa0 = __ldg(w0p + 2 * kk + 0);
                float4 wa1 = __ldg(w0p + 2 * kk + 1);
                float4 wb0 = __ldg(w1p + 2 * kk + 0);
                float4 wb1 = __ldg(w1p + 2 * kk + 1);
                float4 wc0 = __ldg(w2p + 2 * kk + 0);
                float4 wc1 = __ldg(w2p + 2 * kk + 1);
                a00 += dot4_(wa0, hv0); a01 += dot4_(wa1, hv1);
                a10 += dot4_(wb0, hv0); a11 += dot4_(wb1, hv1);
                a20 += dot4_(wc0, hv0); a21 += dot4_(wc1, hv1);
            }
            pex[((0 * CW + cl) * NS + q) * 16 + db] = a00 + a01;
            pex[((1 * CW + cl) * NS + q) * 16 + db] = a10 + a11;
            pex[((2 * CW + cl) * NS + q) * 16 + db] = a20 + a21;
        }
        __syncthreads();

        if (tid < NU) {
            float ghr = 0.f, ghz = 0.f, ghn = 0.f;
            #pragma unroll
            for (int qq = 0; qq < NS; qq++) {
                ghr += pex[((0 * CW + ucl) * NS + qq) * 16 + ub];
                ghz += pex[((1 * CW + ucl) * NS + qq) * 16 + ub];
                ghn += pex[((2 * CW + ucl) * NS + qq) * 16 + ub];
            }
            float r = sigmoidf_(gxr + ghr + bhr);
            float z = sigmoidf_(gxz + ghz + bhz);
            float n = tanhf   (gxn + r * (ghn + bhn));
            float hold = hs[ub * PW + uc];
            float hnew = (1.0f - z) * n + z * hold;
            bool valid = (t < lens_s[ub]);
            __stcg(&hnext[ub * K + uc], valid ? hnew : hold);
            out[(size_t)(ub * T + t) * K + uc] = valid ? hnew : 0.0f;
        }
        grid_barrier(NB);
    }

    if ((maxT & 1) && tid < NU) {
        __stcg(&hA[ub * K + uc], __ldcg(&hB[ub * K + uc]));
    }
}

// ---------------------------------------------------------------------------
// 128x128x8 fp32 SGEMM-NT (R8-proven core). NEW skip semantics: tiles whose
// entire M-range has t >= skiplen[b] are DISCARDED (no compute, no write) —
// their outputs are only ever read-and-discarded by the truncated GRU.
// ---------------------------------------------------------------------------
template<int KD>
__global__ __launch_bounds__(256, 2) void gemm_nt128(
    float* __restrict__ C,
    const float* __restrict__ Adirect,
    const int*   __restrict__ ids,
    const float* __restrict__ Atab,
    const float* __restrict__ W,
    const float* __restrict__ bias,
    int N,
    const int* __restrict__ skiplen,
    int tper)
{
    __shared__ float As[2][8][128];
    __shared__ float Bs[2][8][128];
    const int tid  = threadIdx.x;
    const int row0 = blockIdx.y * 128, col0 = blockIdx.x * 128;
    const int ty = tid >> 4, tx = tid & 15;

    if (skiplen) {   // whole tile dead -> skip entirely (values never consumed)
        int bb = row0 / tper, t0 = row0 % tper;
        if (t0 >= __ldg(&skiplen[bb])) return;
    }

    const int lr  = tid >> 1;
    const int lk4 = (tid & 1) * 4;
    const float* arow = ids ? (Atab + (size_t)__ldg(&ids[row0 + lr]) * KD)
                            : (Adirect + (size_t)(row0 + lr) * KD);
    const float* wrow = W + (size_t)(col0 + lr) * KD;

    {
        float4 av = *(const float4*)(arow + lk4);
        float4 wv = *(const float4*)(wrow + lk4);
        As[0][lk4 + 0][lr] = av.x; As[0][lk4 + 1][lr] = av.y;
        As[0][lk4 + 2][lr] = av.z; As[0][lk4 + 3][lr] = av.w;
        Bs[0][lk4 + 0][lr] = wv.x; Bs[0][lk4 + 1][lr] = wv.y;
        Bs[0][lk4 + 2][lr] = wv.z; Bs[0][lk4 + 3][lr] = wv.w;
    }
    __syncthreads();

    float acc[8][8];
    #pragma unroll
    for (int i = 0; i < 8; i++)
        #pragma unroll
        for (int j = 0; j < 8; j++) acc[i][j] = 0.0f;

    constexpr int NK = KD / 8;
    #pragma unroll 1
    for (int kt = 0; kt < NK; kt++) {
        const int cur = kt & 1;
        float4 av2, wv2;
        if (kt + 1 < NK) {
            av2 = *(const float4*)(arow + (kt + 1) * 8 + lk4);
            wv2 = *(const float4*)(wrow + (kt + 1) * 8 + lk4);
        }
        #pragma unroll
        for (int k = 0; k < 8; k++) {
            float a[8], b[8];
            *(float4*)&a[0] = *(const float4*)&As[cur][k][ty * 8];
            *(float4*)&a[4] = *(const float4*)&As[cur][k][ty * 8 + 4];
            *(float4*)&b[0] = *(const float4*)&Bs[cur][k][tx * 8];
            *(float4*)&b[4] = *(const float4*)&Bs[cur][k][tx * 8 + 4];
            #pragma unroll
            for (int i = 0; i < 8; i++)
                #pragma unroll
                for (int j = 0; j < 8; j++)
                    acc[i][j] += a[i] * b[j];
        }
        if (kt + 1 < NK) {
            const int nxt = cur ^ 1;
            As[nxt][lk4 + 0][lr] = av2.x; As[nxt][lk4 + 1][lr] = av2.y;
            As[nxt][lk4 + 2][lr] = av2.z; As[nxt][lk4 + 3][lr] = av2.w;
            Bs[nxt][lk4 + 0][lr] = wv2.x; Bs[nxt][lk4 + 1][lr] = wv2.y;
            Bs[nxt][lk4 + 2][lr] = wv2.z; Bs[nxt][lk4 + 3][lr] = wv2.w;
        }
        __syncthreads();
    }

    float4 blo = *(const float4*)(bias + col0 + tx * 8);
    float4 bhi = *(const float4*)(bias + col0 + tx * 8 + 4);
    #pragma unroll
    for (int i = 0; i < 8; i++) {
        float* cp = C + (size_t)(row0 + ty * 8 + i) * N + col0 + tx * 8;
        float4 v0 = make_float4(acc[i][0] + blo.x, acc[i][1] + blo.y,
                                acc[i][2] + blo.z, acc[i][3] + blo.w);
        float4 v1 = make_float4(acc[i][4] + bhi.x, acc[i][5] + bhi.y,
                                acc[i][6] + bhi.z, acc[i][7] + bhi.w);
        *(float4*)cp = v0; *(float4*)(cp + 4) = v1;
    }
}

// ---------------------------------------------------------------------------
// Split-bf16 prep: W'[n] = [hi | hi | lo], A'[m] = [hi | lo | hi]
// prep_a zeroes rows t >= dec_len[b] (reference semantics = 0 there).
// ---------------------------------------------------------------------------
__global__ __launch_bounds__(256) void prep_w(const float* __restrict__ W) {
    int n = blockIdx.x, k = threadIdx.x;
    float x = __ldg(&W[(size_t)n * LL + k]);
    __nv_bfloat16 hi = __float2bfloat16(x);
    __nv_bfloat16 lo = __float2bfloat16(x - __bfloat162float(hi));
    __nv_bfloat16* dst = g_wfc_bf + (size_t)n * 768;
    dst[k] = hi; dst[LL + k] = hi; dst[2 * LL + k] = lo;
}
__global__ __launch_bounds__(256) void prep_a(const int* __restrict__ dec_len) {
    int m = blockIdx.x, k = threadIdx.x;
    int b = m / TDD, t = m % TDD;
    float x = (t < __ldg(&dec_len[b])) ? g_dec_out[(size_t)m * LL + k] : 0.0f;
    __nv_bfloat16 hi = __float2bfloat16(x);
    __nv_bfloat16 lo = __float2bfloat16(x - __bfloat162float(hi));
    __nv_bfloat16* dst = g_abf + (size_t)m * 768;
    dst[k] = hi; dst[LL + k] = lo; dst[2 * LL + k] = hi;
}

// ---------------------------------------------------------------------------
// wmma bf16 GEMM for logits (R13-proven): 128x128 tile, 8 warps, K=768 in 12
// chunks of 64, double-buffered smem, C staging overlaps A/B -> 2 CTAs/SM.
// ---------------------------------------------------------------------------
#define WKC   64
#define NCHNK (768 / WKC)
#define APIT  72
#define CPIT  132
#define SM_A  0
#define SM_B  (2 * 128 * APIT * 2)
#define SM_TOT (2 * SM_B)

__global__ __launch_bounds__(256) void logits_wmma(
    const float* __restrict__ bias,
    const int* __restrict__ dec_len,
    float* __restrict__ C)
{
    extern __shared__ char smc[];
    __nv_bfloat16* As = (__nv_bfloat16*)(smc + SM_A);
    __nv_bfloat16* Bs = (__nv_bfloat16*)(smc + SM_B);
    float*        Cst = (float*)(smc + SM_A);

    const int tid = threadIdx.x;
    const int col0 = blockIdx.x * 128, row0 = blockIdx.y * 128;

    {
        int bb = row0 / TDD, t0 = row0 % TDD;
        if (t0 >= __ldg(&dec_len[bb])) {
            int r = tid >> 1, half = tid & 1;
            float* cp = C + (size_t)(row0 + r) * VV + col0 + half * 64;
            #pragma unroll
            for (int i = 0; i < 16; i++) {
                const float* bp = bias + col0 + half * 64 + i * 4;
                *(float4*)(cp + i * 4) = make_float4(__ldg(bp), __ldg(bp + 1),
                                                     __ldg(bp + 2), __ldg(bp + 3));
            }
            return;
        }
    }

    const int wid = tid >> 5;
    const int wm = wid >> 1;
    const int wn = wid & 1;

    const int lr  = tid >> 1;
    const int seg = (tid & 1) * 32;
    const __nv_bfloat16* Ag = g_abf    + (size_t)(row0 + lr) * 768 + seg;
    const __nv_bfloat16* Bg = g_wfc_bf + (size_t)(col0 + lr) * 768 + seg;

    {
        __nv_bfloat16* ap = As + lr * APIT + seg;
        __nv_bfloat16* bp = Bs + lr * APIT + seg;
        #pragma unroll
        for (int i = 0; i < 4; i++) {
            *(uint4*)(ap + i * 8) = *(const uint4*)(Ag + i * 8);
            *(uint4*)(bp + i * 8) = *(const uint4*)(Bg + i * 8);
        }
    }
    __syncthreads();

    wmma::fragment<wmma::accumulator, 16, 16, 16, float> cf[2][4];
    #pragma unroll
    for (int i = 0; i < 2; i++)
        #pragma unroll
        for (int j = 0; j < 4; j++)
            wmma::fill_fragment(cf[i][j], 0.0f);

    #pragma unroll 1
    for (int ch = 0; ch < NCHNK; ch++) {
        const int cur = ch & 1;
        uint4 apre[4], bpre[4];
        if (ch + 1 < NCHNK) {
            const __nv_bfloat16* Agn = Ag + (ch + 1) * WKC;
            const __nv_bfloat16* Bgn = Bg + (ch + 1) * WKC;
            #pragma unroll
            for (int i = 0; i < 4; i++) {
                apre[i] = *(const uint4*)(Agn + i * 8);
                bpre[i] = *(const uint4*)(Bgn + i * 8);
            }
        }

        const __nv_bfloat16* Ab = As + cur * 128 * APIT;
        const __nv_bfloat16* Bb = Bs + cur * 128 * APIT;
        #pragma unroll
        for (int kk = 0; kk < WKC; kk += 16) {
            wmma::fragment<wmma::matrix_a, 16, 16, 16, __nv_bfloat16, wmma::row_major> af[2];
            wmma::fragment<wmma::matrix_b, 16, 16, 16, __nv_bfloat16, wmma::col_major> bf[4];
            #pragma unroll
            for (int i = 0; i < 2; i++)
                wmma::load_matrix_sync(af[i], Ab + (wm * 32 + i * 16) * APIT + kk, APIT);
            #pragma unroll
            for (int j = 0; j < 4; j++)
                wmma::load_matrix_sync(bf[j], Bb + (wn * 64 + j * 16) * APIT + kk, APIT);
            #pragma unroll
            for (int i = 0; i < 2; i++)
                #pragma unroll
                for (int j = 0; j < 4; j++)
                    wmma::mma_sync(cf[i][j], af[i], bf[j], cf[i][j]);
        }

        if (ch + 1 < NCHNK) {
            const int nxt = cur ^ 1;
            __nv_bfloat16* ap = As + nxt * 128 * APIT + lr * APIT + seg;
            __nv_bfloat16* bp = Bs + nxt * 128 * APIT + lr * APIT + seg;
            #pragma unroll
            for (int i = 0; i < 4; i++) {
                *(uint4*)(ap + i * 8) = apre[i];
                *(uint4*)(bp + i * 8) = bpre[i];
            }
        }
        __syncthreads();
    }

    #pragma unroll
    for (int i = 0; i < 2; i++)
        #pragma unroll
        for (int j = 0; j < 4; j++)
            wmma::store_matrix_sync(Cst + (wm * 32 + i * 16) * CPIT + wn * 64 + j * 16,
                                    cf[i][j], CPIT, wmma::mem_row_major);
    __syncthreads();

    {
        int r = tid >> 1, half = tid & 1;
        const float* sp = Cst + r * CPIT + half * 64;
        float* cp = C + (size_t)(row0 + r) * VV + col0 + half * 64;
        #pragma unroll
        for (int i = 0; i < 16; i++) {
            const float* bp = bias + col0 + half * 64 + i * 4;
            float4 v = *(const float4*)(sp + i * 4);
            *(float4*)(cp + i * 4) = make_float4(v.x + __ldg(bp), v.y + __ldg(bp + 1),
                                                 v.z + __ldg(bp + 2), v.w + __ldg(bp + 3));
        }
    }
}

// ---------------------------------------------------------------------------
// Padding no-op (keeps gru_enc at my 4th launch = ncu profiled slot)
// ---------------------------------------------------------------------------
__global__ void noop_a() {}

// ---------------------------------------------------------------------------
// Attention scores, bounded at len (scores beyond len are masked downstream;
// enc_out there is stale after loop truncation).
// ---------------------------------------------------------------------------
__global__ __launch_bounds__(256) void attn_scores(const int* __restrict__ enc_len) {
    const int b = blockIdx.x, tid = threadIdx.x;
    const int len = __ldg(&enc_len[b]);
    __shared__ float last_s[HH], first_s[HH];
    for (int i = tid; i < HH; i += 256) {
        last_s[i]  = g_hA[b * HH + i];
        first_s[i] = g_enc_out[((size_t)b * TEE + 0) * HH + i];
    }
    __syncthreads();
    const int w = tid >> 5, lane = tid & 31;
    for (int t = w; t < len; t += 8) {
        const float* orow = g_enc_out + ((size_t)(b * TEE + t)) * HH;
        float af = 0.0f, ab = 0.0f;
        #pragma unroll 4
        for (int i = lane; i < HH; i += 32) {
            float v = orow[i];
            af += v * last_s[i];
            ab += v * first_s[i];
        }
        #pragma unroll
        for (int o = 16; o > 0; o >>= 1) {
            af += __shfl_xor_sync(0xffffffffu, af, o);
            ab += __shfl_xor_sync(0xffffffffu, ab, o);
        }
        if (lane == 0) { g_sfw[b * TEE + t] = af; g_sbw[b * TEE + t] = ab; }
    }
}

__device__ __forceinline__ float blk_reduce(float v, float* red, bool ismax) {
    #pragma unroll
    for (int o = 16; o > 0; o >>= 1) {
        float u = __shfl_xor_sync(0xffffffffu, v, o);
        v = ismax ? fmaxf(v, u) : (v + u);
    }
    int w = threadIdx.x >> 5;
    if ((threadIdx.x & 31) == 0) red[w] = v;
    __syncthreads();
    if (threadIdx.x == 0) {
        float a = red[0];
        for (int i = 1; i < 8; i++) a = ismax ? fmaxf(a, red[i]) : (a + red[i]);
        red[0] = a;
    }
    __syncthreads();
    float r = red[0];
    __syncthreads();
    return r;
}

// ---------------------------------------------------------------------------
// Masked dual softmax + semantic pooling + h_enc assembly (R14-proven).
// ---------------------------------------------------------------------------
__global__ __launch_bounds__(256) void softmax_semantic(const int* __restrict__ enc_len) {
    const int b = blockIdx.x, tid = threadIdx.x;
    const int len = enc_len[b];
    __shared__ float sa[TEE];
    __shared__ float red[8];

    float v0 = (tid       < len) ? g_sfw[b * TEE + tid]       : -1e30f;
    float v1 = (tid + 256 < len) ? g_sfw[b * TEE + tid + 256] : -1e30f;
    float M = blk_reduce(fmaxf(v0, v1), red, true);
    float e0 = (tid       < len) ? expf(v0 - M) : 0.0f;
    float e1 = (tid + 256 < len) ? expf(v1 - M) : 0.0f;
    float S = blk_reduce(e0 + e1, red, false);
    float inv = 0.5f / S;
    sa[tid] = e0 * inv; sa[tid + 256] = e1 * inv;
    __syncthreads();

    v0 = (tid       < len) ? g_sbw[b * TEE + tid]       : -1e30f;
    v1 = (tid + 256 < len) ? g_sbw[b * TEE + tid + 256] : -1e30f;
    M = blk_reduce(fmaxf(v0, v1), red, true);
    e0 = (tid       < len) ? expf(v0 - M) : 0.0f;
    e1 = (tid + 256 < len) ? expf(v1 - M) : 0.0f;
    S = blk_reduce(e0 + e1, red, false);
    inv = 0.5f / S;
    sa[tid] += e0 * inv; sa[tid + 256] += e1 * inv;
    __syncthreads();

    for (int d = tid; d < HH; d += 256) {
        float acc = 0.0f;
        #pragma unroll 4
        for (int t = 0; t < len; t++)
            acc += sa[t] * g_enc_out[((size_t)(b * TEE + t)) * HH + d];
        g_henc[b * 2 * HH + HH + d] = acc;
        g_henc[b * 2 * HH + d] = g_hA[b * HH + d];
    }
}

// ---------------------------------------------------------------------------
// Latent head (R1-proven)
// ---------------------------------------------------------------------------
__global__ __launch_bounds__(256) void latent_head(
    const float* __restrict__ W_mu, const float* __restrict__ b_mu,
    const float* __restrict__ W_ls, const float* __restrict__ b_ls,
    const float* __restrict__ noise, const int* __restrict__ dec_len,
    float* __restrict__ outbuf)
{
    const int b = blockIdx.x, tid = threadIdx.x;
    __shared__ float he[2 * HH];
    __shared__ float muv[LL], lsv[LL];
    for (int i = tid; i < 2 * HH; i += 256) he[i] = g_henc[b * 2 * HH + i];
    __syncthreads();

    const int w = tid >> 5, lane = tid & 31;
    for (int o = w; o < 2 * LL; o += 8) {
        const float* Wr; float bia; int j;
        if (o < LL) { j = o;      Wr = W_mu + (size_t)j * (2 * HH); bia = b_mu[j]; }
        else        { j = o - LL; Wr = W_ls + (size_t)j * (2 * HH); bia = b_ls[j]; }
        float acc = 0.0f;
        #pragma unroll 4
        for (int k = lane; k < 2 * HH; k += 32) acc += Wr[k] * he[k];
        #pragma unroll
        for (int s = 16; s > 0; s >>= 1) acc += __shfl_xor_sync(0xffffffffu, acc, s);
        if (lane == 0) { if (o < LL) muv[j] = acc + bia; else lsv[j] = acc + bia; }
    }
    __syncthreads();

    if (tid < LL) {
        float mu = muv[tid];
        float sg = expf(lsv[tid]);
        float zz = mu + sg * noise[b * LL + tid];
        g_z[b * LL + tid] = zz;
        outbuf[OFF_MU + b * LL + tid] = mu;
        outbuf[OFF_SG + b * LL + tid] = sg;
    }
    if (b == 0 && tid == 0) {
        int m = 0;
        for (int i = 0; i < BB; i++) m = max(m, dec_len[i]);
        outbuf[OFF_ML] = (float)m;
    }
}

// ---------------------------------------------------------------------------
// Launch (R14 order; gx GEMMs now pass skiplen for tile discard)
// ---------------------------------------------------------------------------
extern "C" void kernel_launch(void* const* d_in, const int* in_sizes, int n_in,
                              void* d_out, int out_size) {
    const float* emb     = (const float*)d_in[0];
    const float* enc_Wih = (const float*)d_in[1];
    const float* enc_Whh = (const float*)d_in[2];
    const float* enc_bih = (const float*)d_in[3];
    const float* enc_bhh = (const float*)d_in[4];
    const float* dec_Wih = (const float*)d_in[5];
    const float* dec_Whh = (const float*)d_in[6];
    const float* dec_bih = (const float*)d_in[7];
    const float* dec_bhh = (const float*)d_in[8];
    const float* W_mu    = (const float*)d_in[9];
    const float* b_mu    = (const float*)d_in[10];
    const float* W_ls    = (const float*)d_in[11];
    const float* b_ls    = (const float*)d_in[12];
    const float* W_fc    = (const float*)d_in[13];
    const float* b_fc    = (const float*)d_in[14];
    const float* noise   = (const float*)d_in[15];
    const int*   enc_ids = (const int*)d_in[16];
    const int*   enc_len = (const int*)d_in[17];
    const int*   dec_ids = (const int*)d_in[18];
    const int*   dec_len = (const int*)d_in[19];
    float* outbuf = (float*)d_out;

    float *p_gx_enc, *p_enc_out, *p_gx_dec, *p_dec_out, *p_hA, *p_hB, *p_z;
    cudaGetSymbolAddress((void**)&p_gx_enc, g_gx_enc);
    cudaGetSymbolAddress((void**)&p_enc_out, g_enc_out);
    cudaGetSymbolAddress((void**)&p_gx_dec, g_gx_dec);
    cudaGetSymbolAddress((void**)&p_dec_out, g_dec_out);
    cudaGetSymbolAddress((void**)&p_hA, g_hA);
    cudaGetSymbolAddress((void**)&p_hB, g_hB);
    cudaGetSymbolAddress((void**)&p_z, g_z);

    cudaFuncSetAttribute(logits_wmma, cudaFuncAttributeMaxDynamicSharedMemorySize, SM_TOT);

    // 1) gx_enc = emb[enc_ids] @ enc_Wih^T + bih  (tiles with t0 >= enc_len[b] discarded)
    gemm_nt128<512><<<dim3(1536 / 128, (BB * TEE) / 128), 256>>>(
        p_gx_enc, nullptr, enc_ids, emb, enc_Wih, enc_bih, 3 * HH, enc_len, TEE);

    // 2) W_fc -> split-bf16 W' (independent; runs early)
    prep_w<<<VV, 256>>>(W_fc);

    // 3) padding no-op
    noop_a<<<1, 32>>>();

    // 4) encoder GRU (persistent, truncated at max(enc_len))  <-- profiled slot
    gru_persist<HH, 4, 8><<<HH / 4, 512>>>(
        p_gx_enc, enc_Whh, enc_bhh, enc_len, nullptr, p_hA, p_hB, p_enc_out, TEE);

    // 5-7) attention + latent path
    attn_scores<<<BB, 256>>>(enc_len);
    softmax_semantic<<<BB, 256>>>(enc_len);
    latent_head<<<BB, 256>>>(W_mu, b_mu, W_ls, b_ls, noise, dec_len, outbuf);

    // 8) gx_dec = emb[dec_ids] @ dec_Wih^T + bih  (tiles with t0 >= dec_len[b] discarded)
    gemm_nt128<512><<<dim3((3 * LL) / 128, (BB * TDD) / 128), 256>>>(
        p_gx_dec, nullptr, dec_ids, emb, dec_Wih, dec_bih, 3 * LL, dec_len, TDD);

    // 9) decoder GRU (persistent, truncated at max(dec_len)), h0 = z
    gru_persist<LL, 2, 8><<<LL / 2, 512>>>(
        p_gx_dec, dec_Whh, dec_bhh, dec_len, p_z, p_hA, p_hB, p_dec_out, TDD);

    // 10) dec_out -> split-bf16 A' (zeros rows t >= dec_len[b])
    prep_a<<<BB * TDD, 256>>>(dec_len);

    // 11) logits = A' @ W'^T + b_fc  (wmma bf16, K=768, zero-tile skip)
    logits_wmma<<<dim3(VV / 128, (BB * TDD) / 128), 256, SM_TOT>>>(
        b_fc, dec_len, outbuf);
}

// round 16
// speedup vs baseline: 1.4223x; 1.0021x over previous
#include <cuda_runtime.h>
#include <cuda_bf16.h>
#include <mma.h>
#include <math.h>
#include <stdint.h>

using namespace nvcuda;

// Problem dims
#define VV 32000
#define HH 512
#define LL 256
#define BB 16
#define TEE 512
#define TDD 256

// Output layout: [logits (B*TD*V)][dec_max_len (1)][mu (B*L)][sigma (B*L)]
#define OFF_ML  ((size_t)BB * TDD * VV)
#define OFF_MU  (OFF_ML + 1)
#define OFF_SG  (OFF_MU + (size_t)BB * LL)

// ---------------------------------------------------------------------------
// Scratch (static device globals; no allocation allowed)
// ---------------------------------------------------------------------------
__device__ float g_gx_enc[(size_t)BB * TEE * 3 * HH];   // 50.3 MB
__device__ float g_enc_out[(size_t)BB * TEE * HH];      // 16.8 MB
__device__ float g_gx_dec[(size_t)BB * TDD * 3 * LL];   // 12.6 MB
__device__ float g_dec_out[(size_t)BB * TDD * LL];      //  4.2 MB
__device__ float g_hA[BB * HH];
__device__ float g_hB[BB * HH];
__device__ float g_sfw[BB * TEE];
__device__ float g_sbw[BB * TEE];
__device__ float g_henc[BB * 2 * HH];
__device__ float g_z[BB * LL];
__device__ unsigned g_bar_count;
__device__ volatile unsigned g_bar_gen;

// Split-bf16 operands for the logits GEMM (K-concat: [hi|lo|hi] x [hi|hi|lo])
__device__ __nv_bfloat16 g_wfc_bf[(size_t)VV * 768];        // 49.2 MB
__device__ __nv_bfloat16 g_abf[(size_t)BB * TDD * 768];     //  6.3 MB

// ---------------------------------------------------------------------------
// Grid-wide barrier (R1/R4-proven flat version; all CTAs co-resident)
// ---------------------------------------------------------------------------
__device__ __forceinline__ void grid_barrier(unsigned nb) {
    __threadfence();
    __syncthreads();
    if (threadIdx.x == 0) {
        unsigned gen = g_bar_gen;
        unsigned arrived = atomicAdd(&g_bar_count, 1u);
        if (arrived == nb - 1) {
            g_bar_count = 0;
            __threadfence();
            g_bar_gen = gen + 1;
        } else {
            while (g_bar_gen == gen) { }
        }
        __threadfence();
    }
    __syncthreads();
}

__device__ __forceinline__ float sigmoidf_(float x) { return 1.0f / (1.0f + expf(-x)); }
__device__ __forceinline__ float dot4_(float4 w, float4 h) {
    return w.x * h.x + w.y * h.y + w.z * h.z + w.w * h.w;
}

// ---------------------------------------------------------------------------
// Persistent GRU (R14-proven): 512 threads, 3-gate-fused dot, NS-way K-split,
// loop truncated at maxT = max(lens), parity copy keeps final state in hA.
// ---------------------------------------------------------------------------
template<int K, int CW, int NS>
__global__ __launch_bounds__(512, 1) void gru_persist(
    const float* __restrict__ gx,
    const float* __restrict__ Whh,
    const float* __restrict__ bhh,
    const int*   __restrict__ lens,
    const float* __restrict__ h0,
    float* hA, float* hB,
    float* __restrict__ out,
    int T)
{
    constexpr int PW = K + 4;
    constexpr int NC = 16 * CW * NS;
    constexpr int NU = 16 * CW;
    constexpr int KQ = K / NS;
    __shared__ float hs[16 * PW];
    __shared__ float pex[3 * CW * NS * 16];
    __shared__ int   lens_s[16];
    __shared__ int   maxT_s;

    const int tid = threadIdx.x;
    const int bx  = blockIdx.x;
    const unsigned NB = gridDim.x;

    const float4 *w0p = nullptr, *w1p = nullptr, *w2p = nullptr;
    int db = tid & 15;
    int q  = (tid >> 4) % NS;
    int cl = tid / (16 * NS);
    if (tid < NC) {
        int dc = bx * CW + cl;
        w0p = (const float4*)(Whh + (size_t)(0 * K + dc) * K + q * KQ);
        w1p = (const float4*)(Whh + (size_t)(1 * K + dc) * K + q * KQ);
        w2p = (const float4*)(Whh + (size_t)(2 * K + dc) * K + q * KQ);
    }
    int ub = tid & 15, ucl = tid >> 4;
    int uc = bx * CW + ucl;
    float bhr = 0.f, bhz = 0.f, bhn = 0.f;
    if (tid < NU) {
        bhr = bhh[uc]; bhz = bhh[K + uc]; bhn = bhh[2 * K + uc];
    }

    if (tid < 16) lens_s[tid] = lens[tid];
    if (tid < NU) {
        float v = h0 ? h0[ub * K + uc] : 0.0f;
        __stcg(&hA[ub * K + uc], v);
    }
    __syncthreads();
    if (tid == 0) {
        int m = 0;
        #pragma unroll
        for (int i = 0; i < 16; i++) m = max(m, lens_s[i]);
        maxT_s = m;
    }
    grid_barrier(NB);
    const int maxT = maxT_s;

    for (int t = 0; t < maxT; t++) {
        float* hcur  = (t & 1) ? hB : hA;
        float* hnext = (t & 1) ? hA : hB;

        float gxr = 0.f, gxz = 0.f, gxn = 0.f;
        if (tid < NU) {
            const float* gxp = gx + (size_t)(ub * T + t) * (3 * K);
            gxr = __ldg(gxp + uc);
            gxz = __ldg(gxp + K + uc);
            gxn = __ldg(gxp + 2 * K + uc);
        }

        const float4* hc4 = (const float4*)hcur;
        #pragma unroll
        for (int i = tid; i < 16 * K / 4; i += 512) {
            float4 v = __ldcg(hc4 + i);
            int b = i / (K / 4), kq = i % (K / 4);
            *(float4*)&hs[b * PW + 4 * kq] = v;
        }
        __syncthreads();

        if (tid < NC) {
            const float4* hp = (const float4*)&hs[db * PW + q * KQ];
            float a00 = 0.f, a01 = 0.f, a10 = 0.f, a11 = 0.f, a20 = 0.f, a21 = 0.f;
            #pragma unroll
            for (int kk = 0; kk < KQ / 8; kk++) {
                float4 hv0 = hp[2 * kk + 0];
                float4 hv1 = hp[2 * kk + 1];
                float4 wa0 = __ldg(w0p + 2 * kk + 0);
                float4 wa1 = __ldg(w0p + 2 * kk + 1);
                float4 wb0 = __ldg(w1p + 2 * kk + 0);
                float4 wb1 = __ldg(w1p + 2 * kk + 1);
                float4 wc0 = __ldg(w2p + 2 * kk + 0);
                float4 wc1 = __ldg(w2p + 2 * kk + 1);
                a00 += dot4_(wa0, hv0); a01 += dot4_(wa1, hv1);
                a10 += dot4_(wb0, hv0); a11 += dot4_(wb1, hv1);
                a20 += dot4_(wc0, hv0); a21 += dot4_(wc1, hv1);
            }
            pex[((0 * CW + cl) * NS + q) * 16 + db] = a00 + a01;
            pex[((1 * CW + cl) * NS + q) * 16 + db] = a10 + a11;
            pex[((2 * CW + cl) * NS + q) * 16 + db] = a20 + a21;
        }
        __syncthreads();

        if (tid < NU) {
            float ghr = 0.f, ghz = 0.f, ghn = 0.f;
            #pragma unroll
            for (int qq = 0; qq < NS; qq++) {
                ghr += pex[((0 * CW + ucl) * NS + qq) * 16 + ub];
                ghz += pex[((1 * CW + ucl) * NS + qq) * 16 + ub];
                ghn += pex[((2 * CW + ucl) * NS + qq) * 16 + ub];
            }
            float r = sigmoidf_(gxr + ghr + bhr);
            float z = sigmoidf_(gxz + ghz + bhz);
            float n = tanhf   (gxn + r * (ghn + bhn));
            float hold = hs[ub * PW + uc];
            float hnew = (1.0f - z) * n + z * hold;
            bool valid = (t < lens_s[ub]);
            __stcg(&hnext[ub * K + uc], valid ? hnew : hold);
            out[(size_t)(ub * T + t) * K + uc] = valid ? hnew : 0.0f;
        }
        grid_barrier(NB);
    }

    if ((maxT & 1) && tid < NU) {
        __stcg(&hA[ub * K + uc], __ldcg(&hB[ub * K + uc]));
    }
}

// ---------------------------------------------------------------------------
// 128x128x8 fp32 SGEMM-NT (R8-proven core). NEW skip semantics: tiles whose
// entire M-range has t >= skiplen[b] are DISCARDED (no compute, no write) —
// their outputs are only ever read-and-discarded by the truncated GRU.
// ---------------------------------------------------------------------------
template<int KD>
__global__ __launch_bounds__(256, 2) void gemm_nt128(
    float* __restrict__ C,
    const float* __restrict__ Adirect,
    const int*   __restrict__ ids,
    const float* __restrict__ Atab,
    const float* __restrict__ W,
    const float* __restrict__ bias,
    int N,
    const int* __restrict__ skiplen,
    int tper)
{
    __shared__ float As[2][8][128];
    __shared__ float Bs[2][8][128];
    const int tid  = threadIdx.x;
    const int row0 = blockIdx.y * 128, col0 = blockIdx.x * 128;
    const int ty = tid >> 4, tx = tid & 15;

    if (skiplen) {   // whole tile dead -> skip entirely (values never consumed)
        int bb = row0 / tper, t0 = row0 % tper;
        if (t0 >= __ldg(&skiplen[bb])) return;
    }

    const int lr  = tid >> 1;
    const int lk4 = (tid & 1) * 4;
    const float* arow = ids ? (Atab + (size_t)__ldg(&ids[row0 + lr]) * KD)
                            : (Adirect + (size_t)(row0 + lr) * KD);
    const float* wrow = W + (size_t)(col0 + lr) * KD;

    {
        float4 av = *(const float4*)(arow + lk4);
        float4 wv = *(const float4*)(wrow + lk4);
        As[0][lk4 + 0][lr] = av.x; As[0][lk4 + 1][lr] = av.y;
        As[0][lk4 + 2][lr] = av.z; As[0][lk4 + 3][lr] = av.w;
        Bs[0][lk4 + 0][lr] = wv.x; Bs[0][lk4 + 1][lr] = wv.y;
        Bs[0][lk4 + 2][lr] = wv.z; Bs[0][lk4 + 3][lr] = wv.w;
    }
    __syncthreads();

    float acc[8][8];
    #pragma unroll
    for (int i = 0; i < 8; i++)
        #pragma unroll
        for (int j = 0; j < 8; j++) acc[i][j] = 0.0f;

    constexpr int NK = KD / 8;
    #pragma unroll 1
    for (int kt = 0; kt < NK; kt++) {
        const int cur = kt & 1;
        float4 av2, wv2;
        if (kt + 1 < NK) {
            av2 = *(const float4*)(arow + (kt + 1) * 8 + lk4);
            wv2 = *(const float4*)(wrow + (kt + 1) * 8 + lk4);
        }
        #pragma unroll
        for (int k = 0; k < 8; k++) {
            float a[8], b[8];
            *(float4*)&a[0] = *(const float4*)&As[cur][k][ty * 8];
            *(float4*)&a[4] = *(const float4*)&As[cur][k][ty * 8 + 4];
            *(float4*)&b[0] = *(const float4*)&Bs[cur][k][tx * 8];
            *(float4*)&b[4] = *(const float4*)&Bs[cur][k][tx * 8 + 4];
            #pragma unroll
            for (int i = 0; i < 8; i++)
                #pragma unroll
                for (int j = 0; j < 8; j++)
                    acc[i][j] += a[i] * b[j];
        }
        if (kt + 1 < NK) {
            const int nxt = cur ^ 1;
            As[nxt][lk4 + 0][lr] = av2.x; As[nxt][lk4 + 1][lr] = av2.y;
            As[nxt][lk4 + 2][lr] = av2.z; As[nxt][lk4 + 3][lr] = av2.w;
            Bs[nxt][lk4 + 0][lr] = wv2.x; Bs[nxt][lk4 + 1][lr] = wv2.y;
            Bs[nxt][lk4 + 2][lr] = wv2.z; Bs[nxt][lk4 + 3][lr] = wv2.w;
        }
        __syncthreads();
    }

    float4 blo = *(const float4*)(bias + col0 + tx * 8);
    float4 bhi = *(const float4*)(bias + col0 + tx * 8 + 4);
    #pragma unroll
    for (int i = 0; i < 8; i++) {
        float* cp = C + (size_t)(row0 + ty * 8 + i) * N + col0 + tx * 8;
        float4 v0 = make_float4(acc[i][0] + blo.x, acc[i][1] + blo.y,
                                acc[i][2] + blo.z, acc[i][3] + blo.w);
        float4 v1 = make_float4(acc[i][4] + bhi.x, acc[i][5] + bhi.y,
                                acc[i][6] + bhi.z, acc[i][7] + bhi.w);
        *(float4*)cp = v0; *(float4*)(cp + 4) = v1;
    }
}

// ---------------------------------------------------------------------------
// Split-bf16 prep: W'[n] = [hi | hi | lo], A'[m] = [hi | lo | hi]
// prep_a zeroes rows t >= dec_len[b] (reference semantics = 0 there).
// ---------------------------------------------------------------------------
__global__ __launch_bounds__(256) void prep_w(const float* __restrict__ W) {
    int n = blockIdx.x, k = threadIdx.x;
    float x = __ldg(&W[(size_t)n * LL + k]);
    __nv_bfloat16 hi = __float2bfloat16(x);
    __nv_bfloat16 lo = __float2bfloat16(x - __bfloat162float(hi));
    __nv_bfloat16* dst = g_wfc_bf + (size_t)n * 768;
    dst[k] = hi; dst[LL + k] = hi; dst[2 * LL + k] = lo;
}
__global__ __launch_bounds__(256) void prep_a(const int* __restrict__ dec_len) {
    int m = blockIdx.x, k = threadIdx.x;
    int b = m / TDD, t = m % TDD;
    float x = (t < __ldg(&dec_len[b])) ? g_dec_out[(size_t)m * LL + k] : 0.0f;
    __nv_bfloat16 hi = __float2bfloat16(x);
    __nv_bfloat16 lo = __float2bfloat16(x - __bfloat162float(hi));
    __nv_bfloat16* dst = g_abf + (size_t)m * 768;
    dst[k] = hi; dst[LL + k] = lo; dst[2 * LL + k] = hi;
}

// ---------------------------------------------------------------------------
// wmma bf16 GEMM for logits (R13-proven): 128x128 tile, 8 warps, K=768 in 12
// chunks of 64, double-buffered smem, C staging overlaps A/B -> 2 CTAs/SM.
// ---------------------------------------------------------------------------
#define WKC   64
#define NCHNK (768 / WKC)
#define APIT  72
#define CPIT  132
#define SM_A  0
#define SM_B  (2 * 128 * APIT * 2)
#define SM_TOT (2 * SM_B)

__global__ __launch_bounds__(256) void logits_wmma(
    const float* __restrict__ bias,
    const int* __restrict__ dec_len,
    float* __restrict__ C)
{
    extern __shared__ char smc[];
    __nv_bfloat16* As = (__nv_bfloat16*)(smc + SM_A);
    __nv_bfloat16* Bs = (__nv_bfloat16*)(smc + SM_B);
    float*        Cst = (float*)(smc + SM_A);

    const int tid = threadIdx.x;
    const int col0 = blockIdx.x * 128, row0 = blockIdx.y * 128;

    {
        int bb = row0 / TDD, t0 = row0 % TDD;
        if (t0 >= __ldg(&dec_len[bb])) {
            int r = tid >> 1, half = tid & 1;
            float* cp = C + (size_t)(row0 + r) * VV + col0 + half * 64;
            #pragma unroll
            for (int i = 0; i < 16; i++) {
                const float* bp = bias + col0 + half * 64 + i * 4;
                *(float4*)(cp + i * 4) = make_float4(__ldg(bp), __ldg(bp + 1),
                                                     __ldg(bp + 2), __ldg(bp + 3));
            }
            return;
        }
    }

    const int wid = tid >> 5;
    const int wm = wid >> 1;
    const int wn = wid & 1;

    const int lr  = tid >> 1;
    const int seg = (tid & 1) * 32;
    const __nv_bfloat16* Ag = g_abf    + (size_t)(row0 + lr) * 768 + seg;
    const __nv_bfloat16* Bg = g_wfc_bf + (size_t)(col0 + lr) * 768 + seg;

    {
        __nv_bfloat16* ap = As + lr * APIT + seg;
        __nv_bfloat16* bp = Bs + lr * APIT + seg;
        #pragma unroll
        for (int i = 0; i < 4; i++) {
            *(uint4*)(ap + i * 8) = *(const uint4*)(Ag + i * 8);
            *(uint4*)(bp + i * 8) = *(const uint4*)(Bg + i * 8);
        }
    }
    __syncthreads();

    wmma::fragment<wmma::accumulator, 16, 16, 16, float> cf[2][4];
    #pragma unroll
    for (int i = 0; i < 2; i++)
        #pragma unroll
        for (int j = 0; j < 4; j++)
            wmma::fill_fragment(cf[i][j], 0.0f);

    #pragma unroll 1
    for (int ch = 0; ch < NCHNK; ch++) {
        const int cur = ch & 1;
        uint4 apre[4], bpre[4];
        if (ch + 1 < NCHNK) {
            const __nv_bfloat16* Agn = Ag + (ch + 1) * WKC;
            const __nv_bfloat16* Bgn = Bg + (ch + 1) * WKC;
            #pragma unroll
            for (int i = 0; i < 4; i++) {
                apre[i] = *(const uint4*)(Agn + i * 8);
                bpre[i] = *(const uint4*)(Bgn + i * 8);
            }
        }

        const __nv_bfloat16* Ab = As + cur * 128 * APIT;
        const __nv_bfloat16* Bb = Bs + cur * 128 * APIT;
        #pragma unroll
        for (int kk = 0; kk < WKC; kk += 16) {
            wmma::fragment<wmma::matrix_a, 16, 16, 16, __nv_bfloat16, wmma::row_major> af[2];
            wmma::fragment<wmma::matrix_b, 16, 16, 16, __nv_bfloat16, wmma::col_major> bf[4];
            #pragma unroll
            for (int i = 0; i < 2; i++)
                wmma::load_matrix_sync(af[i], Ab + (wm * 32 + i * 16) * APIT + kk, APIT);
            #pragma unroll
            for (int j = 0; j < 4; j++)
                wmma::load_matrix_sync(bf[j], Bb + (wn * 64 + j * 16) * APIT + kk, APIT);
            #pragma unroll
            for (int i = 0; i < 2; i++)
                #pragma unroll
                for (int j = 0; j < 4; j++)
                    wmma::mma_sync(cf[i][j], af[i], bf[j], cf[i][j]);
        }

        if (ch + 1 < NCHNK) {
            const int nxt = cur ^ 1;
            __nv_bfloat16* ap = As + nxt * 128 * APIT + lr * APIT + seg;
            __nv_bfloat16* bp = Bs + nxt * 128 * APIT + lr * APIT + seg;
            #pragma unroll
            for (int i = 0; i < 4; i++) {
                *(uint4*)(ap + i * 8) = apre[i];
                *(uint4*)(bp + i * 8) = bpre[i];
            }
        }
        __syncthreads();
    }

    #pragma unroll
    for (int i = 0; i < 2; i++)
        #pragma unroll
        for (int j = 0; j < 4; j++)
            wmma::store_matrix_sync(Cst + (wm * 32 + i * 16) * CPIT + wn * 64 + j * 16,
                                    cf[i][j], CPIT, wmma::mem_row_major);
    __syncthreads();

    {
        int r = tid >> 1, half = tid & 1;
        const float* sp = Cst + r * CPIT + half * 64;
        float* cp = C + (size_t)(row0 + r) * VV + col0 + half * 64;
        #pragma unroll
        for (int i = 0; i < 16; i++) {
            const float* bp = bias + col0 + half * 64 + i * 4;
            float4 v = *(const float4*)(sp + i * 4);
            *(float4*)(cp + i * 4) = make_float4(v.x + __ldg(bp), v.y + __ldg(bp + 1),
                                                 v.z + __ldg(bp + 2), v.w + __ldg(bp + 3));
        }
    }
}

// ---------------------------------------------------------------------------
// Padding no-op (keeps gru_enc at my 4th launch = ncu profiled slot)
// ---------------------------------------------------------------------------
__global__ void noop_a() {}

// ---------------------------------------------------------------------------
// Attention scores, bounded at len (scores beyond len are masked downstream;
// enc_out there is stale after loop truncation).
// ---------------------------------------------------------------------------
__global__ __launch_bounds__(256) void attn_scores(const int* __restrict__ enc_len) {
    const int b = blockIdx.x, tid = threadIdx.x;
    const int len = __ldg(&enc_len[b]);
    __shared__ float last_s[HH], first_s[HH];
    for (int i = tid; i < HH; i += 256) {
        last_s[i]  = g_hA[b * HH + i];
        first_s[i] = g_enc_out[((size_t)b * TEE + 0) * HH + i];
    }
    __syncthreads();
    const int w = tid >> 5, lane = tid & 31;
    for (int t = w; t < len; t += 8) {
        const float* orow = g_enc_out + ((size_t)(b * TEE + t)) * HH;
        float af = 0.0f, ab = 0.0f;
        #pragma unroll 4
        for (int i = lane; i < HH; i += 32) {
            float v = orow[i];
            af += v * last_s[i];
            ab += v * first_s[i];
        }
        #pragma unroll
        for (int o = 16; o > 0; o >>= 1) {
            af += __shfl_xor_sync(0xffffffffu, af, o);
            ab += __shfl_xor_sync(0xffffffffu, ab, o);
        }
        if (lane == 0) { g_sfw[b * TEE + t] = af; g_sbw[b * TEE + t] = ab; }
    }
}

__device__ __forceinline__ float blk_reduce(float v, float* red, bool ismax) {
    #pragma unroll
    for (int o = 16; o > 0; o >>= 1) {
        float u = __shfl_xor_sync(0xffffffffu, v, o);
        v = ismax ? fmaxf(v, u) : (v + u);
    }
    int w = threadIdx.x >> 5;
    if ((threadIdx.x & 31) == 0) red[w] = v;
    __syncthreads();
    if (threadIdx.x == 0) {
        float a = red[0];
        for (int i = 1; i < 8; i++) a = ismax ? fmaxf(a, red[i]) : (a + red[i]);
        red[0] = a;
    }
    __syncthreads();
    float r = red[0];
    __syncthreads();
    return r;
}

// ---------------------------------------------------------------------------
// Masked dual softmax + semantic pooling + h_enc assembly (R14-proven).
// ---------------------------------------------------------------------------
__global__ __launch_bounds__(256) void softmax_semantic(const int* __restrict__ enc_len) {
    const int b = blockIdx.x, tid = threadIdx.x;
    const int len = enc_len[b];
    __shared__ float sa[TEE];
    __shared__ float red[8];

    float v0 = (tid       < len) ? g_sfw[b * TEE + tid]       : -1e30f;
    float v1 = (tid + 256 < len) ? g_sfw[b * TEE + tid + 256] : -1e30f;
    float M = blk_reduce(fmaxf(v0, v1), red, true);
    float e0 = (tid       < len) ? expf(v0 - M) : 0.0f;
    float e1 = (tid + 256 < len) ? expf(v1 - M) : 0.0f;
    float S = blk_reduce(e0 + e1, red, false);
    float inv = 0.5f / S;
    sa[tid] = e0 * inv; sa[tid + 256] = e1 * inv;
    __syncthreads();

    v0 = (tid       < len) ? g_sbw[b * TEE + tid]       : -1e30f;
    v1 = (tid + 256 < len) ? g_sbw[b * TEE + tid + 256] : -1e30f;
    M = blk_reduce(fmaxf(v0, v1), red, true);
    e0 = (tid       < len) ? expf(v0 - M) : 0.0f;
    e1 = (tid + 256 < len) ? expf(v1 - M) : 0.0f;
    S = blk_reduce(e0 + e1, red, false);
    inv = 0.5f / S;
    sa[tid] += e0 * inv; sa[tid + 256] += e1 * inv;
    __syncthreads();

    for (int d = tid; d < HH; d += 256) {
        float acc = 0.0f;
        #pragma unroll 4
        for (int t = 0; t < len; t++)
            acc += sa[t] * g_enc_out[((size_t)(b * TEE + t)) * HH + d];
        g_henc[b * 2 * HH + HH + d] = acc;
        g_henc[b * 2 * HH + d] = g_hA[b * HH + d];
    }
}

// ---------------------------------------------------------------------------
// Latent head (R1-proven)
// ---------------------------------------------------------------------------
__global__ __launch_bounds__(256) void latent_head(
    const float* __restrict__ W_mu, const float* __restrict__ b_mu,
    const float* __restrict__ W_ls, const float* __restrict__ b_ls,
    const float* __restrict__ noise, const int* __restrict__ dec_len,
    float* __restrict__ outbuf)
{
    const int b = blockIdx.x, tid = threadIdx.x;
    __shared__ float he[2 * HH];
    __shared__ float muv[LL], lsv[LL];
    for (int i = tid; i < 2 * HH; i += 256) he[i] = g_henc[b * 2 * HH + i];
    __syncthreads();

    const int w = tid >> 5, lane = tid & 31;
    for (int o = w; o < 2 * LL; o += 8) {
        const float* Wr; float bia; int j;
        if (o < LL) { j = o;      Wr = W_mu + (size_t)j * (2 * HH); bia = b_mu[j]; }
        else        { j = o - LL; Wr = W_ls + (size_t)j * (2 * HH); bia = b_ls[j]; }
        float acc = 0.0f;
        #pragma unroll 4
        for (int k = lane; k < 2 * HH; k += 32) acc += Wr[k] * he[k];
        #pragma unroll
        for (int s = 16; s > 0; s >>= 1) acc += __shfl_xor_sync(0xffffffffu, acc, s);
        if (lane == 0) { if (o < LL) muv[j] = acc + bia; else lsv[j] = acc + bia; }
    }
    __syncthreads();

    if (tid < LL) {
        float mu = muv[tid];
        float sg = expf(lsv[tid]);
        float zz = mu + sg * noise[b * LL + tid];
        g_z[b * LL + tid] = zz;
        outbuf[OFF_MU + b * LL + tid] = mu;
        outbuf[OFF_SG + b * LL + tid] = sg;
    }
    if (b == 0 && tid == 0) {
        int m = 0;
        for (int i = 0; i < BB; i++) m = max(m, dec_len[i]);
        outbuf[OFF_ML] = (float)m;
    }
}

// ---------------------------------------------------------------------------
// Launch (R14 order; gx GEMMs now pass skiplen for tile discard)
// ---------------------------------------------------------------------------
extern "C" void kernel_launch(void* const* d_in, const int* in_sizes, int n_in,
                              void* d_out, int out_size) {
    const float* emb     = (const float*)d_in[0];
    const float* enc_Wih = (const float*)d_in[1];
    const float* enc_Whh = (const float*)d_in[2];
    const float* enc_bih = (const float*)d_in[3];
    const float* enc_bhh = (const float*)d_in[4];
    const float* dec_Wih = (const float*)d_in[5];
    const float* dec_Whh = (const float*)d_in[6];
    const float* dec_bih = (const float*)d_in[7];
    const float* dec_bhh = (const float*)d_in[8];
    const float* W_mu    = (const float*)d_in[9];
    const float* b_mu    = (const float*)d_in[10];
    const float* W_ls    = (const float*)d_in[11];
    const float* b_ls    = (const float*)d_in[12];
    const float* W_fc    = (const float*)d_in[13];
    const float* b_fc    = (const float*)d_in[14];
    const float* noise   = (const float*)d_in[15];
    const int*   enc_ids = (const int*)d_in[16];
    const int*   enc_len = (const int*)d_in[17];
    const int*   dec_ids = (const int*)d_in[18];
    const int*   dec_len = (const int*)d_in[19];
    float* outbuf = (float*)d_out;

    float *p_gx_enc, *p_enc_out, *p_gx_dec, *p_dec_out, *p_hA, *p_hB, *p_z;
    cudaGetSymbolAddress((void**)&p_gx_enc, g_gx_enc);
    cudaGetSymbolAddress((void**)&p_enc_out, g_enc_out);
    cudaGetSymbolAddress((void**)&p_gx_dec, g_gx_dec);
    cudaGetSymbolAddress((void**)&p_dec_out, g_dec_out);
    cudaGetSymbolAddress((void**)&p_hA, g_hA);
    cudaGetSymbolAddress((void**)&p_hB, g_hB);
    cudaGetSymbolAddress((void**)&p_z, g_z);

    cudaFuncSetAttribute(logits_wmma, cudaFuncAttributeMaxDynamicSharedMemorySize, SM_TOT);

    // 1) gx_enc = emb[enc_ids] @ enc_Wih^T + bih  (tiles with t0 >= enc_len[b] discarded)
    gemm_nt128<512><<<dim3(1536 / 128, (BB * TEE) / 128), 256>>>(
        p_gx_enc, nullptr, enc_ids, emb, enc_Wih, enc_bih, 3 * HH, enc_len, TEE);

    // 2) W_fc -> split-bf16 W' (independent; runs early)
    prep_w<<<VV, 256>>>(W_fc);

    // 3) padding no-op
    noop_a<<<1, 32>>>();

    // 4) encoder GRU (persistent, truncated at max(enc_len))  <-- profiled slot
    gru_persist<HH, 4, 8><<<HH / 4, 512>>>(
        p_gx_enc, enc_Whh, enc_bhh, enc_len, nullptr, p_hA, p_hB, p_enc_out, TEE);

    // 5-7) attention + latent path
    attn_scores<<<BB, 256>>>(enc_len);
    softmax_semantic<<<BB, 256>>>(enc_len);
    latent_head<<<BB, 256>>>(W_mu, b_mu, W_ls, b_ls, noise, dec_len, outbuf);

    // 8) gx_dec = emb[dec_ids] @ dec_Wih^T + bih  (tiles with t0 >= dec_len[b] discarded)
    gemm_nt128<512><<<dim3((3 * LL) / 128, (BB * TDD) / 128), 256>>>(
        p_gx_dec, nullptr, dec_ids, emb, dec_Wih, dec_bih, 3 * LL, dec_len, TDD);

    // 9) decoder GRU (persistent, truncated at max(dec_len)), h0 = z
    gru_persist<LL, 2, 8><<<LL / 2, 512>>>(
        p_gx_dec, dec_Whh, dec_bhh, dec_len, p_z, p_hA, p_hB, p_dec_out, TDD);

    // 10) dec_out -> split-bf16 A' (zeros rows t >= dec_len[b])
    prep_a<<<BB * TDD, 256>>>(dec_len);

    // 11) logits = A' @ W'^T + b_fc  (wmma bf16, K=768, zero-tile skip)
    logits_wmma<<<dim3(VV / 128, (BB * TDD) / 128), 256, SM_TOT>>>(
        b_fc, dec_len, outbuf);
}

// round 17
// speedup vs baseline: 1.4337x; 1.0080x over previous
#include <cuda_runtime.h>
#include <cuda_bf16.h>
#include <mma.h>
#include <math.h>
#include <stdint.h>

using namespace nvcuda;

// Problem dims
#define VV 32000
#define HH 512
#define LL 256
#define BB 16
#define TEE 512
#define TDD 256

// Output layout: [logits (B*TD*V)][dec_max_len (1)][mu (B*L)][sigma (B*L)]
#define OFF_ML  ((size_t)BB * TDD * VV)
#define OFF_MU  (OFF_ML + 1)
#define OFF_SG  (OFF_MU + (size_t)BB * LL)

// ---------------------------------------------------------------------------
// Scratch (static device globals; no allocation allowed)
// ---------------------------------------------------------------------------
__device__ float g_gx_enc[(size_t)BB * TEE * 3 * HH];   // 50.3 MB
__device__ float g_enc_out[(size_t)BB * TEE * HH];      // 16.8 MB
__device__ float g_gx_dec[(size_t)BB * TDD * 3 * LL];   // 12.6 MB
__device__ float g_dec_out[(size_t)BB * TDD * LL];      //  4.2 MB
__device__ float g_hA[BB * HH];
__device__ float g_hB[BB * HH];
__device__ float g_sfw[BB * TEE];
__device__ float g_sbw[BB * TEE];
__device__ float g_henc[BB * 2 * HH];
__device__ float g_z[BB * LL];
__device__ unsigned g_bar_count;
__device__ volatile unsigned g_bar_gen;

// Split-bf16 operand tables
__device__ __nv_bfloat16 g_wfc_bf[(size_t)VV * 768];        // 49.2 MB  W_fc  [hi|hi|lo]
__device__ __nv_bfloat16 g_abf[(size_t)BB * TDD * 768];     //  6.3 MB  dec_out [hi|lo|hi]
__device__ __nv_bfloat16 g_emb_bf[(size_t)VV * 1536];       // 98.3 MB  emb   [hi|lo|hi]
__device__ __nv_bfloat16 g_wih_enc[(size_t)1536 * 1536];    //  4.7 MB  enc_Wih [hi|hi|lo]
__device__ __nv_bfloat16 g_wih_dec[(size_t)768 * 1536];     //  2.4 MB  dec_Wih [hi|hi|lo]

// ---------------------------------------------------------------------------
// Grid-wide barrier (R1/R4-proven flat version; all CTAs co-resident)
// ---------------------------------------------------------------------------
__device__ __forceinline__ void grid_barrier(unsigned nb) {
    __threadfence();
    __syncthreads();
    if (threadIdx.x == 0) {
        unsigned gen = g_bar_gen;
        unsigned arrived = atomicAdd(&g_bar_count, 1u);
        if (arrived == nb - 1) {
            g_bar_count = 0;
            __threadfence();
            g_bar_gen = gen + 1;
        } else {
            while (g_bar_gen == gen) { }
        }
        __threadfence();
    }
    __syncthreads();
}

__device__ __forceinline__ float sigmoidf_(float x) { return 1.0f / (1.0f + expf(-x)); }
__device__ __forceinline__ float dot4_(float4 w, float4 h) {
    return w.x * h.x + w.y * h.y + w.z * h.z + w.w * h.w;
}

// ---------------------------------------------------------------------------
// Persistent GRU (R14-proven): 512 threads, 3-gate-fused dot, NS-way K-split,
// loop truncated at maxT = max(lens), parity copy keeps final state in hA.
// ---------------------------------------------------------------------------
template<int K, int CW, int NS>
__global__ __launch_bounds__(512, 1) void gru_persist(
    const float* __restrict__ gx,
    const float* __restrict__ Whh,
    const float* __restrict__ bhh,
    const int*   __restrict__ lens,
    const float* __restrict__ h0,
    float* hA, float* hB,
    float* __restrict__ out,
    int T)
{
    constexpr int PW = K + 4;
    constexpr int NC = 16 * CW * NS;
    constexpr int NU = 16 * CW;
    constexpr int KQ = K / NS;
    __shared__ float hs[16 * PW];
    __shared__ float pex[3 * CW * NS * 16];
    __shared__ int   lens_s[16];
    __shared__ int   maxT_s;

    const int tid = threadIdx.x;
    const int bx  = blockIdx.x;
    const unsigned NB = gridDim.x;

    const float4 *w0p = nullptr, *w1p = nullptr, *w2p = nullptr;
    int db = tid & 15;
    int q  = (tid >> 4) % NS;
    int cl = tid / (16 * NS);
    if (tid < NC) {
        int dc = bx * CW + cl;
        w0p = (const float4*)(Whh + (size_t)(0 * K + dc) * K + q * KQ);
        w1p = (const float4*)(Whh + (size_t)(1 * K + dc) * K + q * KQ);
        w2p = (const float4*)(Whh + (size_t)(2 * K + dc) * K + q * KQ);
    }
    int ub = tid & 15, ucl = tid >> 4;
    int uc = bx * CW + ucl;
    float bhr = 0.f, bhz = 0.f, bhn = 0.f;
    if (tid < NU) {
        bhr = bhh[uc]; bhz = bhh[K + uc]; bhn = bhh[2 * K + uc];
    }

    if (tid < 16) lens_s[tid] = lens[tid];
    if (tid < NU) {
        float v = h0 ? h0[ub * K + uc] : 0.0f;
        __stcg(&hA[ub * K + uc], v);
    }
    __syncthreads();
    if (tid == 0) {
        int m = 0;
        #pragma unroll
        for (int i = 0; i < 16; i++) m = max(m, lens_s[i]);
        maxT_s = m;
    }
    grid_barrier(NB);
    const int maxT = maxT_s;

    for (int t = 0; t < maxT; t++) {
        float* hcur  = (t & 1) ? hB : hA;
        float* hnext = (t & 1) ? hA : hB;

        float gxr = 0.f, gxz = 0.f, gxn = 0.f;
        if (tid < NU) {
            const float* gxp = gx + (size_t)(ub * T + t) * (3 * K);
            gxr = __ldg(gxp + uc);
            gxz = __ldg(gxp + K + uc);
            gxn = __ldg(gxp + 2 * K + uc);
        }

        const float4* hc4 = (const float4*)hcur;
        #pragma unroll
        for (int i = tid; i < 16 * K / 4; i += 512) {
            float4 v = __ldcg(hc4 + i);
            int b = i / (K / 4), kq = i % (K / 4);
            *(float4*)&hs[b * PW + 4 * kq] = v;
        }
        __syncthreads();

        if (tid < NC) {
            const float4* hp = (const float4*)&hs[db * PW + q * KQ];
            float a00 = 0.f, a01 = 0.f, a10 = 0.f, a11 = 0.f, a20 = 0.f, a21 = 0.f;
            #pragma unroll
            for (int kk = 0; kk < KQ / 8; kk++) {
                float4 hv0 = hp[2 * kk + 0];
                float4 hv1 = hp[2 * kk + 1];
                float4 wa0 = __ldg(w0p + 2 * kk + 0);
                float4 wa1 = __ldg(w0p + 2 * kk + 1);
                float4 wb0 = __ldg(w1p + 2 * kk + 0);
                float4 wb1 = __ldg(w1p + 2 * kk + 1);
                float4 wc0 = __ldg(w2p + 2 * kk + 0);
                float4 wc1 = __ldg(w2p + 2 * kk + 1);
                a00 += dot4_(wa0, hv0); a01 += dot4_(wa1, hv1);
                a10 += dot4_(wb0, hv0); a11 += dot4_(wb1, hv1);
                a20 += dot4_(wc0, hv0); a21 += dot4_(wc1, hv1);
            }
            pex[((0 * CW + cl) * NS + q) * 16 + db] = a00 + a01;
            pex[((1 * CW + cl) * NS + q) * 16 + db] = a10 + a11;
            pex[((2 * CW + cl) * NS + q) * 16 + db] = a20 + a21;
        }
        __syncthreads();

        if (tid < NU) {
            float ghr = 0.f, ghz = 0.f, ghn = 0.f;
            #pragma unroll
            for (int qq = 0; qq < NS; qq++) {
                ghr += pex[((0 * CW + ucl) * NS + qq) * 16 + ub];
                ghz += pex[((1 * CW + ucl) * NS + qq) * 16 + ub];
                ghn += pex[((2 * CW + ucl) * NS + qq) * 16 + ub];
            }
            float r = sigmoidf_(gxr + ghr + bhr);
            float z = sigmoidf_(gxz + ghz + bhz);
            float n = tanhf   (gxn + r * (ghn + bhn));
            float hold = hs[ub * PW + uc];
            float hnew = (1.0f - z) * n + z * hold;
            bool valid = (t < lens_s[ub]);
            __stcg(&hnext[ub * K + uc], valid ? hnew : hold);
            out[(size_t)(ub * T + t) * K + uc] = valid ? hnew : 0.0f;
        }
        grid_barrier(NB);
    }

    if ((maxT & 1) && tid < NU) {
        __stcg(&hA[ub * K + uc], __ldcg(&hB[ub * K + uc]));
    }
}

// ---------------------------------------------------------------------------
// Split-bf16 prep kernels.
//   A-layout: [hi | lo | hi]   (left operand rows)
//   B-layout: [hi | hi | lo]   (right operand rows)
// ---------------------------------------------------------------------------
__global__ __launch_bounds__(256) void prep_split3_A(
    const float* __restrict__ S, __nv_bfloat16* __restrict__ D, int KO)
{
    int n = blockIdx.x;
    __nv_bfloat16* dst = D + (size_t)n * 3 * KO;
    const float* src = S + (size_t)n * KO;
    for (int k = threadIdx.x; k < KO; k += 256) {
        float x = __ldg(src + k);
        __nv_bfloat16 hi = __float2bfloat16(x);
        __nv_bfloat16 lo = __float2bfloat16(x - __bfloat162float(hi));
        dst[k] = hi; dst[KO + k] = lo; dst[2 * KO + k] = hi;
    }
}
__global__ __launch_bounds__(256) void prep_split3_B(
    const float* __restrict__ S, __nv_bfloat16* __restrict__ D, int KO)
{
    int n = blockIdx.x;
    __nv_bfloat16* dst = D + (size_t)n * 3 * KO;
    const float* src = S + (size_t)n * KO;
    for (int k = threadIdx.x; k < KO; k += 256) {
        float x = __ldg(src + k);
        __nv_bfloat16 hi = __float2bfloat16(x);
        __nv_bfloat16 lo = __float2bfloat16(x - __bfloat162float(hi));
        dst[k] = hi; dst[KO + k] = hi; dst[2 * KO + k] = lo;
    }
}
// dec_out -> A-layout, zeroing rows t >= dec_len[b] (reference semantics)
__global__ __launch_bounds__(256) void prep_a(const int* __restrict__ dec_len) {
    int m = blockIdx.x, k = threadIdx.x;
    int b = m / TDD, t = m % TDD;
    float x = (t < __ldg(&dec_len[b])) ? g_dec_out[(size_t)m * LL + k] : 0.0f;
    __nv_bfloat16 hi = __float2bfloat16(x);
    __nv_bfloat16 lo = __float2bfloat16(x - __bfloat162float(hi));
    __nv_bfloat16* dst = g_abf + (size_t)m * 768;
    dst[k] = hi; dst[LL + k] = lo; dst[2 * LL + k] = hi;
}

// ---------------------------------------------------------------------------
// Generalized wmma bf16 GEMM (R13-proven structure):
// C[M, ldc](cols col0..col0+128) = A'[rows, KD] @ B'[N, KD]^T + bias
// 128x128 tile, 8 warps (4m x 2n), K in KD/64 chunks of 64, double-buffered
// smem, C staging overlaps A/B buffers (73.7 KB -> 2 CTAs/SM).
// Optional row gather via ids. Skip for tiles with t0 >= lens[b]:
//   FILLBIAS=true  -> write bias rows (logits semantics)
//   FILLBIAS=false -> discard tile entirely (gx semantics; outputs never
//                     validly consumed by the truncated GRU)
// ---------------------------------------------------------------------------
#define APIT  72
#define CPIT  132
#define SM_A  0
#define SM_B  (2 * 128 * APIT * 2)
#define SM_TOT (2 * SM_B)

template<int KD, bool FILLBIAS>
__global__ __launch_bounds__(256) void gemm_wmma(
    const __nv_bfloat16* __restrict__ Atab,
    const int* __restrict__ ids,
    const __nv_bfloat16* __restrict__ Bm,
    const float* __restrict__ bias,
    const int* __restrict__ lens, int tper,
    int ldc, float* __restrict__ C)
{
    constexpr int NCHNK = KD / 64;
    extern __shared__ char smc[];
    __nv_bfloat16* As = (__nv_bfloat16*)(smc + SM_A);
    __nv_bfloat16* Bs = (__nv_bfloat16*)(smc + SM_B);
    float*        Cst = (float*)(smc + SM_A);

    const int tid = threadIdx.x;
    const int col0 = blockIdx.x * 128, row0 = blockIdx.y * 128;

    {
        int bb = row0 / tper, t0 = row0 % tper;
        if (t0 >= __ldg(&lens[bb])) {
            if (FILLBIAS) {
                int r = tid >> 1, half = tid & 1;
                float* cp = C + (size_t)(row0 + r) * ldc + col0 + half * 64;
                #pragma unroll
                for (int i = 0; i < 16; i++) {
                    const float* bp = bias + col0 + half * 64 + i * 4;
                    *(float4*)(cp + i * 4) = make_float4(__ldg(bp), __ldg(bp + 1),
                                                         __ldg(bp + 2), __ldg(bp + 3));
                }
            }
            return;
        }
    }

    const int wid = tid >> 5;
    const int wm = wid >> 1;
    const int wn = wid & 1;

    const int lr  = tid >> 1;
    const int seg = (tid & 1) * 32;
    const int arow = ids ? __ldg(&ids[row0 + lr]) : (row0 + lr);
    const __nv_bfloat16* Ag = Atab + (size_t)arow * KD + seg;
    const __nv_bfloat16* Bg = Bm + (size_t)(col0 + lr) * KD + seg;

    {
        __nv_bfloat16* ap = As + lr * APIT + seg;
        __nv_bfloat16* bp = Bs + lr * APIT + seg;
        #pragma unroll
        for (int i = 0; i < 4; i++) {
            *(uint4*)(ap + i * 8) = *(const uint4*)(Ag + i * 8);
            *(uint4*)(bp + i * 8) = *(const uint4*)(Bg + i * 8);
        }
    }
    __syncthreads();

    wmma::fragment<wmma::accumulator, 16, 16, 16, float> cf[2][4];
    #pragma unroll
    for (int i = 0; i < 2; i++)
        #pragma unroll
        for (int j = 0; j < 4; j++)
            wmma::fill_fragment(cf[i][j], 0.0f);

    #pragma unroll 1
    for (int ch = 0; ch < NCHNK; ch++) {
        const int cur = ch & 1;
        uint4 apre[4], bpre[4];
        if (ch + 1 < NCHNK) {
            const __nv_bfloat16* Agn = Ag + (ch + 1) * 64;
            const __nv_bfloat16* Bgn = Bg + (ch + 1) * 64;
            #pragma unroll
            for (int i = 0; i < 4; i++) {
                apre[i] = *(const uint4*)(Agn + i * 8);
                bpre[i] = *(const uint4*)(Bgn + i * 8);
            }
        }

        const __nv_bfloat16* Ab = As + cur * 128 * APIT;
        const __nv_bfloat16* Bb = Bs + cur * 128 * APIT;
        #pragma unroll
        for (int kk = 0; kk < 64; kk += 16) {
            wmma::fragment<wmma::matrix_a, 16, 16, 16, __nv_bfloat16, wmma::row_major> af[2];
            wmma::fragment<wmma::matrix_b, 16, 16, 16, __nv_bfloat16, wmma::col_major> bf[4];
            #pragma unroll
            for (int i = 0; i < 2; i++)
                wmma::load_matrix_sync(af[i], Ab + (wm * 32 + i * 16) * APIT + kk, APIT);
            #pragma unroll
            for (int j = 0; j < 4; j++)
                wmma::load_matrix_sync(bf[j], Bb + (wn * 64 + j * 16) * APIT + kk, APIT);
            #pragma unroll
            for (int i = 0; i < 2; i++)
                #pragma unroll
                for (int j = 0; j < 4; j++)
                    wmma::mma_sync(cf[i][j], af[i], bf[j], cf[i][j]);
        }

        if (ch + 1 < NCHNK) {
            const int nxt = cur ^ 1;
            __nv_bfloat16* ap = As + nxt * 128 * APIT + lr * APIT + seg;
            __nv_bfloat16* bp = Bs + nxt * 128 * APIT + lr * APIT + seg;
            #pragma unroll
            for (int i = 0; i < 4; i++) {
                *(uint4*)(ap + i * 8) = apre[i];
                *(uint4*)(bp + i * 8) = bpre[i];
            }
        }
        __syncthreads();
    }

    #pragma unroll
    for (int i = 0; i < 2; i++)
        #pragma unroll
        for (int j = 0; j < 4; j++)
            wmma::store_matrix_sync(Cst + (wm * 32 + i * 16) * CPIT + wn * 64 + j * 16,
                                    cf[i][j], CPIT, wmma::mem_row_major);
    __syncthreads();

    {
        int r = tid >> 1, half = tid & 1;
        const float* sp = Cst + r * CPIT + half * 64;
        float* cp = C + (size_t)(row0 + r) * ldc + col0 + half * 64;
        #pragma unroll
        for (int i = 0; i < 16; i++) {
            const float* bp = bias + col0 + half * 64 + i * 4;
            float4 v = *(const float4*)(sp + i * 4);
            *(float4*)(cp + i * 4) = make_float4(v.x + __ldg(bp), v.y + __ldg(bp + 1),
                                                 v.z + __ldg(bp + 2), v.w + __ldg(bp + 3));
        }
    }
}

// ---------------------------------------------------------------------------
// Attention scores, bounded at len (R16-proven)
// ---------------------------------------------------------------------------
__global__ __launch_bounds__(256) void attn_scores(const int* __restrict__ enc_len) {
    const int b = blockIdx.x, tid = threadIdx.x;
    const int len = __ldg(&enc_len[b]);
    __shared__ float last_s[HH], first_s[HH];
    for (int i = tid; i < HH; i += 256) {
        last_s[i]  = g_hA[b * HH + i];
        first_s[i] = g_enc_out[((size_t)b * TEE + 0) * HH + i];
    }
    __syncthreads();
    const int w = tid >> 5, lane = tid & 31;
    for (int t = w; t < len; t += 8) {
        const float* orow = g_enc_out + ((size_t)(b * TEE + t)) * HH;
        float af = 0.0f, ab = 0.0f;
        #pragma unroll 4
        for (int i = lane; i < HH; i += 32) {
            float v = orow[i];
            af += v * last_s[i];
            ab += v * first_s[i];
        }
        #pragma unroll
        for (int o = 16; o > 0; o >>= 1) {
            af += __shfl_xor_sync(0xffffffffu, af, o);
            ab += __shfl_xor_sync(0xffffffffu, ab, o);
        }
        if (lane == 0) { g_sfw[b * TEE + t] = af; g_sbw[b * TEE + t] = ab; }
    }
}

__device__ __forceinline__ float blk_reduce(float v, float* red, bool ismax) {
    #pragma unroll
    for (int o = 16; o > 0; o >>= 1) {
        float u = __shfl_xor_sync(0xffffffffu, v, o);
        v = ismax ? fmaxf(v, u) : (v + u);
    }
    int w = threadIdx.x >> 5;
    if ((threadIdx.x & 31) == 0) red[w] = v;
    __syncthreads();
    if (threadIdx.x == 0) {
        float a = red[0];
        for (int i = 1; i < 8; i++) a = ismax ? fmaxf(a, red[i]) : (a + red[i]);
        red[0] = a;
    }
    __syncthreads();
    float r = red[0];
    __syncthreads();
    return r;
}

// ---------------------------------------------------------------------------
// Masked dual softmax + semantic pooling + h_enc assembly (R14-proven).
// ---------------------------------------------------------------------------
__global__ __launch_bounds__(256) void softmax_semantic(const int* __restrict__ enc_len) {
    const int b = blockIdx.x, tid = threadIdx.x;
    const int len = enc_len[b];
    __shared__ float sa[TEE];
    __shared__ float red[8];

    float v0 = (tid       < len) ? g_sfw[b * TEE + tid]       : -1e30f;
    float v1 = (tid + 256 < len) ? g_sfw[b * TEE + tid + 256] : -1e30f;
    float M = blk_reduce(fmaxf(v0, v1), red, true);
    float e0 = (tid       < len) ? expf(v0 - M) : 0.0f;
    float e1 = (tid + 256 < len) ? expf(v1 - M) : 0.0f;
    float S = blk_reduce(e0 + e1, red, false);
    float inv = 0.5f / S;
    sa[tid] = e0 * inv; sa[tid + 256] = e1 * inv;
    __syncthreads();

    v0 = (tid       < len) ? g_sbw[b * TEE + tid]       : -1e30f;
    v1 = (tid + 256 < len) ? g_sbw[b * TEE + tid + 256] : -1e30f;
    M = blk_reduce(fmaxf(v0, v1), red, true);
    e0 = (tid       < len) ? expf(v0 - M) : 0.0f;
    e1 = (tid + 256 < len) ? expf(v1 - M) : 0.0f;
    S = blk_reduce(e0 + e1, red, false);
    inv = 0.5f / S;
    sa[tid] += e0 * inv; sa[tid + 256] += e1 * inv;
    __syncthreads();

    for (int d = tid; d < HH; d += 256) {
        float acc = 0.0f;
        #pragma unroll 4
        for (int t = 0; t < len; t++)
            acc += sa[t] * g_enc_out[((size_t)(b * TEE + t)) * HH + d];
        g_henc[b * 2 * HH + HH + d] = acc;
        g_henc[b * 2 * HH + d] = g_hA[b * HH + d];
    }
}

// ---------------------------------------------------------------------------
// Latent head (R1-proven)
// ---------------------------------------------------------------------------
__global__ __launch_bounds__(256) void latent_head(
    const float* __restrict__ W_mu, const float* __restrict__ b_mu,
    const float* __restrict__ W_ls, const float* __restrict__ b_ls,
    const float* __restrict__ noise, const int* __restrict__ dec_len,
    float* __restrict__ outbuf)
{
    const int b = blockIdx.x, tid = threadIdx.x;
    __shared__ float he[2 * HH];
    __shared__ float muv[LL], lsv[LL];
    for (int i = tid; i < 2 * HH; i += 256) he[i] = g_henc[b * 2 * HH + i];
    __syncthreads();

    const int w = tid >> 5, lane = tid & 31;
    for (int o = w; o < 2 * LL; o += 8) {
        const float* Wr; float bia; int j;
        if (o < LL) { j = o;      Wr = W_mu + (size_t)j * (2 * HH); bia = b_mu[j]; }
        else        { j = o - LL; Wr = W_ls + (size_t)j * (2 * HH); bia = b_ls[j]; }
        float acc = 0.0f;
        #pragma unroll 4
        for (int k = lane; k < 2 * HH; k += 32) acc += Wr[k] * he[k];
        #pragma unroll
        for (int s = 16; s > 0; s >>= 1) acc += __shfl_xor_sync(0xffffffffu, acc, s);
        if (lane == 0) { if (o < LL) muv[j] = acc + bia; else lsv[j] = acc + bia; }
    }
    __syncthreads();

    if (tid < LL) {
        float mu = muv[tid];
        float sg = expf(lsv[tid]);
        float zz = mu + sg * noise[b * LL + tid];
        g_z[b * LL + tid] = zz;
        outbuf[OFF_MU + b * LL + tid] = mu;
        outbuf[OFF_SG + b * LL + tid] = sg;
    }
    if (b == 0 && tid == 0) {
        int m = 0;
        for (int i = 0; i < BB; i++) m = max(m, dec_len[i]);
        outbuf[OFF_ML] = (float)m;
    }
}

// ---------------------------------------------------------------------------
// Launch (gru_enc stays at launch #4 = profiled slot)
// ---------------------------------------------------------------------------
extern "C" void kernel_launch(void* const* d_in, const int* in_sizes, int n_in,
                              void* d_out, int out_size) {
    const float* emb     = (const float*)d_in[0];
    const float* enc_Wih = (const float*)d_in[1];
    const float* enc_Whh = (const float*)d_in[2];
    const float* enc_bih = (const float*)d_in[3];
    const float* enc_bhh = (const float*)d_in[4];
    const float* dec_Wih = (const float*)d_in[5];
    const float* dec_Whh = (const float*)d_in[6];
    const float* dec_bih = (const float*)d_in[7];
    const float* dec_bhh = (const float*)d_in[8];
    const float* W_mu    = (const float*)d_in[9];
    const float* b_mu    = (const float*)d_in[10];
    const float* W_ls    = (const float*)d_in[11];
    const float* b_ls    = (const float*)d_in[12];
    const float* W_fc    = (const float*)d_in[13];
    const float* b_fc    = (const float*)d_in[14];
    const float* noise   = (const float*)d_in[15];
    const int*   enc_ids = (const int*)d_in[16];
    const int*   enc_len = (const int*)d_in[17];
    const int*   dec_ids = (const int*)d_in[18];
    const int*   dec_len = (const int*)d_in[19];
    float* outbuf = (float*)d_out;

    float *p_gx_enc, *p_enc_out, *p_gx_dec, *p_dec_out, *p_hA, *p_hB, *p_z;
    __nv_bfloat16 *p_emb_bf, *p_wih_enc, *p_wih_dec, *p_wfc_bf, *p_abf;
    cudaGetSymbolAddress((void**)&p_gx_enc, g_gx_enc);
    cudaGetSymbolAddress((void**)&p_enc_out, g_enc_out);
    cudaGetSymbolAddress((void**)&p_gx_dec, g_gx_dec);
    cudaGetSymbolAddress((void**)&p_dec_out, g_dec_out);
    cudaGetSymbolAddress((void**)&p_hA, g_hA);
    cudaGetSymbolAddress((void**)&p_hB, g_hB);
    cudaGetSymbolAddress((void**)&p_z, g_z);
    cudaGetSymbolAddress((void**)&p_emb_bf, g_emb_bf);
    cudaGetSymbolAddress((void**)&p_wih_enc, g_wih_enc);
    cudaGetSymbolAddress((void**)&p_wih_dec, g_wih_dec);
    cudaGetSymbolAddress((void**)&p_wfc_bf, g_wfc_bf);
    cudaGetSymbolAddress((void**)&p_abf, g_abf);

    cudaFuncSetAttribute(gemm_wmma<1536, false>,
                         cudaFuncAttributeMaxDynamicSharedMemorySize, SM_TOT);
    cudaFuncSetAttribute(gemm_wmma<768, true>,
                         cudaFuncAttributeMaxDynamicSharedMemorySize, SM_TOT);

    // 1) emb -> split-bf16 A-table [hi|lo|hi] (K=512 -> 1536)
    prep_split3_A<<<VV, 256>>>(emb, p_emb_bf, HH);

    // 2) enc_Wih -> split-bf16 B-table [hi|hi|lo]
    prep_split3_B<<<3 * HH, 256>>>(enc_Wih, p_wih_enc, HH);

    // 3) gx_enc = emb'[enc_ids] @ enc_Wih'^T + bih (wmma; dead tiles discarded)
    gemm_wmma<1536, false><<<dim3((3 * HH) / 128, (BB * TEE) / 128), 256, SM_TOT>>>(
        p_emb_bf, enc_ids, p_wih_enc, enc_bih, enc_len, TEE, 3 * HH, p_gx_enc);

    // 4) encoder GRU (persistent, truncated at max(enc_len))  <-- profiled slot
    gru_persist<HH, 4, 8><<<HH / 4, 512>>>(
        p_gx_enc, enc_Whh, enc_bhh, enc_len, nullptr, p_hA, p_hB, p_enc_out, TEE);

    // 5-7) attention + latent path
    attn_scores<<<BB, 256>>>(enc_len);
    softmax_semantic<<<BB, 256>>>(enc_len);
    latent_head<<<BB, 256>>>(W_mu, b_mu, W_ls, b_ls, noise, dec_len, outbuf);

    // 8) dec_Wih -> split-bf16 B-table
    prep_split3_B<<<3 * LL, 256>>>(dec_Wih, p_wih_dec, HH);

    // 9) gx_dec = emb'[dec_ids] @ dec_Wih'^T + bih (wmma; dead tiles discarded)
    gemm_wmma<1536, false><<<dim3((3 * LL) / 128, (BB * TDD) / 128), 256, SM_TOT>>>(
        p_emb_bf, dec_ids, p_wih_dec, dec_bih, dec_len, TDD, 3 * LL, p_gx_dec);

    // 10) decoder GRU (persistent, truncated at max(dec_len)), h0 = z
    gru_persist<LL, 2, 8><<<LL / 2, 512>>>(
        p_gx_dec, dec_Whh, dec_bhh, dec_len, p_z, p_hA, p_hB, p_dec_out, TDD);

    // 11) dec_out -> split-bf16 A' (zeros rows t >= dec_len[b])
    prep_a<<<BB * TDD, 256>>>(dec_len);

    // 12) W_fc -> split-bf16 B-table [hi|hi|lo] (K=256 -> 768)
    prep_split3_B<<<VV, 256>>>(W_fc, p_wfc_bf, LL);

    // 13) logits = A' @ W_fc'^T + b_fc (wmma; zero tiles -> bias fill)
    gemm_wmma<768, true><<<dim3(VV / 128, (BB * TDD) / 128), 256, SM_TOT>>>(
        p_abf, nullptr, p_wfc_bf, b_fc, dec_len, TDD, VV, outbuf);
}